// round 1
// baseline (speedup 1.0000x reference)
#include <cuda_runtime.h>
#include <math.h>

#define NATOMS 30000
#define NPAIRS 1200000
#define NBASIS 7
#define NRAD   5
#define NSPEC  119
#define NFEAT  360
#define NMOM   100      // 5 radial * (1+3+6+10) symmetric components
#define NU1    512
#define NU2    512

// ---------------- static scratch (no allocations allowed) ----------------
__device__ float g_Mom[NMOM * NATOMS];     // SoA: [component][atom]
__device__ float g_GM [NFEAT * NATOMS];    // feature-major: [feat][atom]
__device__ float g_H1 [NATOMS * NU1];      // row-major [atom][unit]
__device__ float g_H2 [NATOMS * NU2];

// ---------------- zero the moment buffer ----------------
__global__ void zero_mom_kernel() {
    int i = blockIdx.x * blockDim.x + threadIdx.x;
    if (i < NMOM * NATOMS) g_Mom[i] = 0.0f;
}

// ---------------- per-pair: radial embedding + symmetric moment atomics ----------------
__global__ __launch_bounds__(256) void pair_kernel(
    const float* __restrict__ R, const int* __restrict__ Z,
    const int* __restrict__ idx, const float* __restrict__ Wr)
{
    int p = blockIdx.x * blockDim.x + threadIdx.x;
    if (p >= NPAIRS) return;
    int i = idx[p];
    int j = idx[NPAIRS + p];

    float dx = R[3*j+0] - R[3*i+0];
    float dy = R[3*j+1] - R[3*i+1];
    float dz = R[3*j+2] - R[3*i+2];
    float dr = sqrtf(dx*dx + dy*dy + dz*dz + 1e-12f);
    if (dr >= 6.0f) return;   // cutoff factor would be 0 -> zero contribution

    const float PI = 3.14159265358979323846f;
    float cut = 0.5f * (__cosf((PI / 6.0f) * dr) + 1.0f) * 0.37796447300922720f; // * 1/sqrt(7)

    float inv = 1.0f / (dr + 1e-5f);
    float ux = dx * inv, uy = dy * inv, uz = dz * inv;

    const float betta = 49.0f / 36.0f;
    const float rn = sqrtf(sqrtf(2.0f * betta / 3.14159265358979323846f));
    float basis[NBASIS];
#pragma unroll
    for (int b = 0; b < NBASIS; b++) {
        float d = dr - (0.5f + 0.7857142857142857f * (float)b);
        basis[b] = rn * __expf(-betta * d * d);
    }

    int zi = Z[i], zj = Z[j];
    const float* cf = Wr + ((size_t)(zi * NSPEC + zj) * NRAD) * NBASIS;
    float radial[NRAD];
#pragma unroll
    for (int k = 0; k < NRAD; k++) {
        float s = 0.0f;
#pragma unroll
        for (int b = 0; b < NBASIS; b++) s = fmaf(cf[k*NBASIS + b], basis[b], s);
        radial[k] = s * cut;
    }

    // 20 unique symmetric geometric components
    float g[20];
    g[0] = 1.0f;
    g[1] = ux; g[2] = uy; g[3] = uz;
    float xx = ux*ux, yy = uy*uy, zz = uz*uz;
    float xy = ux*uy, xz = ux*uz, yz = uy*uz;
    g[4] = xx; g[5] = yy; g[6] = zz; g[7] = xy; g[8] = xz; g[9] = yz;
    // sorted triples: 000,001,002,011,012,022,111,112,122,222
    g[10] = xx*ux; g[11] = xx*uy; g[12] = xx*uz;
    g[13] = yy*ux; g[14] = xy*uz; g[15] = zz*ux;
    g[16] = yy*uy; g[17] = yy*uz; g[18] = zz*uy; g[19] = zz*uz;

#pragma unroll
    for (int k = 0; k < NRAD; k++) {
        float rk = radial[k];
#pragma unroll
        for (int m = 0; m < 20; m++) {
            atomicAdd(&g_Mom[(k*20 + m) * NATOMS + i], rk * g[m]);
        }
    }
}

// ---------------- per-atom: invariant contractions -> 360 features ----------------
__global__ __launch_bounds__(128) void feat_kernel()
{
    int a = blockIdx.x * blockDim.x + threadIdx.x;
    if (a >= NATOMS) return;

    // symmetric-index expansion tables
    const int T2[9]  = {0,3,4, 3,1,5, 4,5,2};
    const int T3[27] = {0,1,2, 1,3,4, 2,4,5,
                        1,3,4, 3,6,7, 4,7,8,
                        2,4,5, 4,7,8, 5,8,9};

    float m0v[NRAD];
    float m1v[NRAD][3];
    float m2v[NRAD][9];
    float m3v[NRAD][27];

    for (int k = 0; k < NRAD; k++) {
        const float* base = g_Mom + (size_t)(k*20) * NATOMS;
        m0v[k] = base[a];
        for (int d = 0; d < 3; d++) m1v[k][d] = base[(1+d)*NATOMS + a];
        float s2[6];
        for (int u = 0; u < 6; u++) s2[u] = base[(4+u)*NATOMS + a];
        for (int e = 0; e < 9; e++) m2v[k][e] = s2[T2[e]];
        float s3[10];
        for (int u = 0; u < 10; u++) s3[u] = base[(10+u)*NATOMS + a];
        for (int e = 0; e < 27; e++) m3v[k][e] = s3[T3[e]];
    }

    int f = 0;
#define EMIT(v) do { g_GM[(size_t)(f) * NATOMS + a] = (v); f++; } while (0)

    // m0
    for (int k = 0; k < NRAD; k++) EMIT(m0v[k]);

    // c1 = m1r . m1s  (tri2)
    for (int r = 0; r < NRAD; r++)
        for (int s = r; s < NRAD; s++) {
            float v = m1v[r][0]*m1v[s][0] + m1v[r][1]*m1v[s][1] + m1v[r][2]*m1v[s][2];
            EMIT(v);
        }

    // c2 = <m2r, m2s>_F  (tri2)
    for (int r = 0; r < NRAD; r++)
        for (int s = r; s < NRAD; s++) {
            float v = 0.0f;
            for (int e = 0; e < 9; e++) v = fmaf(m2v[r][e], m2v[s][e], v);
            EMIT(v);
        }

    // c3 = <m3r, m3s>  (tri2)
    for (int r = 0; r < NRAD; r++)
        for (int s = r; s < NRAD; s++) {
            float v = 0.0f;
            for (int e = 0; e < 27; e++) v = fmaf(m3v[r][e], m3v[s][e], v);
            EMIT(v);
        }

    // c4[r,s,t] = sum_ijk Ar_ij As_ik At_jk  (tri3)
    for (int r = 0; r < NRAD; r++)
        for (int s = r; s < NRAD; s++)
            for (int t = s; t < NRAD; t++) {
                float v = 0.0f;
                for (int jj = 0; jj < 3; jj++)
                    for (int kk = 0; kk < 3; kk++) {
                        float pjk = 0.0f;
                        for (int ii = 0; ii < 3; ii++)
                            pjk = fmaf(m2v[r][ii*3 + jj], m2v[s][ii*3 + kk], pjk);
                        v = fmaf(pjk, m2v[t][jj*3 + kk], v);
                    }
                EMIT(v);
            }

    // c5[r,s,t] = sum_ij m1r_i m1s_j m2t_ij  (tri2 x full t)
    for (int r = 0; r < NRAD; r++)
        for (int s = r; s < NRAD; s++) {
            float O[9];
            for (int ii = 0; ii < 3; ii++)
                for (int jj = 0; jj < 3; jj++)
                    O[ii*3 + jj] = m1v[r][ii] * m1v[s][jj];
            for (int t = 0; t < NRAD; t++) {
                float v = 0.0f;
                for (int e = 0; e < 9; e++) v = fmaf(O[e], m2v[t][e], v);
                EMIT(v);
            }
        }

    // c6[r,s,t] = sum_{ijkl} m3r_ijk m3s_ijl m2t_kl  (tri2 x full t)
    for (int r = 0; r < NRAD; r++)
        for (int s = r; s < NRAD; s++) {
            float T[9];
            for (int kk = 0; kk < 3; kk++)
                for (int ll = 0; ll < 3; ll++) {
                    float acc = 0.0f;
                    for (int ij = 0; ij < 9; ij++)
                        acc = fmaf(m3v[r][ij*3 + kk], m3v[s][ij*3 + ll], acc);
                    T[kk*3 + ll] = acc;
                }
            for (int t = 0; t < NRAD; t++) {
                float v = 0.0f;
                for (int e = 0; e < 9; e++) v = fmaf(T[e], m2v[t][e], v);
                EMIT(v);
            }
        }

    // c7[r,s,t] = sum_ijk m3r_ijk m2s_ij m1t_k  (full 5x5x5)
    for (int r = 0; r < NRAD; r++)
        for (int s = 0; s < NRAD; s++) {
            float w[3];
            for (int kk = 0; kk < 3; kk++) {
                float acc = 0.0f;
                for (int ij = 0; ij < 9; ij++)
                    acc = fmaf(m3v[r][ij*3 + kk], m2v[s][ij], acc);
                w[kk] = acc;
            }
            for (int t = 0; t < NRAD; t++) {
                float v = w[0]*m1v[t][0] + w[1]*m1v[t][1] + w[2]*m1v[t][2];
                EMIT(v);
            }
        }
#undef EMIT
}

// ---------------- tiled SGEMM with fused bias + optional swish ----------------
#define BM 64
#define BN 64
#define BK 8

template<bool ATRANS, bool SWISH>
__global__ __launch_bounds__(256) void gemm_kernel(
    const float* __restrict__ A, const float* __restrict__ W,
    const float* __restrict__ bias, float* __restrict__ C,
    int M, int N, int K)
{
    __shared__ float As[BK][BM];
    __shared__ float Ws[BK][BN];

    int tid = threadIdx.x;
    int tx = tid & 15;       // col group
    int ty = tid >> 4;       // row group
    int m0 = blockIdx.y * BM;
    int n0 = blockIdx.x * BN;

    float acc[4][4] = {};

    for (int kt = 0; kt < K; kt += BK) {
        if (ATRANS) {
            // A is [K][M]
#pragma unroll
            for (int e = tid; e < BM*BK; e += 256) {
                int k = e >> 6, m = e & 63;
                int gm = m0 + m;
                As[k][m] = (gm < M) ? A[(size_t)(kt + k) * M + gm] : 0.0f;
            }
        } else {
            // A is [M][K]
#pragma unroll
            for (int e = tid; e < BM*BK; e += 256) {
                int m = e >> 3, k = e & 7;
                int gm = m0 + m;
                As[k][m] = (gm < M) ? A[(size_t)gm * K + kt + k] : 0.0f;
            }
        }
#pragma unroll
        for (int e = tid; e < BN*BK; e += 256) {
            int k = e >> 6, n = e & 63;
            Ws[k][n] = W[(size_t)(kt + k) * N + n0 + n];
        }
        __syncthreads();

#pragma unroll
        for (int k = 0; k < BK; k++) {
            float4 av = *(const float4*)&As[k][ty * 4];
            float4 bv = *(const float4*)&Ws[k][tx * 4];
            float a[4] = {av.x, av.y, av.z, av.w};
            float b[4] = {bv.x, bv.y, bv.z, bv.w};
#pragma unroll
            for (int ii = 0; ii < 4; ii++)
#pragma unroll
                for (int jj = 0; jj < 4; jj++)
                    acc[ii][jj] = fmaf(a[ii], b[jj], acc[ii][jj]);
        }
        __syncthreads();
    }

#pragma unroll
    for (int ii = 0; ii < 4; ii++) {
        int gm = m0 + ty * 4 + ii;
        if (gm >= M) continue;
#pragma unroll
        for (int jj = 0; jj < 4; jj++) {
            int gn = n0 + tx * 4 + jj;
            float v = acc[ii][jj] + bias[gn];
            if (SWISH) v = v / (1.0f + __expf(-v));
            C[(size_t)gm * N + gn] = v;
        }
    }
}

// ---------------- final layer: per-row dot + scale/shift ----------------
__global__ __launch_bounds__(256) void out_kernel(
    const float* __restrict__ w3, const float* __restrict__ b3,
    const float* __restrict__ scale, const float* __restrict__ shift,
    const int* __restrict__ Z, float* __restrict__ out)
{
    int gw = (blockIdx.x * blockDim.x + threadIdx.x) >> 5;
    int lane = threadIdx.x & 31;
    if (gw >= NATOMS) return;
    const float* h = g_H2 + (size_t)gw * NU2;
    float s = 0.0f;
#pragma unroll
    for (int t = 0; t < NU2 / 32; t++) {
        int i = lane + t * 32;
        s = fmaf(h[i], w3[i], s);
    }
#pragma unroll
    for (int o = 16; o; o >>= 1) s += __shfl_xor_sync(0xffffffffu, s, o);
    if (lane == 0) {
        float v = s + b3[0];
        int z = Z[gw];
        out[gw] = scale[z] * v + shift[z];
    }
}

// ---------------- launch ----------------
extern "C" void kernel_launch(void* const* d_in, const int* in_sizes, int n_in,
                              void* d_out, int out_size)
{
    const float* R     = (const float*)d_in[0];
    const int*   Z     = (const int*)  d_in[1];
    const int*   idx   = (const int*)  d_in[2];
    const float* Wr    = (const float*)d_in[3];
    const float* w1    = (const float*)d_in[4];
    const float* b1    = (const float*)d_in[5];
    const float* w2    = (const float*)d_in[6];
    const float* b2    = (const float*)d_in[7];
    const float* w3    = (const float*)d_in[8];
    const float* b3    = (const float*)d_in[9];
    const float* scale = (const float*)d_in[10];
    const float* shift = (const float*)d_in[11];
    float* out = (float*)d_out;

    // resolve scratch symbol addresses (host-side, no allocation)
    float *pGM = nullptr, *pH1 = nullptr, *pH2 = nullptr;
    cudaGetSymbolAddress((void**)&pGM, g_GM);
    cudaGetSymbolAddress((void**)&pH1, g_H1);
    cudaGetSymbolAddress((void**)&pH2, g_H2);

    zero_mom_kernel<<<(NMOM * NATOMS + 511) / 512, 512>>>();
    pair_kernel<<<(NPAIRS + 255) / 256, 256>>>(R, Z, idx, Wr);
    feat_kernel<<<(NATOMS + 127) / 128, 128>>>();

    dim3 g1(NU1 / BN, (NATOMS + BM - 1) / BM);
    gemm_kernel<true, true><<<g1, 256>>>(pGM, w1, b1, pH1, NATOMS, NU1, NFEAT);

    dim3 g2(NU2 / BN, (NATOMS + BM - 1) / BM);
    gemm_kernel<false, true><<<g2, 256>>>(pH1, w2, b2, pH2, NATOMS, NU2, NU1);

    out_kernel<<<(NATOMS * 32 + 255) / 256, 256>>>(w3, b3, scale, shift, Z, out);
}

// round 2
// speedup vs baseline: 1.2332x; 1.2332x over previous
#include <cuda_runtime.h>
#include <math.h>

#define NATOMS 30000
#define NPAIRS 1200000
#define NBASIS 7
#define NRAD   5
#define NSPEC  119
#define NFEAT  360
#define NMOM   100      // 5 radial * (1+3+6+10) symmetric components
#define NU1    512
#define NU2    512

// ---------------- static scratch (no allocations allowed) ----------------
__device__ int   g_cnt[NATOMS];
__device__ int   g_off[NATOMS];
__device__ int   g_cur[NATOMS];
__device__ float g_pd[(size_t)NPAIRS * 8];   // sorted pair data: [pos][rad0..4, ux,uy,uz]
__device__ float g_Mom[NMOM * NATOMS];       // SoA: [component][atom]
__device__ float g_GM [NFEAT * NATOMS];      // feature-major: [feat][atom]
__device__ float g_H1 [NATOMS * NU1];        // row-major [atom][unit]
__device__ float g_H2 [NATOMS * NU2];

// ---------------- zero the per-atom counters ----------------
__global__ void zero_cnt_kernel() {
    int i = blockIdx.x * blockDim.x + threadIdx.x;
    if (i < NATOMS) g_cnt[i] = 0;
}

// ---------------- histogram: pairs per center atom ----------------
__global__ __launch_bounds__(256) void hist_kernel(const int* __restrict__ idx) {
    int p = blockIdx.x * blockDim.x + threadIdx.x;
    if (p < NPAIRS) atomicAdd(&g_cnt[idx[p]], 1);
}

// ---------------- single-block exclusive prefix scan over 30k counters ----------------
__global__ __launch_bounds__(1024) void scan_kernel() {
    __shared__ int s[1024];
    int tid = threadIdx.x;
    int run = 0;
    for (int base = 0; base < NATOMS; base += 1024) {
        int i = base + tid;
        int v = (i < NATOMS) ? g_cnt[i] : 0;
        s[tid] = v;
        __syncthreads();
        // Hillis-Steele inclusive scan
        for (int d = 1; d < 1024; d <<= 1) {
            int t = (tid >= d) ? s[tid - d] : 0;
            __syncthreads();
            s[tid] += t;
            __syncthreads();
        }
        if (i < NATOMS) {
            int ex = run + s[tid] - v;
            g_off[i] = ex;
            g_cur[i] = ex;
        }
        run += s[1023];
        __syncthreads();
    }
}

// ---------------- per-pair math + scatter into atom-sorted slots ----------------
__global__ __launch_bounds__(256) void scatter_kernel(
    const float* __restrict__ R, const int* __restrict__ Z,
    const int* __restrict__ idx, const float* __restrict__ Wr)
{
    int p = blockIdx.x * blockDim.x + threadIdx.x;
    if (p >= NPAIRS) return;
    int i = idx[p];
    int j = idx[NPAIRS + p];

    float dx = R[3*j+0] - R[3*i+0];
    float dy = R[3*j+1] - R[3*i+1];
    float dz = R[3*j+2] - R[3*i+2];
    float dr = sqrtf(dx*dx + dy*dy + dz*dz + 1e-12f);

    const float PI = 3.14159265358979323846f;
    float cut = (dr < 6.0f)
              ? 0.5f * (__cosf((PI / 6.0f) * dr) + 1.0f) * 0.37796447300922720f // * 1/sqrt(7)
              : 0.0f;

    float inv = 1.0f / (dr + 1e-5f);
    float ux = dx * inv, uy = dy * inv, uz = dz * inv;

    const float betta = 49.0f / 36.0f;
    const float rn = 0.9601717136386805f;  // (2*betta/pi)^0.25
    float basis[NBASIS];
#pragma unroll
    for (int b = 0; b < NBASIS; b++) {
        float d = dr - (0.5f + 0.7857142857142857f * (float)b);
        basis[b] = rn * __expf(-betta * d * d);
    }

    int zi = Z[i], zj = Z[j];
    const float* cf = Wr + ((size_t)(zi * NSPEC + zj) * NRAD) * NBASIS;
    float radial[NRAD];
#pragma unroll
    for (int k = 0; k < NRAD; k++) {
        float s = 0.0f;
#pragma unroll
        for (int b = 0; b < NBASIS; b++) s = fmaf(cf[k*NBASIS + b], basis[b], s);
        radial[k] = s * cut;
    }

    int pos = atomicAdd(&g_cur[i], 1);
    float4 lo = make_float4(radial[0], radial[1], radial[2], radial[3]);
    float4 hi = make_float4(radial[4], ux, uy, uz);
    *(float4*)&g_pd[(size_t)pos * 8 + 0] = lo;
    *(float4*)&g_pd[(size_t)pos * 8 + 4] = hi;
}

// ---------------- per-(atom, radial) register accumulation of symmetric moments ----------------
__global__ __launch_bounds__(256) void accum_kernel()
{
    int t = blockIdx.x * blockDim.x + threadIdx.x;
    if (t >= NATOMS * NRAD) return;
    int k = t / NATOMS;          // radial channel (uniform across most of a warp region)
    int a = t - k * NATOMS;      // atom (consecutive within warp -> coalesced stores)

    int beg = g_off[a];
    int end = beg + g_cnt[a];

    float acc[20];
#pragma unroll
    for (int m = 0; m < 20; m++) acc[m] = 0.0f;

    for (int p = beg; p < end; p++) {
        float4 lo = *(const float4*)&g_pd[(size_t)p * 8 + 0];
        float4 hi = *(const float4*)&g_pd[(size_t)p * 8 + 4];
        float rk;
        switch (k) {
            case 0: rk = lo.x; break;
            case 1: rk = lo.y; break;
            case 2: rk = lo.z; break;
            case 3: rk = lo.w; break;
            default: rk = hi.x; break;
        }
        float ux = hi.y, uy = hi.z, uz = hi.w;
        float xx = ux*ux, yy = uy*uy, zz = uz*uz;
        float xy = ux*uy, xz = ux*uz, yz = uy*uz;

        acc[0]  += rk;
        acc[1]  = fmaf(rk, ux, acc[1]);
        acc[2]  = fmaf(rk, uy, acc[2]);
        acc[3]  = fmaf(rk, uz, acc[3]);
        acc[4]  = fmaf(rk, xx, acc[4]);
        acc[5]  = fmaf(rk, yy, acc[5]);
        acc[6]  = fmaf(rk, zz, acc[6]);
        acc[7]  = fmaf(rk, xy, acc[7]);
        acc[8]  = fmaf(rk, xz, acc[8]);
        acc[9]  = fmaf(rk, yz, acc[9]);
        acc[10] = fmaf(rk, xx*ux, acc[10]);
        acc[11] = fmaf(rk, xx*uy, acc[11]);
        acc[12] = fmaf(rk, xx*uz, acc[12]);
        acc[13] = fmaf(rk, yy*ux, acc[13]);
        acc[14] = fmaf(rk, xy*uz, acc[14]);
        acc[15] = fmaf(rk, zz*ux, acc[15]);
        acc[16] = fmaf(rk, yy*uy, acc[16]);
        acc[17] = fmaf(rk, yy*uz, acc[17]);
        acc[18] = fmaf(rk, zz*uy, acc[18]);
        acc[19] = fmaf(rk, zz*uz, acc[19]);
    }

#pragma unroll
    for (int m = 0; m < 20; m++)
        g_Mom[(size_t)(k * 20 + m) * NATOMS + a] = acc[m];
}

// ---------------- per-atom: invariant contractions -> 360 features ----------------
__global__ __launch_bounds__(128) void feat_kernel()
{
    int a = blockIdx.x * blockDim.x + threadIdx.x;
    if (a >= NATOMS) return;

    // symmetric-index expansion tables
    const int T2[9]  = {0,3,4, 3,1,5, 4,5,2};
    const int T3[27] = {0,1,2, 1,3,4, 2,4,5,
                        1,3,4, 3,6,7, 4,7,8,
                        2,4,5, 4,7,8, 5,8,9};

    float m0v[NRAD];
    float m1v[NRAD][3];
    float m2v[NRAD][9];
    float m3v[NRAD][27];

    for (int k = 0; k < NRAD; k++) {
        const float* base = g_Mom + (size_t)(k*20) * NATOMS;
        m0v[k] = base[a];
        for (int d = 0; d < 3; d++) m1v[k][d] = base[(1+d)*NATOMS + a];
        float s2[6];
        for (int u = 0; u < 6; u++) s2[u] = base[(4+u)*NATOMS + a];
        for (int e = 0; e < 9; e++) m2v[k][e] = s2[T2[e]];
        float s3[10];
        for (int u = 0; u < 10; u++) s3[u] = base[(10+u)*NATOMS + a];
        for (int e = 0; e < 27; e++) m3v[k][e] = s3[T3[e]];
    }

    int f = 0;
#define EMIT(v) do { g_GM[(size_t)(f) * NATOMS + a] = (v); f++; } while (0)

    // m0
    for (int k = 0; k < NRAD; k++) EMIT(m0v[k]);

    // c1 = m1r . m1s  (tri2)
    for (int r = 0; r < NRAD; r++)
        for (int s = r; s < NRAD; s++) {
            float v = m1v[r][0]*m1v[s][0] + m1v[r][1]*m1v[s][1] + m1v[r][2]*m1v[s][2];
            EMIT(v);
        }

    // c2 = <m2r, m2s>_F  (tri2)
    for (int r = 0; r < NRAD; r++)
        for (int s = r; s < NRAD; s++) {
            float v = 0.0f;
            for (int e = 0; e < 9; e++) v = fmaf(m2v[r][e], m2v[s][e], v);
            EMIT(v);
        }

    // c3 = <m3r, m3s>  (tri2)
    for (int r = 0; r < NRAD; r++)
        for (int s = r; s < NRAD; s++) {
            float v = 0.0f;
            for (int e = 0; e < 27; e++) v = fmaf(m3v[r][e], m3v[s][e], v);
            EMIT(v);
        }

    // c4[r,s,t] = sum_ijk Ar_ij As_ik At_jk  (tri3)
    for (int r = 0; r < NRAD; r++)
        for (int s = r; s < NRAD; s++)
            for (int t = s; t < NRAD; t++) {
                float v = 0.0f;
                for (int jj = 0; jj < 3; jj++)
                    for (int kk = 0; kk < 3; kk++) {
                        float pjk = 0.0f;
                        for (int ii = 0; ii < 3; ii++)
                            pjk = fmaf(m2v[r][ii*3 + jj], m2v[s][ii*3 + kk], pjk);
                        v = fmaf(pjk, m2v[t][jj*3 + kk], v);
                    }
                EMIT(v);
            }

    // c5[r,s,t] = sum_ij m1r_i m1s_j m2t_ij  (tri2 x full t)
    for (int r = 0; r < NRAD; r++)
        for (int s = r; s < NRAD; s++) {
            float O[9];
            for (int ii = 0; ii < 3; ii++)
                for (int jj = 0; jj < 3; jj++)
                    O[ii*3 + jj] = m1v[r][ii] * m1v[s][jj];
            for (int t = 0; t < NRAD; t++) {
                float v = 0.0f;
                for (int e = 0; e < 9; e++) v = fmaf(O[e], m2v[t][e], v);
                EMIT(v);
            }
        }

    // c6[r,s,t] = sum_{ijkl} m3r_ijk m3s_ijl m2t_kl  (tri2 x full t)
    for (int r = 0; r < NRAD; r++)
        for (int s = r; s < NRAD; s++) {
            float T[9];
            for (int kk = 0; kk < 3; kk++)
                for (int ll = 0; ll < 3; ll++) {
                    float acc2 = 0.0f;
                    for (int ij = 0; ij < 9; ij++)
                        acc2 = fmaf(m3v[r][ij*3 + kk], m3v[s][ij*3 + ll], acc2);
                    T[kk*3 + ll] = acc2;
                }
            for (int t = 0; t < NRAD; t++) {
                float v = 0.0f;
                for (int e = 0; e < 9; e++) v = fmaf(T[e], m2v[t][e], v);
                EMIT(v);
            }
        }

    // c7[r,s,t] = sum_ijk m3r_ijk m2s_ij m1t_k  (full 5x5x5)
    for (int r = 0; r < NRAD; r++)
        for (int s = 0; s < NRAD; s++) {
            float w[3];
            for (int kk = 0; kk < 3; kk++) {
                float acc2 = 0.0f;
                for (int ij = 0; ij < 9; ij++)
                    acc2 = fmaf(m3v[r][ij*3 + kk], m2v[s][ij], acc2);
                w[kk] = acc2;
            }
            for (int t = 0; t < NRAD; t++) {
                float v = w[0]*m1v[t][0] + w[1]*m1v[t][1] + w[2]*m1v[t][2];
                EMIT(v);
            }
        }
#undef EMIT
}

// ---------------- tiled SGEMM with fused bias + optional swish ----------------
#define BM 64
#define BN 64
#define BK 8

template<bool ATRANS, bool SWISH>
__global__ __launch_bounds__(256) void gemm_kernel(
    const float* __restrict__ A, const float* __restrict__ W,
    const float* __restrict__ bias, float* __restrict__ C,
    int M, int N, int K)
{
    __shared__ float As[BK][BM];
    __shared__ float Ws[BK][BN];

    int tid = threadIdx.x;
    int tx = tid & 15;       // col group
    int ty = tid >> 4;       // row group
    int m0 = blockIdx.y * BM;
    int n0 = blockIdx.x * BN;

    float acc[4][4] = {};

    for (int kt = 0; kt < K; kt += BK) {
        if (ATRANS) {
            // A is [K][M]
#pragma unroll
            for (int e = tid; e < BM*BK; e += 256) {
                int k = e >> 6, m = e & 63;
                int gm = m0 + m;
                As[k][m] = (gm < M) ? A[(size_t)(kt + k) * M + gm] : 0.0f;
            }
        } else {
            // A is [M][K]
#pragma unroll
            for (int e = tid; e < BM*BK; e += 256) {
                int m = e >> 3, k = e & 7;
                int gm = m0 + m;
                As[k][m] = (gm < M) ? A[(size_t)gm * K + kt + k] : 0.0f;
            }
        }
#pragma unroll
        for (int e = tid; e < BN*BK; e += 256) {
            int k = e >> 6, n = e & 63;
            Ws[k][n] = W[(size_t)(kt + k) * N + n0 + n];
        }
        __syncthreads();

#pragma unroll
        for (int k = 0; k < BK; k++) {
            float4 av = *(const float4*)&As[k][ty * 4];
            float4 bv = *(const float4*)&Ws[k][tx * 4];
            float a[4] = {av.x, av.y, av.z, av.w};
            float b[4] = {bv.x, bv.y, bv.z, bv.w};
#pragma unroll
            for (int ii = 0; ii < 4; ii++)
#pragma unroll
                for (int jj = 0; jj < 4; jj++)
                    acc[ii][jj] = fmaf(a[ii], b[jj], acc[ii][jj]);
        }
        __syncthreads();
    }

#pragma unroll
    for (int ii = 0; ii < 4; ii++) {
        int gm = m0 + ty * 4 + ii;
        if (gm >= M) continue;
#pragma unroll
        for (int jj = 0; jj < 4; jj++) {
            int gn = n0 + tx * 4 + jj;
            float v = acc[ii][jj] + bias[gn];
            if (SWISH) v = v / (1.0f + __expf(-v));
            C[(size_t)gm * N + gn] = v;
        }
    }
}

// ---------------- final layer: per-row dot + scale/shift ----------------
__global__ __launch_bounds__(256) void out_kernel(
    const float* __restrict__ w3, const float* __restrict__ b3,
    const float* __restrict__ scale, const float* __restrict__ shift,
    const int* __restrict__ Z, float* __restrict__ out)
{
    int gw = (blockIdx.x * blockDim.x + threadIdx.x) >> 5;
    int lane = threadIdx.x & 31;
    if (gw >= NATOMS) return;
    const float* h = g_H2 + (size_t)gw * NU2;
    float s = 0.0f;
#pragma unroll
    for (int t = 0; t < NU2 / 32; t++) {
        int i = lane + t * 32;
        s = fmaf(h[i], w3[i], s);
    }
#pragma unroll
    for (int o = 16; o; o >>= 1) s += __shfl_xor_sync(0xffffffffu, s, o);
    if (lane == 0) {
        float v = s + b3[0];
        int z = Z[gw];
        out[gw] = scale[z] * v + shift[z];
    }
}

// ---------------- launch ----------------
extern "C" void kernel_launch(void* const* d_in, const int* in_sizes, int n_in,
                              void* d_out, int out_size)
{
    const float* R     = (const float*)d_in[0];
    const int*   Z     = (const int*)  d_in[1];
    const int*   idx   = (const int*)  d_in[2];
    const float* Wr    = (const float*)d_in[3];
    const float* w1    = (const float*)d_in[4];
    const float* b1    = (const float*)d_in[5];
    const float* w2    = (const float*)d_in[6];
    const float* b2    = (const float*)d_in[7];
    const float* w3    = (const float*)d_in[8];
    const float* b3    = (const float*)d_in[9];
    const float* scale = (const float*)d_in[10];
    const float* shift = (const float*)d_in[11];
    float* out = (float*)d_out;

    float *pGM = nullptr, *pH1 = nullptr, *pH2 = nullptr;
    cudaGetSymbolAddress((void**)&pGM, g_GM);
    cudaGetSymbolAddress((void**)&pH1, g_H1);
    cudaGetSymbolAddress((void**)&pH2, g_H2);

    zero_cnt_kernel<<<(NATOMS + 255) / 256, 256>>>();
    hist_kernel<<<(NPAIRS + 255) / 256, 256>>>(idx);
    scan_kernel<<<1, 1024>>>();
    scatter_kernel<<<(NPAIRS + 255) / 256, 256>>>(R, Z, idx, Wr);
    accum_kernel<<<(NATOMS * NRAD + 255) / 256, 256>>>();
    feat_kernel<<<(NATOMS + 127) / 128, 128>>>();

    dim3 g1(NU1 / BN, (NATOMS + BM - 1) / BM);
    gemm_kernel<true, true><<<g1, 256>>>(pGM, w1, b1, pH1, NATOMS, NU1, NFEAT);

    dim3 g2(NU2 / BN, (NATOMS + BM - 1) / BM);
    gemm_kernel<false, true><<<g2, 256>>>(pH1, w2, b2, pH2, NATOMS, NU2, NU1);

    out_kernel<<<(NATOMS * 32 + 255) / 256, 256>>>(w3, b3, scale, shift, Z, out);
}

// round 4
// speedup vs baseline: 1.4570x; 1.1815x over previous
#include <cuda_runtime.h>
#include <math.h>

#define NATOMS 30000
#define NPAIRS 1200000
#define NBASIS 7
#define NRAD   5
#define NSPEC  119
#define NFEAT  360
#define NMOM   100      // 5 radial * (1+3+6+10) symmetric components
#define NU1    512
#define NU2    512

// ---------------- static scratch (no allocations allowed) ----------------
__device__ int   g_cnt[NATOMS];
__device__ int   g_off[NATOMS];
__device__ int   g_cur[NATOMS];
__device__ float g_pd[(size_t)NPAIRS * 8];   // sorted pair data: [pos][rad0..4, ux,uy,uz]
__device__ float g_Mom[NMOM * NATOMS];       // SoA: [component][atom]
__device__ float g_GM [NFEAT * NATOMS];      // feature-major: [feat][atom]
__device__ float g_H1 [NATOMS * NU1];        // row-major [atom][unit]
__device__ float g_H2 [NATOMS * NU2];

// ---------------- zero the per-atom counters ----------------
__global__ void zero_cnt_kernel() {
    int i = blockIdx.x * blockDim.x + threadIdx.x;
    if (i < NATOMS) g_cnt[i] = 0;
}

// ---------------- histogram: pairs per center atom ----------------
__global__ __launch_bounds__(256) void hist_kernel(const int* __restrict__ idx) {
    int p = blockIdx.x * blockDim.x + threadIdx.x;
    if (p < NPAIRS) atomicAdd(&g_cnt[idx[p]], 1);
}

// ---------------- single-block exclusive prefix scan over 30k counters ----------------
__global__ __launch_bounds__(1024) void scan_kernel() {
    __shared__ int s[1024];
    int tid = threadIdx.x;
    int run = 0;
    for (int base = 0; base < NATOMS; base += 1024) {
        int i = base + tid;
        int v = (i < NATOMS) ? g_cnt[i] : 0;
        s[tid] = v;
        __syncthreads();
        for (int d = 1; d < 1024; d <<= 1) {
            int t = (tid >= d) ? s[tid - d] : 0;
            __syncthreads();
            s[tid] += t;
            __syncthreads();
        }
        if (i < NATOMS) {
            int ex = run + s[tid] - v;
            g_off[i] = ex;
            g_cur[i] = ex;
        }
        run += s[1023];
        __syncthreads();
    }
}

// ---------------- per-pair math + scatter into atom-sorted slots ----------------
__global__ __launch_bounds__(256) void scatter_kernel(
    const float* __restrict__ R, const int* __restrict__ Z,
    const int* __restrict__ idx, const float* __restrict__ Wr)
{
    int p = blockIdx.x * blockDim.x + threadIdx.x;
    if (p >= NPAIRS) return;
    int i = idx[p];
    int j = idx[NPAIRS + p];

    float dx = R[3*j+0] - R[3*i+0];
    float dy = R[3*j+1] - R[3*i+1];
    float dz = R[3*j+2] - R[3*i+2];
    float dr = sqrtf(dx*dx + dy*dy + dz*dz + 1e-12f);

    const float PI = 3.14159265358979323846f;
    float cut = (dr < 6.0f)
              ? 0.5f * (__cosf((PI / 6.0f) * dr) + 1.0f) * 0.37796447300922720f // * 1/sqrt(7)
              : 0.0f;

    float inv = 1.0f / (dr + 1e-5f);
    float ux = dx * inv, uy = dy * inv, uz = dz * inv;

    const float betta = 49.0f / 36.0f;
    const float rn = 0.9601717136386805f;  // (2*betta/pi)^0.25
    float basis[NBASIS];
#pragma unroll
    for (int b = 0; b < NBASIS; b++) {
        float d = dr - (0.5f + 0.7857142857142857f * (float)b);
        basis[b] = rn * __expf(-betta * d * d);
    }

    int zi = Z[i], zj = Z[j];
    const float* cf = Wr + ((size_t)(zi * NSPEC + zj) * NRAD) * NBASIS;
    float radial[NRAD];
#pragma unroll
    for (int k = 0; k < NRAD; k++) {
        float s = 0.0f;
#pragma unroll
        for (int b = 0; b < NBASIS; b++) s = fmaf(cf[k*NBASIS + b], basis[b], s);
        radial[k] = s * cut;
    }

    int pos = atomicAdd(&g_cur[i], 1);
    float4 lo = make_float4(radial[0], radial[1], radial[2], radial[3]);
    float4 hi = make_float4(radial[4], ux, uy, uz);
    *(float4*)&g_pd[(size_t)pos * 8 + 0] = lo;
    *(float4*)&g_pd[(size_t)pos * 8 + 4] = hi;
}

// ---------------- per-(atom, radial) register accumulation of symmetric moments ----------------
__global__ __launch_bounds__(256) void accum_kernel()
{
    int t = blockIdx.x * blockDim.x + threadIdx.x;
    if (t >= NATOMS * NRAD) return;
    int k = t / NATOMS;          // radial channel
    int a = t - k * NATOMS;      // atom (consecutive within warp -> coalesced stores)

    int beg = g_off[a];
    int end = beg + g_cnt[a];

    float acc[20];
#pragma unroll
    for (int m = 0; m < 20; m++) acc[m] = 0.0f;

    for (int p = beg; p < end; p++) {
        float4 lo = *(const float4*)&g_pd[(size_t)p * 8 + 0];
        float4 hi = *(const float4*)&g_pd[(size_t)p * 8 + 4];
        float rk;
        switch (k) {
            case 0: rk = lo.x; break;
            case 1: rk = lo.y; break;
            case 2: rk = lo.z; break;
            case 3: rk = lo.w; break;
            default: rk = hi.x; break;
        }
        float ux = hi.y, uy = hi.z, uz = hi.w;
        float xx = ux*ux, yy = uy*uy, zz = uz*uz;
        float xy = ux*uy, xz = ux*uz, yz = uy*uz;

        acc[0]  += rk;
        acc[1]  = fmaf(rk, ux, acc[1]);
        acc[2]  = fmaf(rk, uy, acc[2]);
        acc[3]  = fmaf(rk, uz, acc[3]);
        acc[4]  = fmaf(rk, xx, acc[4]);
        acc[5]  = fmaf(rk, yy, acc[5]);
        acc[6]  = fmaf(rk, zz, acc[6]);
        acc[7]  = fmaf(rk, xy, acc[7]);
        acc[8]  = fmaf(rk, xz, acc[8]);
        acc[9]  = fmaf(rk, yz, acc[9]);
        acc[10] = fmaf(rk, xx*ux, acc[10]);
        acc[11] = fmaf(rk, xx*uy, acc[11]);
        acc[12] = fmaf(rk, xx*uz, acc[12]);
        acc[13] = fmaf(rk, yy*ux, acc[13]);
        acc[14] = fmaf(rk, xy*uz, acc[14]);
        acc[15] = fmaf(rk, zz*ux, acc[15]);
        acc[16] = fmaf(rk, yy*uy, acc[16]);
        acc[17] = fmaf(rk, yy*uz, acc[17]);
        acc[18] = fmaf(rk, zz*uy, acc[18]);
        acc[19] = fmaf(rk, zz*uz, acc[19]);
    }

#pragma unroll
    for (int m = 0; m < 20; m++)
        g_Mom[(size_t)(k * 20 + m) * NATOMS + a] = acc[m];
}

// ---------------- per-atom: invariant contractions -> 360 features ----------------
__global__ __launch_bounds__(128) void feat_kernel()
{
    int a = blockIdx.x * blockDim.x + threadIdx.x;
    if (a >= NATOMS) return;

    const int T2[9]  = {0,3,4, 3,1,5, 4,5,2};
    const int T3[27] = {0,1,2, 1,3,4, 2,4,5,
                        1,3,4, 3,6,7, 4,7,8,
                        2,4,5, 4,7,8, 5,8,9};

    float m0v[NRAD];
    float m1v[NRAD][3];
    float m2v[NRAD][9];
    float m3v[NRAD][27];

    for (int k = 0; k < NRAD; k++) {
        const float* base = g_Mom + (size_t)(k*20) * NATOMS;
        m0v[k] = base[a];
        for (int d = 0; d < 3; d++) m1v[k][d] = base[(1+d)*NATOMS + a];
        float s2[6];
        for (int u = 0; u < 6; u++) s2[u] = base[(4+u)*NATOMS + a];
        for (int e = 0; e < 9; e++) m2v[k][e] = s2[T2[e]];
        float s3[10];
        for (int u = 0; u < 10; u++) s3[u] = base[(10+u)*NATOMS + a];
        for (int e = 0; e < 27; e++) m3v[k][e] = s3[T3[e]];
    }

    int f = 0;
#define EMIT(v) do { g_GM[(size_t)(f) * NATOMS + a] = (v); f++; } while (0)

    for (int k = 0; k < NRAD; k++) EMIT(m0v[k]);

    for (int r = 0; r < NRAD; r++)
        for (int s = r; s < NRAD; s++) {
            float v = m1v[r][0]*m1v[s][0] + m1v[r][1]*m1v[s][1] + m1v[r][2]*m1v[s][2];
            EMIT(v);
        }

    for (int r = 0; r < NRAD; r++)
        for (int s = r; s < NRAD; s++) {
            float v = 0.0f;
            for (int e = 0; e < 9; e++) v = fmaf(m2v[r][e], m2v[s][e], v);
            EMIT(v);
        }

    for (int r = 0; r < NRAD; r++)
        for (int s = r; s < NRAD; s++) {
            float v = 0.0f;
            for (int e = 0; e < 27; e++) v = fmaf(m3v[r][e], m3v[s][e], v);
            EMIT(v);
        }

    for (int r = 0; r < NRAD; r++)
        for (int s = r; s < NRAD; s++)
            for (int t = s; t < NRAD; t++) {
                float v = 0.0f;
                for (int jj = 0; jj < 3; jj++)
                    for (int kk = 0; kk < 3; kk++) {
                        float pjk = 0.0f;
                        for (int ii = 0; ii < 3; ii++)
                            pjk = fmaf(m2v[r][ii*3 + jj], m2v[s][ii*3 + kk], pjk);
                        v = fmaf(pjk, m2v[t][jj*3 + kk], v);
                    }
                EMIT(v);
            }

    for (int r = 0; r < NRAD; r++)
        for (int s = r; s < NRAD; s++) {
            float O[9];
            for (int ii = 0; ii < 3; ii++)
                for (int jj = 0; jj < 3; jj++)
                    O[ii*3 + jj] = m1v[r][ii] * m1v[s][jj];
            for (int t = 0; t < NRAD; t++) {
                float v = 0.0f;
                for (int e = 0; e < 9; e++) v = fmaf(O[e], m2v[t][e], v);
                EMIT(v);
            }
        }

    for (int r = 0; r < NRAD; r++)
        for (int s = r; s < NRAD; s++) {
            float T[9];
            for (int kk = 0; kk < 3; kk++)
                for (int ll = 0; ll < 3; ll++) {
                    float acc2 = 0.0f;
                    for (int ij = 0; ij < 9; ij++)
                        acc2 = fmaf(m3v[r][ij*3 + kk], m3v[s][ij*3 + ll], acc2);
                    T[kk*3 + ll] = acc2;
                }
            for (int t = 0; t < NRAD; t++) {
                float v = 0.0f;
                for (int e = 0; e < 9; e++) v = fmaf(T[e], m2v[t][e], v);
                EMIT(v);
            }
        }

    for (int r = 0; r < NRAD; r++)
        for (int s = 0; s < NRAD; s++) {
            float w[3];
            for (int kk = 0; kk < 3; kk++) {
                float acc2 = 0.0f;
                for (int ij = 0; ij < 9; ij++)
                    acc2 = fmaf(m3v[r][ij*3 + kk], m2v[s][ij], acc2);
                w[kk] = acc2;
            }
            for (int t = 0; t < NRAD; t++) {
                float v = w[0]*m1v[t][0] + w[1]*m1v[t][1] + w[2]*m1v[t][2];
                EMIT(v);
            }
        }
#undef EMIT
}

// ---------------- f32x2 packed-fp32 SGEMM with fused bias + swish ----------------
// 128x128 block tile, 256 threads, 8x8 per-thread microtile, BK=8.
// APAD must be a multiple of 4 so every As row is 16B-aligned (float4 loads);
// 132 mod 32 = 4 also makes the transposing stores conflict-free.
#define GBM 128
#define GBN 128
#define GBK 8
#define APAD 132

#define PACK2(d, lo, hi) \
    asm("mov.b64 %0, {%1, %2};" : "=l"(d) : "r"(__float_as_uint(lo)), "r"(__float_as_uint(hi)))
#define FFMA2(d, a, b) \
    asm("fma.rn.f32x2 %0, %1, %2, %3;" : "=l"(d) : "l"(a), "l"(b), "l"(d))

template<bool ATRANS, bool SWISH>
__global__ __launch_bounds__(256) void gemm2_kernel(
    const float* __restrict__ A, const float* __restrict__ W,
    const float* __restrict__ bias, float* __restrict__ C,
    int M, int N, int K)
{
    __shared__ float As[GBK][APAD];
    __shared__ float Ws[GBK][GBN];

    int tid = threadIdx.x;
    int tx = tid & 15;       // 16 col groups (8 cols each)
    int ty = tid >> 4;       // 16 row groups (8 rows each)
    int m0 = blockIdx.y * GBM;
    int n0 = blockIdx.x * GBN;

    unsigned long long acc[8][4];
#pragma unroll
    for (int ii = 0; ii < 8; ii++)
#pragma unroll
        for (int jj = 0; jj < 4; jj++) acc[ii][jj] = 0ull;

    for (int kt = 0; kt < K; kt += GBK) {
        // --- load A tile into As[k][m] ---
        if (ATRANS) {
            // A is [K][M]; coalesced float4 along m
            int kk = tid >> 5;
            int mm = (tid & 31) * 4;
            int gm = m0 + mm;
            if (gm + 3 < M) {
                float4 v = *(const float4*)&A[(size_t)(kt + kk) * M + gm];
                *(float4*)&As[kk][mm] = v;
            } else {
#pragma unroll
                for (int q = 0; q < 4; q++)
                    As[kk][mm+q] = (gm + q < M) ? A[(size_t)(kt + kk) * M + gm + q] : 0.0f;
            }
        } else {
            // A is [M][K]; float4 along K then transpose into smem
            int m = tid >> 1;
            int kg = (tid & 1) * 4;
            int gm = m0 + m;
            if (gm < M) {
                float4 v = *(const float4*)&A[(size_t)gm * K + kt + kg];
                As[kg+0][m] = v.x; As[kg+1][m] = v.y;
                As[kg+2][m] = v.z; As[kg+3][m] = v.w;
            } else {
                As[kg+0][m] = 0.0f; As[kg+1][m] = 0.0f;
                As[kg+2][m] = 0.0f; As[kg+3][m] = 0.0f;
            }
        }
        // --- load W tile into Ws[k][n] ---
        {
            int kk = tid >> 5;
            int nn = (tid & 31) * 4;
            float4 v = *(const float4*)&W[(size_t)(kt + kk) * N + n0 + nn];
            *(float4*)&Ws[kk][nn] = v;
        }
        __syncthreads();

#pragma unroll
        for (int k = 0; k < GBK; k++) {
            float4 a0 = *(const float4*)&As[k][ty * 8];
            float4 a1 = *(const float4*)&As[k][ty * 8 + 4];
            ulonglong2 b01 = *(const ulonglong2*)&Ws[k][tx * 8];
            ulonglong2 b23 = *(const ulonglong2*)&Ws[k][tx * 8 + 4];
            unsigned long long bp[4] = {b01.x, b01.y, b23.x, b23.y};
            float av[8] = {a0.x, a0.y, a0.z, a0.w, a1.x, a1.y, a1.z, a1.w};
#pragma unroll
            for (int ii = 0; ii < 8; ii++) {
                unsigned long long ap;
                PACK2(ap, av[ii], av[ii]);
#pragma unroll
                for (int jj = 0; jj < 4; jj++)
                    FFMA2(acc[ii][jj], ap, bp[jj]);
            }
        }
        __syncthreads();
    }

    // --- epilogue: bias + swish + store ---
#pragma unroll
    for (int ii = 0; ii < 8; ii++) {
        int gm = m0 + ty * 8 + ii;
        if (gm >= M) continue;
#pragma unroll
        for (int jj = 0; jj < 4; jj++) {
            int gn = n0 + tx * 8 + jj * 2;
            union { unsigned long long u; float2 f; } cv;
            cv.u = acc[ii][jj];
            float v0 = cv.f.x + bias[gn + 0];
            float v1 = cv.f.y + bias[gn + 1];
            if (SWISH) {
                v0 = v0 / (1.0f + __expf(-v0));
                v1 = v1 / (1.0f + __expf(-v1));
            }
            *(float2*)&C[(size_t)gm * N + gn] = make_float2(v0, v1);
        }
    }
}

// ---------------- final layer: per-row dot + scale/shift ----------------
__global__ __launch_bounds__(256) void out_kernel(
    const float* __restrict__ w3, const float* __restrict__ b3,
    const float* __restrict__ scale, const float* __restrict__ shift,
    const int* __restrict__ Z, float* __restrict__ out)
{
    int gw = (blockIdx.x * blockDim.x + threadIdx.x) >> 5;
    int lane = threadIdx.x & 31;
    if (gw >= NATOMS) return;
    const float* h = g_H2 + (size_t)gw * NU2;
    float s = 0.0f;
#pragma unroll
    for (int t = 0; t < NU2 / 32; t++) {
        int i = lane + t * 32;
        s = fmaf(h[i], w3[i], s);
    }
#pragma unroll
    for (int o = 16; o; o >>= 1) s += __shfl_xor_sync(0xffffffffu, s, o);
    if (lane == 0) {
        float v = s + b3[0];
        int z = Z[gw];
        out[gw] = scale[z] * v + shift[z];
    }
}

// ---------------- launch ----------------
extern "C" void kernel_launch(void* const* d_in, const int* in_sizes, int n_in,
                              void* d_out, int out_size)
{
    const float* R     = (const float*)d_in[0];
    const int*   Z     = (const int*)  d_in[1];
    const int*   idx   = (const int*)  d_in[2];
    const float* Wr    = (const float*)d_in[3];
    const float* w1    = (const float*)d_in[4];
    const float* b1    = (const float*)d_in[5];
    const float* w2    = (const float*)d_in[6];
    const float* b2    = (const float*)d_in[7];
    const float* w3    = (const float*)d_in[8];
    const float* b3    = (const float*)d_in[9];
    const float* scale = (const float*)d_in[10];
    const float* shift = (const float*)d_in[11];
    float* out = (float*)d_out;

    float *pGM = nullptr, *pH1 = nullptr, *pH2 = nullptr;
    cudaGetSymbolAddress((void**)&pGM, g_GM);
    cudaGetSymbolAddress((void**)&pH1, g_H1);
    cudaGetSymbolAddress((void**)&pH2, g_H2);

    zero_cnt_kernel<<<(NATOMS + 255) / 256, 256>>>();
    hist_kernel<<<(NPAIRS + 255) / 256, 256>>>(idx);
    scan_kernel<<<1, 1024>>>();
    scatter_kernel<<<(NPAIRS + 255) / 256, 256>>>(R, Z, idx, Wr);
    accum_kernel<<<(NATOMS * NRAD + 255) / 256, 256>>>();
    feat_kernel<<<(NATOMS + 127) / 128, 128>>>();

    dim3 g1(NU1 / GBN, (NATOMS + GBM - 1) / GBM);
    gemm2_kernel<true, true><<<g1, 256>>>(pGM, w1, b1, pH1, NATOMS, NU1, NFEAT);

    dim3 g2(NU2 / GBN, (NATOMS + GBM - 1) / GBM);
    gemm2_kernel<false, true><<<g2, 256>>>(pH1, w2, b2, pH2, NATOMS, NU2, NU1);

    out_kernel<<<(NATOMS * 32 + 255) / 256, 256>>>(w3, b3, scale, shift, Z, out);
}

// round 5
// speedup vs baseline: 1.7622x; 1.2094x over previous
#include <cuda_runtime.h>
#include <math.h>

#define NATOMS 30000
#define NPAIRS 1200000
#define NBASIS 7
#define NRAD   5
#define NSPEC  119
#define NFEAT  360
#define NMOM   100
#define NU1    512
#define NU2    512

// ---------------- static scratch (no allocations allowed) ----------------
__device__ int    g_cnt[NATOMS];
__device__ int    g_off[NATOMS];
__device__ int    g_cur[NATOMS];
__device__ float4 g_R4[NATOMS];              // padded positions
__device__ float  g_pd[(size_t)NPAIRS * 8];  // sorted pair data: [pos][rad0..4, ux,uy,uz]
__device__ float  g_Mom[NMOM * NATOMS];      // SoA: [component][atom]
__device__ float  g_GM [NFEAT * NATOMS];     // feature-major: [feat][atom]
__device__ float  g_H1 [NATOMS * NU1];
__device__ float  g_H2 [NATOMS * NU2];

// ---------------- prep: zero counters + pad R ----------------
__global__ void prep_kernel(const float* __restrict__ R) {
    int i = blockIdx.x * blockDim.x + threadIdx.x;
    if (i < NATOMS) {
        g_cnt[i] = 0;
        g_R4[i] = make_float4(R[3*i+0], R[3*i+1], R[3*i+2], 0.0f);
    }
}

// ---------------- histogram: pairs per center atom ----------------
__global__ __launch_bounds__(256) void hist_kernel(const int* __restrict__ idx) {
    int p = blockIdx.x * blockDim.x + threadIdx.x;
    if (p < NPAIRS) atomicAdd(&g_cnt[idx[p]], 1);
}

// ---------------- single-block shuffle-based exclusive scan over 30k counters ----------------
__global__ __launch_bounds__(1024) void scan_kernel() {
    __shared__ int wsum[32];
    __shared__ int chunk_base;
    int tid = threadIdx.x;
    int lane = tid & 31, wid = tid >> 5;
    if (tid == 0) chunk_base = 0;
    __syncthreads();
    for (int base = 0; base < NATOMS; base += 1024) {
        int i = base + tid;
        int v = (i < NATOMS) ? g_cnt[i] : 0;
        // warp inclusive scan
        int x = v;
#pragma unroll
        for (int o = 1; o < 32; o <<= 1) {
            int y = __shfl_up_sync(0xffffffffu, x, o);
            if (lane >= o) x += y;
        }
        if (lane == 31) wsum[wid] = x;
        __syncthreads();
        if (wid == 0) {
            int w = wsum[lane];
            int xs = w;
#pragma unroll
            for (int o = 1; o < 32; o <<= 1) {
                int y = __shfl_up_sync(0xffffffffu, xs, o);
                if (lane >= o) xs += y;
            }
            wsum[lane] = xs - w;   // exclusive warp offsets
        }
        __syncthreads();
        int ex = chunk_base + wsum[wid] + x - v;
        if (i < NATOMS) { g_off[i] = ex; g_cur[i] = ex; }
        __syncthreads();
        if (tid == 1023) chunk_base += wsum[31] + x;   // wsum[31] excl + last warp's inclusive total
        __syncthreads();
    }
}

// ---------------- per-pair math + scatter into atom-sorted slots ----------------
__global__ __launch_bounds__(256) void scatter_kernel(
    const int* __restrict__ Z,
    const int* __restrict__ idx, const float* __restrict__ Wr)
{
    int p = blockIdx.x * blockDim.x + threadIdx.x;
    if (p >= NPAIRS) return;
    int i = idx[p];
    int j = idx[NPAIRS + p];

    float4 Ri = g_R4[i];
    float4 Rj = g_R4[j];
    float dx = Rj.x - Ri.x;
    float dy = Rj.y - Ri.y;
    float dz = Rj.z - Ri.z;
    float dr = sqrtf(dx*dx + dy*dy + dz*dz + 1e-12f);

    const float PI = 3.14159265358979323846f;
    float cut = (dr < 6.0f)
              ? 0.5f * (__cosf((PI / 6.0f) * dr) + 1.0f) * 0.37796447300922720f // * 1/sqrt(7)
              : 0.0f;

    float inv = 1.0f / (dr + 1e-5f);
    float ux = dx * inv, uy = dy * inv, uz = dz * inv;

    const float betta = 49.0f / 36.0f;
    const float rn = 0.9601717136386805f;  // (2*betta/pi)^0.25
    float basis[NBASIS];
#pragma unroll
    for (int b = 0; b < NBASIS; b++) {
        float d = dr - (0.5f + 0.7857142857142857f * (float)b);
        basis[b] = rn * __expf(-betta * d * d);
    }

    int zi = Z[i], zj = Z[j];
    const float* cf = Wr + ((size_t)(zi * NSPEC + zj) * NRAD) * NBASIS;
    float radial[NRAD];
#pragma unroll
    for (int k = 0; k < NRAD; k++) {
        float s = 0.0f;
#pragma unroll
        for (int b = 0; b < NBASIS; b++) s = fmaf(cf[k*NBASIS + b], basis[b], s);
        radial[k] = s * cut;
    }

    int pos = atomicAdd(&g_cur[i], 1);
    float4 lo = make_float4(radial[0], radial[1], radial[2], radial[3]);
    float4 hi = make_float4(radial[4], ux, uy, uz);
    *(float4*)&g_pd[(size_t)pos * 8 + 0] = lo;
    *(float4*)&g_pd[(size_t)pos * 8 + 4] = hi;
}

// ---------------- per-(atom, radial) register accumulation of symmetric moments ----------------
__global__ __launch_bounds__(256) void accum_kernel()
{
    int t = blockIdx.x * blockDim.x + threadIdx.x;
    if (t >= NATOMS * NRAD) return;
    int k = t / NATOMS;
    int a = t - k * NATOMS;

    int beg = g_off[a];
    int end = beg + g_cnt[a];

    float acc[20];
#pragma unroll
    for (int m = 0; m < 20; m++) acc[m] = 0.0f;

    for (int p = beg; p < end; p++) {
        float4 lo = *(const float4*)&g_pd[(size_t)p * 8 + 0];
        float4 hi = *(const float4*)&g_pd[(size_t)p * 8 + 4];
        float rk;
        switch (k) {
            case 0: rk = lo.x; break;
            case 1: rk = lo.y; break;
            case 2: rk = lo.z; break;
            case 3: rk = lo.w; break;
            default: rk = hi.x; break;
        }
        float ux = hi.y, uy = hi.z, uz = hi.w;
        float xx = ux*ux, yy = uy*uy, zz = uz*uz;
        float xy = ux*uy, xz = ux*uz, yz = uy*uz;

        acc[0]  += rk;
        acc[1]  = fmaf(rk, ux, acc[1]);
        acc[2]  = fmaf(rk, uy, acc[2]);
        acc[3]  = fmaf(rk, uz, acc[3]);
        acc[4]  = fmaf(rk, xx, acc[4]);
        acc[5]  = fmaf(rk, yy, acc[5]);
        acc[6]  = fmaf(rk, zz, acc[6]);
        acc[7]  = fmaf(rk, xy, acc[7]);
        acc[8]  = fmaf(rk, xz, acc[8]);
        acc[9]  = fmaf(rk, yz, acc[9]);
        acc[10] = fmaf(rk, xx*ux, acc[10]);
        acc[11] = fmaf(rk, xx*uy, acc[11]);
        acc[12] = fmaf(rk, xx*uz, acc[12]);
        acc[13] = fmaf(rk, yy*ux, acc[13]);
        acc[14] = fmaf(rk, xy*uz, acc[14]);
        acc[15] = fmaf(rk, zz*ux, acc[15]);
        acc[16] = fmaf(rk, yy*uy, acc[16]);
        acc[17] = fmaf(rk, yy*uz, acc[17]);
        acc[18] = fmaf(rk, zz*uy, acc[18]);
        acc[19] = fmaf(rk, zz*uz, acc[19]);
    }

#pragma unroll
    for (int m = 0; m < 20; m++)
        g_Mom[(size_t)(k * 20 + m) * NATOMS + a] = acc[m];
}

// ---------------- per-atom: invariant contractions -> 360 features ----------------
__global__ __launch_bounds__(128) void feat_kernel()
{
    int a = blockIdx.x * blockDim.x + threadIdx.x;
    if (a >= NATOMS) return;

    const int T2[9]  = {0,3,4, 3,1,5, 4,5,2};
    const int T3[27] = {0,1,2, 1,3,4, 2,4,5,
                        1,3,4, 3,6,7, 4,7,8,
                        2,4,5, 4,7,8, 5,8,9};

    float m0v[NRAD];
    float m1v[NRAD][3];
    float m2v[NRAD][9];
    float m3v[NRAD][27];

    for (int k = 0; k < NRAD; k++) {
        const float* base = g_Mom + (size_t)(k*20) * NATOMS;
        m0v[k] = base[a];
        for (int d = 0; d < 3; d++) m1v[k][d] = base[(1+d)*NATOMS + a];
        float s2[6];
        for (int u = 0; u < 6; u++) s2[u] = base[(4+u)*NATOMS + a];
        for (int e = 0; e < 9; e++) m2v[k][e] = s2[T2[e]];
        float s3[10];
        for (int u = 0; u < 10; u++) s3[u] = base[(10+u)*NATOMS + a];
        for (int e = 0; e < 27; e++) m3v[k][e] = s3[T3[e]];
    }

    int f = 0;
#define EMIT(v) do { g_GM[(size_t)(f) * NATOMS + a] = (v); f++; } while (0)

    for (int k = 0; k < NRAD; k++) EMIT(m0v[k]);

    for (int r = 0; r < NRAD; r++)
        for (int s = r; s < NRAD; s++) {
            float v = m1v[r][0]*m1v[s][0] + m1v[r][1]*m1v[s][1] + m1v[r][2]*m1v[s][2];
            EMIT(v);
        }

    for (int r = 0; r < NRAD; r++)
        for (int s = r; s < NRAD; s++) {
            float v = 0.0f;
            for (int e = 0; e < 9; e++) v = fmaf(m2v[r][e], m2v[s][e], v);
            EMIT(v);
        }

    for (int r = 0; r < NRAD; r++)
        for (int s = r; s < NRAD; s++) {
            float v = 0.0f;
            for (int e = 0; e < 27; e++) v = fmaf(m3v[r][e], m3v[s][e], v);
            EMIT(v);
        }

    for (int r = 0; r < NRAD; r++)
        for (int s = r; s < NRAD; s++)
            for (int t = s; t < NRAD; t++) {
                float v = 0.0f;
                for (int jj = 0; jj < 3; jj++)
                    for (int kk = 0; kk < 3; kk++) {
                        float pjk = 0.0f;
                        for (int ii = 0; ii < 3; ii++)
                            pjk = fmaf(m2v[r][ii*3 + jj], m2v[s][ii*3 + kk], pjk);
                        v = fmaf(pjk, m2v[t][jj*3 + kk], v);
                    }
                EMIT(v);
            }

    for (int r = 0; r < NRAD; r++)
        for (int s = r; s < NRAD; s++) {
            float O[9];
            for (int ii = 0; ii < 3; ii++)
                for (int jj = 0; jj < 3; jj++)
                    O[ii*3 + jj] = m1v[r][ii] * m1v[s][jj];
            for (int t = 0; t < NRAD; t++) {
                float v = 0.0f;
                for (int e = 0; e < 9; e++) v = fmaf(O[e], m2v[t][e], v);
                EMIT(v);
            }
        }

    for (int r = 0; r < NRAD; r++)
        for (int s = r; s < NRAD; s++) {
            float T[9];
            for (int kk = 0; kk < 3; kk++)
                for (int ll = 0; ll < 3; ll++) {
                    float acc2 = 0.0f;
                    for (int ij = 0; ij < 9; ij++)
                        acc2 = fmaf(m3v[r][ij*3 + kk], m3v[s][ij*3 + ll], acc2);
                    T[kk*3 + ll] = acc2;
                }
            for (int t = 0; t < NRAD; t++) {
                float v = 0.0f;
                for (int e = 0; e < 9; e++) v = fmaf(T[e], m2v[t][e], v);
                EMIT(v);
            }
        }

    for (int r = 0; r < NRAD; r++)
        for (int s = 0; s < NRAD; s++) {
            float w[3];
            for (int kk = 0; kk < 3; kk++) {
                float acc2 = 0.0f;
                for (int ij = 0; ij < 9; ij++)
                    acc2 = fmaf(m3v[r][ij*3 + kk], m2v[s][ij], acc2);
                w[kk] = acc2;
            }
            for (int t = 0; t < NRAD; t++) {
                float v = w[0]*m1v[t][0] + w[1]*m1v[t][1] + w[2]*m1v[t][2];
                EMIT(v);
            }
        }
#undef EMIT
}

// ---------------- double-buffered f32x2 packed-fp32 SGEMM, fused bias+swish ----------------
// 128x128 block tile, 256 threads, 8x8 microtile (B cols split tx*4 and 64+tx*4), BK=8.
#define GBM 128
#define GBN 128
#define GBK 8
#define APAD 132   // multiple of 4 (16B-aligned rows); 132 % 32 = 4 -> transposing stores conflict-free

#define PACK2(d, lo, hi) \
    asm("mov.b64 %0, {%1, %2};" : "=l"(d) : "r"(__float_as_uint(lo)), "r"(__float_as_uint(hi)))
#define FFMA2(d, a, b) \
    asm("fma.rn.f32x2 %0, %1, %2, %3;" : "=l"(d) : "l"(a), "l"(b), "l"(d))

template<bool ATRANS, bool SWISH>
__global__ __launch_bounds__(256) void gemm2_kernel(
    const float* __restrict__ A, const float* __restrict__ W,
    const float* __restrict__ bias, float* __restrict__ C,
    int M, int N, int K)
{
    __shared__ float As[2][GBK][APAD];
    __shared__ float Ws[2][GBK][GBN];

    int tid = threadIdx.x;
    int tx = tid & 15;       // 16 col groups
    int ty = tid >> 4;       // 16 row groups (8 rows each)
    int m0 = blockIdx.y * GBM;
    int n0 = blockIdx.x * GBN;

    // loader indices
    int lakk = tid >> 5;           // 0..7 (k within tile)
    int lamm = (tid & 31) * 4;     // ATRANS: m offset
    int lm   = tid >> 1;           // !ATRANS: m row
    int lkg  = (tid & 1) * 4;      // !ATRANS: k group
    int lwnn = (tid & 31) * 4;     // W: n offset

    unsigned long long acc[8][4];
#pragma unroll
    for (int ii = 0; ii < 8; ii++)
#pragma unroll
        for (int jj = 0; jj < 4; jj++) acc[ii][jj] = 0ull;

    int nT = K / GBK;

    // ---- preload tile 0 into buffer 0 ----
    {
        if (ATRANS) {
            int gm = m0 + lamm;
            if (gm + 3 < M) {
                *(float4*)&As[0][lakk][lamm] = *(const float4*)&A[(size_t)lakk * M + gm];
            } else {
#pragma unroll
                for (int q = 0; q < 4; q++)
                    As[0][lakk][lamm+q] = (gm + q < M) ? A[(size_t)lakk * M + gm + q] : 0.0f;
            }
        } else {
            int gm = m0 + lm;
            float4 v = make_float4(0.f, 0.f, 0.f, 0.f);
            if (gm < M) v = *(const float4*)&A[(size_t)gm * K + lkg];
            As[0][lkg+0][lm] = v.x; As[0][lkg+1][lm] = v.y;
            As[0][lkg+2][lm] = v.z; As[0][lkg+3][lm] = v.w;
        }
        *(float4*)&Ws[0][lakk][lwnn] = *(const float4*)&W[(size_t)lakk * N + n0 + lwnn];
    }
    __syncthreads();

    for (int t = 0; t < nT; t++) {
        int cur = t & 1;
        int nxt = cur ^ 1;
        bool has = (t + 1 < nT);
        int kt1 = (t + 1) * GBK;

        // ---- prefetch tile t+1 into registers ----
        float pa0 = 0.f, pa1 = 0.f, pa2 = 0.f, pa3 = 0.f;
        float4 pw;
        if (has) {
            if (ATRANS) {
                int gm = m0 + lamm;
                if (gm + 3 < M) {
                    float4 v = *(const float4*)&A[(size_t)(kt1 + lakk) * M + gm];
                    pa0 = v.x; pa1 = v.y; pa2 = v.z; pa3 = v.w;
                } else {
                    if (gm + 0 < M) pa0 = A[(size_t)(kt1 + lakk) * M + gm + 0];
                    if (gm + 1 < M) pa1 = A[(size_t)(kt1 + lakk) * M + gm + 1];
                    if (gm + 2 < M) pa2 = A[(size_t)(kt1 + lakk) * M + gm + 2];
                    if (gm + 3 < M) pa3 = A[(size_t)(kt1 + lakk) * M + gm + 3];
                }
            } else {
                int gm = m0 + lm;
                if (gm < M) {
                    float4 v = *(const float4*)&A[(size_t)gm * K + kt1 + lkg];
                    pa0 = v.x; pa1 = v.y; pa2 = v.z; pa3 = v.w;
                }
            }
            pw = *(const float4*)&W[(size_t)(kt1 + lakk) * N + n0 + lwnn];
        }

        // ---- compute on buffer cur ----
#pragma unroll
        for (int k = 0; k < GBK; k++) {
            float4 a0 = *(const float4*)&As[cur][k][ty * 8];
            float4 a1 = *(const float4*)&As[cur][k][ty * 8 + 4];
            ulonglong2 bA = *(const ulonglong2*)&Ws[cur][k][tx * 4];
            ulonglong2 bB = *(const ulonglong2*)&Ws[cur][k][64 + tx * 4];
            unsigned long long bp[4] = {bA.x, bA.y, bB.x, bB.y};
            float av[8] = {a0.x, a0.y, a0.z, a0.w, a1.x, a1.y, a1.z, a1.w};
#pragma unroll
            for (int ii = 0; ii < 8; ii++) {
                unsigned long long ap;
                PACK2(ap, av[ii], av[ii]);
#pragma unroll
                for (int jj = 0; jj < 4; jj++)
                    FFMA2(acc[ii][jj], ap, bp[jj]);
            }
        }

        // ---- commit prefetched tile into buffer nxt ----
        if (has) {
            if (ATRANS) {
                As[nxt][lakk][lamm+0] = pa0;
                As[nxt][lakk][lamm+1] = pa1;
                As[nxt][lakk][lamm+2] = pa2;
                As[nxt][lakk][lamm+3] = pa3;
            } else {
                As[nxt][lkg+0][lm] = pa0;
                As[nxt][lkg+1][lm] = pa1;
                As[nxt][lkg+2][lm] = pa2;
                As[nxt][lkg+3][lm] = pa3;
            }
            *(float4*)&Ws[nxt][lakk][lwnn] = pw;
        }
        __syncthreads();
    }

    // ---- epilogue: bias + swish + store ----
#pragma unroll
    for (int ii = 0; ii < 8; ii++) {
        int gm = m0 + ty * 8 + ii;
        if (gm >= M) continue;
#pragma unroll
        for (int jj = 0; jj < 4; jj++) {
            int gn = n0 + ((jj < 2) ? (tx * 4 + jj * 2) : (64 + tx * 4 + (jj - 2) * 2));
            union { unsigned long long u; float2 f; } cv;
            cv.u = acc[ii][jj];
            float v0 = cv.f.x + bias[gn + 0];
            float v1 = cv.f.y + bias[gn + 1];
            if (SWISH) {
                v0 = v0 / (1.0f + __expf(-v0));
                v1 = v1 / (1.0f + __expf(-v1));
            }
            *(float2*)&C[(size_t)gm * N + gn] = make_float2(v0, v1);
        }
    }
}

// ---------------- final layer: per-row dot + scale/shift ----------------
__global__ __launch_bounds__(256) void out_kernel(
    const float* __restrict__ w3, const float* __restrict__ b3,
    const float* __restrict__ scale, const float* __restrict__ shift,
    const int* __restrict__ Z, float* __restrict__ out)
{
    int gw = (blockIdx.x * blockDim.x + threadIdx.x) >> 5;
    int lane = threadIdx.x & 31;
    if (gw >= NATOMS) return;
    const float* h = g_H2 + (size_t)gw * NU2;
    float s = 0.0f;
#pragma unroll
    for (int t = 0; t < NU2 / 32; t++) {
        int i = lane + t * 32;
        s = fmaf(h[i], w3[i], s);
    }
#pragma unroll
    for (int o = 16; o; o >>= 1) s += __shfl_xor_sync(0xffffffffu, s, o);
    if (lane == 0) {
        float v = s + b3[0];
        int z = Z[gw];
        out[gw] = scale[z] * v + shift[z];
    }
}

// ---------------- launch ----------------
extern "C" void kernel_launch(void* const* d_in, const int* in_sizes, int n_in,
                              void* d_out, int out_size)
{
    const float* R     = (const float*)d_in[0];
    const int*   Z     = (const int*)  d_in[1];
    const int*   idx   = (const int*)  d_in[2];
    const float* Wr    = (const float*)d_in[3];
    const float* w1    = (const float*)d_in[4];
    const float* b1    = (const float*)d_in[5];
    const float* w2    = (const float*)d_in[6];
    const float* b2    = (const float*)d_in[7];
    const float* w3    = (const float*)d_in[8];
    const float* b3    = (const float*)d_in[9];
    const float* scale = (const float*)d_in[10];
    const float* shift = (const float*)d_in[11];
    float* out = (float*)d_out;

    float *pGM = nullptr, *pH1 = nullptr, *pH2 = nullptr;
    cudaGetSymbolAddress((void**)&pGM, g_GM);
    cudaGetSymbolAddress((void**)&pH1, g_H1);
    cudaGetSymbolAddress((void**)&pH2, g_H2);

    prep_kernel<<<(NATOMS + 255) / 256, 256>>>(R);
    hist_kernel<<<(NPAIRS + 255) / 256, 256>>>(idx);
    scan_kernel<<<1, 1024>>>();
    scatter_kernel<<<(NPAIRS + 255) / 256, 256>>>(Z, idx, Wr);
    accum_kernel<<<(NATOMS * NRAD + 255) / 256, 256>>>();
    feat_kernel<<<(NATOMS + 127) / 128, 128>>>();

    dim3 g1(NU1 / GBN, (NATOMS + GBM - 1) / GBM);
    gemm2_kernel<true, true><<<g1, 256>>>(pGM, w1, b1, pH1, NATOMS, NU1, NFEAT);

    dim3 g2(NU2 / GBN, (NATOMS + GBM - 1) / GBM);
    gemm2_kernel<false, true><<<g2, 256>>>(pH1, w2, b2, pH2, NATOMS, NU2, NU1);

    out_kernel<<<(NATOMS * 32 + 255) / 256, 256>>>(w3, b3, scale, shift, Z, out);
}

// round 6
// speedup vs baseline: 2.2083x; 1.2531x over previous
#include <cuda_runtime.h>
#include <cuda_bf16.h>
#include <math.h>

#define NATOMS 30000
#define NPAIRS 1200000
#define NBASIS 7
#define NRAD   5
#define NSPEC  119
#define NFEAT  360
#define NMOM   100
#define NU1    512
#define NU2    512

// ---------------- static scratch (no allocations allowed) ----------------
__device__ int    g_cnt[NATOMS];
__device__ int    g_off[NATOMS];
__device__ int    g_cur[NATOMS];
__device__ float4 g_R4[NATOMS];
__device__ float  g_pd[(size_t)NPAIRS * 8];
__device__ float  g_Mom[NMOM * NATOMS];
__device__ float  g_GM [NFEAT * NATOMS];     // feature-major: [feat][atom]
__device__ float  g_H1 [NATOMS * NU1];
__device__ float  g_H2 [NATOMS * NU2];

// ---------------- prep: zero counters + pad R ----------------
__global__ void prep_kernel(const float* __restrict__ R) {
    int i = blockIdx.x * blockDim.x + threadIdx.x;
    if (i < NATOMS) {
        g_cnt[i] = 0;
        g_R4[i] = make_float4(R[3*i+0], R[3*i+1], R[3*i+2], 0.0f);
    }
}

// ---------------- histogram ----------------
__global__ __launch_bounds__(256) void hist_kernel(const int* __restrict__ idx) {
    int p = blockIdx.x * blockDim.x + threadIdx.x;
    if (p < NPAIRS) atomicAdd(&g_cnt[idx[p]], 1);
}

// ---------------- single-block shuffle-based exclusive scan ----------------
__global__ __launch_bounds__(1024) void scan_kernel() {
    __shared__ int wsum[32];
    __shared__ int chunk_base;
    int tid = threadIdx.x;
    int lane = tid & 31, wid = tid >> 5;
    if (tid == 0) chunk_base = 0;
    __syncthreads();
    for (int base = 0; base < NATOMS; base += 1024) {
        int i = base + tid;
        int v = (i < NATOMS) ? g_cnt[i] : 0;
        int x = v;
#pragma unroll
        for (int o = 1; o < 32; o <<= 1) {
            int y = __shfl_up_sync(0xffffffffu, x, o);
            if (lane >= o) x += y;
        }
        if (lane == 31) wsum[wid] = x;
        __syncthreads();
        if (wid == 0) {
            int w = wsum[lane];
            int xs = w;
#pragma unroll
            for (int o = 1; o < 32; o <<= 1) {
                int y = __shfl_up_sync(0xffffffffu, xs, o);
                if (lane >= o) xs += y;
            }
            wsum[lane] = xs - w;
        }
        __syncthreads();
        int ex = chunk_base + wsum[wid] + x - v;
        if (i < NATOMS) { g_off[i] = ex; g_cur[i] = ex; }
        __syncthreads();
        if (tid == 1023) chunk_base += wsum[31] + x;
        __syncthreads();
    }
}

// ---------------- per-pair math + scatter ----------------
__global__ __launch_bounds__(256) void scatter_kernel(
    const int* __restrict__ Z,
    const int* __restrict__ idx, const float* __restrict__ Wr)
{
    int p = blockIdx.x * blockDim.x + threadIdx.x;
    if (p >= NPAIRS) return;
    int i = idx[p];
    int j = idx[NPAIRS + p];

    float4 Ri = g_R4[i];
    float4 Rj = g_R4[j];
    float dx = Rj.x - Ri.x;
    float dy = Rj.y - Ri.y;
    float dz = Rj.z - Ri.z;
    float dr = sqrtf(dx*dx + dy*dy + dz*dz + 1e-12f);

    const float PI = 3.14159265358979323846f;
    float cut = (dr < 6.0f)
              ? 0.5f * (__cosf((PI / 6.0f) * dr) + 1.0f) * 0.37796447300922720f
              : 0.0f;

    float inv = 1.0f / (dr + 1e-5f);
    float ux = dx * inv, uy = dy * inv, uz = dz * inv;

    const float betta = 49.0f / 36.0f;
    const float rn = 0.9601717136386805f;
    float basis[NBASIS];
#pragma unroll
    for (int b = 0; b < NBASIS; b++) {
        float d = dr - (0.5f + 0.7857142857142857f * (float)b);
        basis[b] = rn * __expf(-betta * d * d);
    }

    int zi = Z[i], zj = Z[j];
    const float* cf = Wr + ((size_t)(zi * NSPEC + zj) * NRAD) * NBASIS;
    float radial[NRAD];
#pragma unroll
    for (int k = 0; k < NRAD; k++) {
        float s = 0.0f;
#pragma unroll
        for (int b = 0; b < NBASIS; b++) s = fmaf(cf[k*NBASIS + b], basis[b], s);
        radial[k] = s * cut;
    }

    int pos = atomicAdd(&g_cur[i], 1);
    float4 lo = make_float4(radial[0], radial[1], radial[2], radial[3]);
    float4 hi = make_float4(radial[4], ux, uy, uz);
    *(float4*)&g_pd[(size_t)pos * 8 + 0] = lo;
    *(float4*)&g_pd[(size_t)pos * 8 + 4] = hi;
}

// ---------------- per-(atom, radial) moment accumulation ----------------
__global__ __launch_bounds__(256) void accum_kernel()
{
    int t = blockIdx.x * blockDim.x + threadIdx.x;
    if (t >= NATOMS * NRAD) return;
    int k = t / NATOMS;
    int a = t - k * NATOMS;

    int beg = g_off[a];
    int end = beg + g_cnt[a];

    float acc[20];
#pragma unroll
    for (int m = 0; m < 20; m++) acc[m] = 0.0f;

    for (int p = beg; p < end; p++) {
        float4 lo = *(const float4*)&g_pd[(size_t)p * 8 + 0];
        float4 hi = *(const float4*)&g_pd[(size_t)p * 8 + 4];
        float rk;
        switch (k) {
            case 0: rk = lo.x; break;
            case 1: rk = lo.y; break;
            case 2: rk = lo.z; break;
            case 3: rk = lo.w; break;
            default: rk = hi.x; break;
        }
        float ux = hi.y, uy = hi.z, uz = hi.w;
        float xx = ux*ux, yy = uy*uy, zz = uz*uz;
        float xy = ux*uy, xz = ux*uz, yz = uy*uz;

        acc[0]  += rk;
        acc[1]  = fmaf(rk, ux, acc[1]);
        acc[2]  = fmaf(rk, uy, acc[2]);
        acc[3]  = fmaf(rk, uz, acc[3]);
        acc[4]  = fmaf(rk, xx, acc[4]);
        acc[5]  = fmaf(rk, yy, acc[5]);
        acc[6]  = fmaf(rk, zz, acc[6]);
        acc[7]  = fmaf(rk, xy, acc[7]);
        acc[8]  = fmaf(rk, xz, acc[8]);
        acc[9]  = fmaf(rk, yz, acc[9]);
        acc[10] = fmaf(rk, xx*ux, acc[10]);
        acc[11] = fmaf(rk, xx*uy, acc[11]);
        acc[12] = fmaf(rk, xx*uz, acc[12]);
        acc[13] = fmaf(rk, yy*ux, acc[13]);
        acc[14] = fmaf(rk, xy*uz, acc[14]);
        acc[15] = fmaf(rk, zz*ux, acc[15]);
        acc[16] = fmaf(rk, yy*uy, acc[16]);
        acc[17] = fmaf(rk, yy*uz, acc[17]);
        acc[18] = fmaf(rk, zz*uy, acc[18]);
        acc[19] = fmaf(rk, zz*uz, acc[19]);
    }

#pragma unroll
    for (int m = 0; m < 20; m++)
        g_Mom[(size_t)(k * 20 + m) * NATOMS + a] = acc[m];
}

// ---------------- per-atom invariant contractions -> 360 features ----------------
__global__ __launch_bounds__(128) void feat_kernel()
{
    int a = blockIdx.x * blockDim.x + threadIdx.x;
    if (a >= NATOMS) return;

    const int T2[9]  = {0,3,4, 3,1,5, 4,5,2};
    const int T3[27] = {0,1,2, 1,3,4, 2,4,5,
                        1,3,4, 3,6,7, 4,7,8,
                        2,4,5, 4,7,8, 5,8,9};

    float m0v[NRAD];
    float m1v[NRAD][3];
    float m2v[NRAD][9];
    float m3v[NRAD][27];

    for (int k = 0; k < NRAD; k++) {
        const float* base = g_Mom + (size_t)(k*20) * NATOMS;
        m0v[k] = base[a];
        for (int d = 0; d < 3; d++) m1v[k][d] = base[(1+d)*NATOMS + a];
        float s2[6];
        for (int u = 0; u < 6; u++) s2[u] = base[(4+u)*NATOMS + a];
        for (int e = 0; e < 9; e++) m2v[k][e] = s2[T2[e]];
        float s3[10];
        for (int u = 0; u < 10; u++) s3[u] = base[(10+u)*NATOMS + a];
        for (int e = 0; e < 27; e++) m3v[k][e] = s3[T3[e]];
    }

    int f = 0;
#define EMIT(v) do { g_GM[(size_t)(f) * NATOMS + a] = (v); f++; } while (0)

    for (int k = 0; k < NRAD; k++) EMIT(m0v[k]);

    for (int r = 0; r < NRAD; r++)
        for (int s = r; s < NRAD; s++) {
            float v = m1v[r][0]*m1v[s][0] + m1v[r][1]*m1v[s][1] + m1v[r][2]*m1v[s][2];
            EMIT(v);
        }

    for (int r = 0; r < NRAD; r++)
        for (int s = r; s < NRAD; s++) {
            float v = 0.0f;
            for (int e = 0; e < 9; e++) v = fmaf(m2v[r][e], m2v[s][e], v);
            EMIT(v);
        }

    for (int r = 0; r < NRAD; r++)
        for (int s = r; s < NRAD; s++) {
            float v = 0.0f;
            for (int e = 0; e < 27; e++) v = fmaf(m3v[r][e], m3v[s][e], v);
            EMIT(v);
        }

    for (int r = 0; r < NRAD; r++)
        for (int s = r; s < NRAD; s++)
            for (int t = s; t < NRAD; t++) {
                float v = 0.0f;
                for (int jj = 0; jj < 3; jj++)
                    for (int kk = 0; kk < 3; kk++) {
                        float pjk = 0.0f;
                        for (int ii = 0; ii < 3; ii++)
                            pjk = fmaf(m2v[r][ii*3 + jj], m2v[s][ii*3 + kk], pjk);
                        v = fmaf(pjk, m2v[t][jj*3 + kk], v);
                    }
                EMIT(v);
            }

    for (int r = 0; r < NRAD; r++)
        for (int s = r; s < NRAD; s++) {
            float O[9];
            for (int ii = 0; ii < 3; ii++)
                for (int jj = 0; jj < 3; jj++)
                    O[ii*3 + jj] = m1v[r][ii] * m1v[s][jj];
            for (int t = 0; t < NRAD; t++) {
                float v = 0.0f;
                for (int e = 0; e < 9; e++) v = fmaf(O[e], m2v[t][e], v);
                EMIT(v);
            }
        }

    for (int r = 0; r < NRAD; r++)
        for (int s = r; s < NRAD; s++) {
            float T[9];
            for (int kk = 0; kk < 3; kk++)
                for (int ll = 0; ll < 3; ll++) {
                    float acc2 = 0.0f;
                    for (int ij = 0; ij < 9; ij++)
                        acc2 = fmaf(m3v[r][ij*3 + kk], m3v[s][ij*3 + ll], acc2);
                    T[kk*3 + ll] = acc2;
                }
            for (int t = 0; t < NRAD; t++) {
                float v = 0.0f;
                for (int e = 0; e < 9; e++) v = fmaf(T[e], m2v[t][e], v);
                EMIT(v);
            }
        }

    for (int r = 0; r < NRAD; r++)
        for (int s = 0; s < NRAD; s++) {
            float w[3];
            for (int kk = 0; kk < 3; kk++) {
                float acc2 = 0.0f;
                for (int ij = 0; ij < 9; ij++)
                    acc2 = fmaf(m3v[r][ij*3 + kk], m2v[s][ij], acc2);
                w[kk] = acc2;
            }
            for (int t = 0; t < NRAD; t++) {
                float v = w[0]*m1v[t][0] + w[1]*m1v[t][1] + w[2]*m1v[t][2];
                EMIT(v);
            }
        }
#undef EMIT
}

// ============================================================================
// bf16x3 tensor-core GEMM (mma.sync.m16n8k16), fused bias + swish
// CTA tile 128x128, 8 warps (4m x 2n), BK=16, reg-prefetch double buffer.
// a = hi + lo split; acc += hi*hi + hi*lo + lo*hi (fp32 accumulators).
// ============================================================================
#define AS_STR 24     // bf16 elems per A smem row (16 data + pad) -> 48B stride
#define BS_STR 136    // bf16 elems per B smem row (128 data + pad) -> 272B stride

__device__ __forceinline__ unsigned smem_u32(const void* p) {
    return (unsigned)__cvta_generic_to_shared(p);
}
__device__ __forceinline__ void ldsm4(unsigned* r, unsigned addr) {
    asm volatile("ldmatrix.sync.aligned.m8n8.x4.shared.b16 {%0,%1,%2,%3}, [%4];"
        : "=r"(r[0]), "=r"(r[1]), "=r"(r[2]), "=r"(r[3]) : "r"(addr));
}
__device__ __forceinline__ void ldsm4t(unsigned* r, unsigned addr) {
    asm volatile("ldmatrix.sync.aligned.m8n8.x4.trans.shared.b16 {%0,%1,%2,%3}, [%4];"
        : "=r"(r[0]), "=r"(r[1]), "=r"(r[2]), "=r"(r[3]) : "r"(addr));
}
__device__ __forceinline__ void mma_bf16(float* d, const unsigned* a, unsigned b0, unsigned b1) {
    asm volatile("mma.sync.aligned.m16n8k16.row.col.f32.bf16.bf16.f32 "
        "{%0,%1,%2,%3}, {%4,%5,%6,%7}, {%8,%9}, {%0,%1,%2,%3};"
        : "+f"(d[0]), "+f"(d[1]), "+f"(d[2]), "+f"(d[3])
        : "r"(a[0]), "r"(a[1]), "r"(a[2]), "r"(a[3]), "r"(b0), "r"(b1));
}
__device__ __forceinline__ void bsplit(float v, __nv_bfloat16& h, __nv_bfloat16& l) {
    h = __float2bfloat16(v);
    l = __float2bfloat16(v - __bfloat162float(h));
}

template<bool ATRANS, bool SWISH>
__global__ __launch_bounds__(256) void mma_gemm_kernel(
    const float* __restrict__ A, const float* __restrict__ W,
    const float* __restrict__ bias, float* __restrict__ C,
    int M, int N, int K)
{
    __shared__ __align__(16) __nv_bfloat16 Ash[2][2][128 * AS_STR]; // [buf][hi/lo]
    __shared__ __align__(16) __nv_bfloat16 Bsh[2][2][16 * BS_STR];

    int tid = threadIdx.x;
    int lane = tid & 31;
    int wid = tid >> 5;
    int wm = wid & 3;           // 4 m-groups of 32 rows
    int wn = wid >> 2;          // 2 n-groups of 64 cols
    int m0 = blockIdx.y * 128;
    int n0 = blockIdx.x * 128;

    // loader indices
    int lkA = tid >> 5;            // ATRANS: k row 0..7 (and +8)
    int lmA = (tid & 31) * 4;      // ATRANS: m offset
    int lmB = tid >> 1;            // !ATRANS: m row 0..127
    int lkg = (tid & 1) * 8;       // !ATRANS: k offset (8 floats)
    int lkW = tid >> 4;            // W: k row 0..15
    int lnW = (tid & 15) * 8;      // W: n offset (8 floats)

    float acc[2][8][4];
#pragma unroll
    for (int f = 0; f < 2; f++)
#pragma unroll
        for (int n8 = 0; n8 < 8; n8++)
#pragma unroll
            for (int q = 0; q < 4; q++) acc[f][n8][q] = 0.0f;

    int nT = (K + 15) / 16;

    // ---- helpers to fetch one tile's raw fp32 into registers ----
    float va[2][4], vw[2][4];
    auto fetchA = [&](int kt) {
        if (ATRANS) {
#pragma unroll
            for (int s = 0; s < 2; s++) {
                int gk = kt + lkA + s * 8;
                int gm = m0 + lmA;
                if (gk < K && gm + 3 < M) {
                    float4 v = *(const float4*)&A[(size_t)gk * M + gm];
                    va[s][0] = v.x; va[s][1] = v.y; va[s][2] = v.z; va[s][3] = v.w;
                } else {
#pragma unroll
                    for (int q = 0; q < 4; q++)
                        va[s][q] = (gk < K && gm + q < M) ? A[(size_t)gk * M + gm + q] : 0.0f;
                }
            }
        } else {
            int gm = m0 + lmB;
#pragma unroll
            for (int s = 0; s < 2; s++) {
                if (gm < M) {
                    float4 v = *(const float4*)&A[(size_t)gm * K + kt + lkg + s * 4];
                    va[s][0] = v.x; va[s][1] = v.y; va[s][2] = v.z; va[s][3] = v.w;
                } else {
                    va[s][0] = va[s][1] = va[s][2] = va[s][3] = 0.0f;
                }
            }
        }
    };
    auto fetchW = [&](int kt) {
        int gk = kt + lkW;
#pragma unroll
        for (int s = 0; s < 2; s++) {
            if (gk < K) {
                float4 v = *(const float4*)&W[(size_t)gk * N + n0 + lnW + s * 4];
                vw[s][0] = v.x; vw[s][1] = v.y; vw[s][2] = v.z; vw[s][3] = v.w;
            } else {
                vw[s][0] = vw[s][1] = vw[s][2] = vw[s][3] = 0.0f;
            }
        }
    };
    auto commit = [&](int buf) {
        if (ATRANS) {
#pragma unroll
            for (int s = 0; s < 2; s++)
#pragma unroll
                for (int q = 0; q < 4; q++) {
                    __nv_bfloat16 h, l;
                    bsplit(va[s][q], h, l);
                    Ash[buf][0][(lmA + q) * AS_STR + lkA + s * 8] = h;
                    Ash[buf][1][(lmA + q) * AS_STR + lkA + s * 8] = l;
                }
        } else {
#pragma unroll
            for (int s = 0; s < 2; s++)
#pragma unroll
                for (int q = 0; q < 4; q++) {
                    __nv_bfloat16 h, l;
                    bsplit(va[s][q], h, l);
                    Ash[buf][0][lmB * AS_STR + lkg + s * 4 + q] = h;
                    Ash[buf][1][lmB * AS_STR + lkg + s * 4 + q] = l;
                }
        }
#pragma unroll
        for (int s = 0; s < 2; s++)
#pragma unroll
            for (int q = 0; q < 4; q++) {
                __nv_bfloat16 h, l;
                bsplit(vw[s][q], h, l);
                Bsh[buf][0][lkW * BS_STR + lnW + s * 4 + q] = h;
                Bsh[buf][1][lkW * BS_STR + lnW + s * 4 + q] = l;
            }
    };

    // frag smem address offsets (bytes)
    unsigned aoff = ((wm * 32 + (lane & 15)) * AS_STR + (lane >> 4) * 8) * 2;
    unsigned boff = ((lane & 15) * BS_STR + wn * 64 + (lane >> 4) * 8) * 2;

    // ---- preload tile 0 ----
    fetchA(0); fetchW(0);
    commit(0);
    __syncthreads();

    for (int t = 0; t < nT; t++) {
        int cur = t & 1;
        bool has = (t + 1 < nT);
        if (has) { fetchA((t + 1) * 16); fetchW((t + 1) * 16); }

        unsigned aBaseH = smem_u32(&Ash[cur][0][0]) + aoff;
        unsigned aBaseL = smem_u32(&Ash[cur][1][0]) + aoff;
        unsigned bBaseH = smem_u32(&Bsh[cur][0][0]) + boff;
        unsigned bBaseL = smem_u32(&Bsh[cur][1][0]) + boff;

        unsigned ah[2][4], al[2][4], bh[4][4], bl[4][4];
#pragma unroll
        for (int f = 0; f < 2; f++) {
            ldsm4(ah[f], aBaseH + f * 16 * AS_STR * 2);
            ldsm4(al[f], aBaseL + f * 16 * AS_STR * 2);
        }
#pragma unroll
        for (int nb = 0; nb < 4; nb++) {
            ldsm4t(bh[nb], bBaseH + nb * 32);
            ldsm4t(bl[nb], bBaseL + nb * 32);
        }

#pragma unroll
        for (int f = 0; f < 2; f++)
#pragma unroll
            for (int nb = 0; nb < 4; nb++)
#pragma unroll
                for (int j = 0; j < 2; j++) {
                    float* d = acc[f][nb * 2 + j];
                    unsigned bh0 = bh[nb][2 * j], bh1 = bh[nb][2 * j + 1];
                    unsigned bl0 = bl[nb][2 * j], bl1 = bl[nb][2 * j + 1];
                    mma_bf16(d, ah[f], bh0, bh1);
                    mma_bf16(d, ah[f], bl0, bl1);
                    mma_bf16(d, al[f], bh0, bh1);
                }

        if (has) commit(cur ^ 1);
        __syncthreads();
    }

    // ---- epilogue: bias + swish + store ----
#pragma unroll
    for (int f = 0; f < 2; f++) {
#pragma unroll
        for (int n8 = 0; n8 < 8; n8++) {
            int rm = m0 + wm * 32 + f * 16 + (lane >> 2);
            int cn = n0 + wn * 64 + n8 * 8 + (lane & 3) * 2;
            float b0 = bias[cn], b1 = bias[cn + 1];
            if (rm < M) {
                float v0 = acc[f][n8][0] + b0;
                float v1 = acc[f][n8][1] + b1;
                if (SWISH) {
                    v0 = v0 / (1.0f + __expf(-v0));
                    v1 = v1 / (1.0f + __expf(-v1));
                }
                *(float2*)&C[(size_t)rm * N + cn] = make_float2(v0, v1);
            }
            if (rm + 8 < M) {
                float v2 = acc[f][n8][2] + b0;
                float v3 = acc[f][n8][3] + b1;
                if (SWISH) {
                    v2 = v2 / (1.0f + __expf(-v2));
                    v3 = v3 / (1.0f + __expf(-v3));
                }
                *(float2*)&C[(size_t)(rm + 8) * N + cn] = make_float2(v2, v3);
            }
        }
    }
}

// ---------------- final layer: per-row dot + scale/shift ----------------
__global__ __launch_bounds__(256) void out_kernel(
    const float* __restrict__ w3, const float* __restrict__ b3,
    const float* __restrict__ scale, const float* __restrict__ shift,
    const int* __restrict__ Z, float* __restrict__ out)
{
    int gw = (blockIdx.x * blockDim.x + threadIdx.x) >> 5;
    int lane = threadIdx.x & 31;
    if (gw >= NATOMS) return;
    const float* h = g_H2 + (size_t)gw * NU2;
    float s = 0.0f;
#pragma unroll
    for (int t = 0; t < NU2 / 32; t++) {
        int i = lane + t * 32;
        s = fmaf(h[i], w3[i], s);
    }
#pragma unroll
    for (int o = 16; o; o >>= 1) s += __shfl_xor_sync(0xffffffffu, s, o);
    if (lane == 0) {
        float v = s + b3[0];
        int z = Z[gw];
        out[gw] = scale[z] * v + shift[z];
    }
}

// ---------------- launch ----------------
extern "C" void kernel_launch(void* const* d_in, const int* in_sizes, int n_in,
                              void* d_out, int out_size)
{
    const float* R     = (const float*)d_in[0];
    const int*   Z     = (const int*)  d_in[1];
    const int*   idx   = (const int*)  d_in[2];
    const float* Wr    = (const float*)d_in[3];
    const float* w1    = (const float*)d_in[4];
    const float* b1    = (const float*)d_in[5];
    const float* w2    = (const float*)d_in[6];
    const float* b2    = (const float*)d_in[7];
    const float* w3    = (const float*)d_in[8];
    const float* b3    = (const float*)d_in[9];
    const float* scale = (const float*)d_in[10];
    const float* shift = (const float*)d_in[11];
    float* out = (float*)d_out;

    float *pGM = nullptr, *pH1 = nullptr, *pH2 = nullptr;
    cudaGetSymbolAddress((void**)&pGM, g_GM);
    cudaGetSymbolAddress((void**)&pH1, g_H1);
    cudaGetSymbolAddress((void**)&pH2, g_H2);

    prep_kernel<<<(NATOMS + 255) / 256, 256>>>(R);
    hist_kernel<<<(NPAIRS + 255) / 256, 256>>>(idx);
    scan_kernel<<<1, 1024>>>();
    scatter_kernel<<<(NPAIRS + 255) / 256, 256>>>(Z, idx, Wr);
    accum_kernel<<<(NATOMS * NRAD + 255) / 256, 256>>>();
    feat_kernel<<<(NATOMS + 127) / 128, 128>>>();

    dim3 g1(NU1 / 128, (NATOMS + 127) / 128);
    mma_gemm_kernel<true, true><<<g1, 256>>>(pGM, w1, b1, pH1, NATOMS, NU1, NFEAT);

    dim3 g2(NU2 / 128, (NATOMS + 127) / 128);
    mma_gemm_kernel<false, true><<<g2, 256>>>(pH1, w2, b2, pH2, NATOMS, NU2, NU1);

    out_kernel<<<(NATOMS * 32 + 255) / 256, 256>>>(w3, b3, scale, shift, Z, out);
}

// round 7
// speedup vs baseline: 2.3728x; 1.0745x over previous
#include <cuda_runtime.h>
#include <cuda_bf16.h>
#include <math.h>

#define NATOMS 30000
#define NPAIRS 1200000
#define NBASIS 7
#define NRAD   5
#define NSPEC  119
#define NFEAT  360
#define NFEATP 368          // K padded to multiple of 16
#define AP     30080        // M (atoms) padded to multiple of 128/8
#define NMOM   100
#define NU1    512
#define NU2    512

// ---------------- static scratch (no allocations allowed) ----------------
__device__ int    g_cnt[NATOMS];
__device__ int    g_off[NATOMS];
__device__ int    g_cur[NATOMS];
__device__ float4 g_R4[NATOMS];
__device__ float  g_pd[(size_t)NPAIRS * 8];
__device__ float  g_Mom[NMOM * NATOMS];
// bf16 hi/lo operand buffers (zero-initialized at load; pads never written)
__device__ __nv_bfloat16 g_GMh[(size_t)NFEATP * AP];
__device__ __nv_bfloat16 g_GMl[(size_t)NFEATP * AP];
__device__ __nv_bfloat16 g_w1h[NFEATP * NU1];
__device__ __nv_bfloat16 g_w1l[NFEATP * NU1];
__device__ __nv_bfloat16 g_w2h[NU1 * NU2];
__device__ __nv_bfloat16 g_w2l[NU1 * NU2];
__device__ __nv_bfloat16 g_H1h[(size_t)NATOMS * NU1];
__device__ __nv_bfloat16 g_H1l[(size_t)NATOMS * NU1];
__device__ float  g_H2 [(size_t)NATOMS * NU2];

__device__ __forceinline__ void bsplit(float v, __nv_bfloat16& h, __nv_bfloat16& l) {
    h = __float2bfloat16(v);
    l = __float2bfloat16(v - __bfloat162float(h));
}

// ---------------- prep: zero counters + pad R ----------------
__global__ void prep_kernel(const float* __restrict__ R) {
    int i = blockIdx.x * blockDim.x + threadIdx.x;
    if (i < NATOMS) {
        g_cnt[i] = 0;
        g_R4[i] = make_float4(R[3*i+0], R[3*i+1], R[3*i+2], 0.0f);
    }
}

// ---------------- convert weights to bf16 hi/lo (w1 padded in K) ----------------
__global__ void convw_kernel(const float* __restrict__ w1, const float* __restrict__ w2) {
    int i = blockIdx.x * blockDim.x + threadIdx.x;
    if (i < NFEATP * NU1) {
        int k = i / NU1, n = i % NU1;
        float v = (k < NFEAT) ? w1[(size_t)k * NU1 + n] : 0.0f;
        bsplit(v, g_w1h[i], g_w1l[i]);
    }
    if (i < NU1 * NU2) {
        bsplit(w2[i], g_w2h[i], g_w2l[i]);
    }
}

// ---------------- histogram ----------------
__global__ __launch_bounds__(256) void hist_kernel(const int* __restrict__ idx) {
    int p = blockIdx.x * blockDim.x + threadIdx.x;
    if (p < NPAIRS) atomicAdd(&g_cnt[idx[p]], 1);
}

// ---------------- single-block shuffle-based exclusive scan ----------------
__global__ __launch_bounds__(1024) void scan_kernel() {
    __shared__ int wsum[32];
    __shared__ int chunk_base;
    int tid = threadIdx.x;
    int lane = tid & 31, wid = tid >> 5;
    if (tid == 0) chunk_base = 0;
    __syncthreads();
    for (int base = 0; base < NATOMS; base += 1024) {
        int i = base + tid;
        int v = (i < NATOMS) ? g_cnt[i] : 0;
        int x = v;
#pragma unroll
        for (int o = 1; o < 32; o <<= 1) {
            int y = __shfl_up_sync(0xffffffffu, x, o);
            if (lane >= o) x += y;
        }
        if (lane == 31) wsum[wid] = x;
        __syncthreads();
        if (wid == 0) {
            int w = wsum[lane];
            int xs = w;
#pragma unroll
            for (int o = 1; o < 32; o <<= 1) {
                int y = __shfl_up_sync(0xffffffffu, xs, o);
                if (lane >= o) xs += y;
            }
            wsum[lane] = xs - w;
        }
        __syncthreads();
        int ex = chunk_base + wsum[wid] + x - v;
        if (i < NATOMS) { g_off[i] = ex; g_cur[i] = ex; }
        __syncthreads();
        if (tid == 1023) chunk_base += wsum[31] + x;
        __syncthreads();
    }
}

// ---------------- per-pair math + scatter ----------------
__global__ __launch_bounds__(256) void scatter_kernel(
    const int* __restrict__ Z,
    const int* __restrict__ idx, const float* __restrict__ Wr)
{
    int p = blockIdx.x * blockDim.x + threadIdx.x;
    if (p >= NPAIRS) return;
    int i = idx[p];
    int j = idx[NPAIRS + p];

    float4 Ri = g_R4[i];
    float4 Rj = g_R4[j];
    float dx = Rj.x - Ri.x;
    float dy = Rj.y - Ri.y;
    float dz = Rj.z - Ri.z;
    float dr = sqrtf(dx*dx + dy*dy + dz*dz + 1e-12f);

    const float PI = 3.14159265358979323846f;
    float cut = (dr < 6.0f)
              ? 0.5f * (__cosf((PI / 6.0f) * dr) + 1.0f) * 0.37796447300922720f
              : 0.0f;

    float inv = 1.0f / (dr + 1e-5f);
    float ux = dx * inv, uy = dy * inv, uz = dz * inv;

    const float betta = 49.0f / 36.0f;
    const float rn = 0.9601717136386805f;
    float basis[NBASIS];
#pragma unroll
    for (int b = 0; b < NBASIS; b++) {
        float d = dr - (0.5f + 0.7857142857142857f * (float)b);
        basis[b] = rn * __expf(-betta * d * d);
    }

    int zi = Z[i], zj = Z[j];
    const float* cf = Wr + ((size_t)(zi * NSPEC + zj) * NRAD) * NBASIS;
    float radial[NRAD];
#pragma unroll
    for (int k = 0; k < NRAD; k++) {
        float s = 0.0f;
#pragma unroll
        for (int b = 0; b < NBASIS; b++) s = fmaf(cf[k*NBASIS + b], basis[b], s);
        radial[k] = s * cut;
    }

    int pos = atomicAdd(&g_cur[i], 1);
    float4 lo = make_float4(radial[0], radial[1], radial[2], radial[3]);
    float4 hi = make_float4(radial[4], ux, uy, uz);
    *(float4*)&g_pd[(size_t)pos * 8 + 0] = lo;
    *(float4*)&g_pd[(size_t)pos * 8 + 4] = hi;
}

// ---------------- per-(atom, radial) moment accumulation ----------------
__global__ __launch_bounds__(256) void accum_kernel()
{
    int t = blockIdx.x * blockDim.x + threadIdx.x;
    if (t >= NATOMS * NRAD) return;
    int k = t / NATOMS;
    int a = t - k * NATOMS;

    int beg = g_off[a];
    int end = beg + g_cnt[a];

    float acc[20];
#pragma unroll
    for (int m = 0; m < 20; m++) acc[m] = 0.0f;

    for (int p = beg; p < end; p++) {
        float4 lo = *(const float4*)&g_pd[(size_t)p * 8 + 0];
        float4 hi = *(const float4*)&g_pd[(size_t)p * 8 + 4];
        float rk;
        switch (k) {
            case 0: rk = lo.x; break;
            case 1: rk = lo.y; break;
            case 2: rk = lo.z; break;
            case 3: rk = lo.w; break;
            default: rk = hi.x; break;
        }
        float ux = hi.y, uy = hi.z, uz = hi.w;
        float xx = ux*ux, yy = uy*uy, zz = uz*uz;
        float xy = ux*uy, xz = ux*uz, yz = uy*uz;

        acc[0]  += rk;
        acc[1]  = fmaf(rk, ux, acc[1]);
        acc[2]  = fmaf(rk, uy, acc[2]);
        acc[3]  = fmaf(rk, uz, acc[3]);
        acc[4]  = fmaf(rk, xx, acc[4]);
        acc[5]  = fmaf(rk, yy, acc[5]);
        acc[6]  = fmaf(rk, zz, acc[6]);
        acc[7]  = fmaf(rk, xy, acc[7]);
        acc[8]  = fmaf(rk, xz, acc[8]);
        acc[9]  = fmaf(rk, yz, acc[9]);
        acc[10] = fmaf(rk, xx*ux, acc[10]);
        acc[11] = fmaf(rk, xx*uy, acc[11]);
        acc[12] = fmaf(rk, xx*uz, acc[12]);
        acc[13] = fmaf(rk, yy*ux, acc[13]);
        acc[14] = fmaf(rk, xy*uz, acc[14]);
        acc[15] = fmaf(rk, zz*ux, acc[15]);
        acc[16] = fmaf(rk, yy*uy, acc[16]);
        acc[17] = fmaf(rk, yy*uz, acc[17]);
        acc[18] = fmaf(rk, zz*uy, acc[18]);
        acc[19] = fmaf(rk, zz*uz, acc[19]);
    }

#pragma unroll
    for (int m = 0; m < 20; m++)
        g_Mom[(size_t)(k * 20 + m) * NATOMS + a] = acc[m];
}

// ---------------- per-atom invariant contractions -> 360 bf16 hi/lo features ----------------
__global__ __launch_bounds__(128) void feat_kernel()
{
    int a = blockIdx.x * blockDim.x + threadIdx.x;
    if (a >= NATOMS) return;

    const int T2[9]  = {0,3,4, 3,1,5, 4,5,2};
    const int T3[27] = {0,1,2, 1,3,4, 2,4,5,
                        1,3,4, 3,6,7, 4,7,8,
                        2,4,5, 4,7,8, 5,8,9};

    float m0v[NRAD];
    float m1v[NRAD][3];
    float m2v[NRAD][9];
    float m3v[NRAD][27];

    for (int k = 0; k < NRAD; k++) {
        const float* base = g_Mom + (size_t)(k*20) * NATOMS;
        m0v[k] = base[a];
        for (int d = 0; d < 3; d++) m1v[k][d] = base[(1+d)*NATOMS + a];
        float s2[6];
        for (int u = 0; u < 6; u++) s2[u] = base[(4+u)*NATOMS + a];
        for (int e = 0; e < 9; e++) m2v[k][e] = s2[T2[e]];
        float s3[10];
        for (int u = 0; u < 10; u++) s3[u] = base[(10+u)*NATOMS + a];
        for (int e = 0; e < 27; e++) m3v[k][e] = s3[T3[e]];
    }

    int f = 0;
#define EMIT(v) do { __nv_bfloat16 _h, _l; bsplit((v), _h, _l); \
    g_GMh[(size_t)(f) * AP + a] = _h; g_GMl[(size_t)(f) * AP + a] = _l; f++; } while (0)

    for (int k = 0; k < NRAD; k++) EMIT(m0v[k]);

    for (int r = 0; r < NRAD; r++)
        for (int s = r; s < NRAD; s++) {
            float v = m1v[r][0]*m1v[s][0] + m1v[r][1]*m1v[s][1] + m1v[r][2]*m1v[s][2];
            EMIT(v);
        }

    for (int r = 0; r < NRAD; r++)
        for (int s = r; s < NRAD; s++) {
            float v = 0.0f;
            for (int e = 0; e < 9; e++) v = fmaf(m2v[r][e], m2v[s][e], v);
            EMIT(v);
        }

    for (int r = 0; r < NRAD; r++)
        for (int s = r; s < NRAD; s++) {
            float v = 0.0f;
            for (int e = 0; e < 27; e++) v = fmaf(m3v[r][e], m3v[s][e], v);
            EMIT(v);
        }

    for (int r = 0; r < NRAD; r++)
        for (int s = r; s < NRAD; s++)
            for (int t = s; t < NRAD; t++) {
                float v = 0.0f;
                for (int jj = 0; jj < 3; jj++)
                    for (int kk = 0; kk < 3; kk++) {
                        float pjk = 0.0f;
                        for (int ii = 0; ii < 3; ii++)
                            pjk = fmaf(m2v[r][ii*3 + jj], m2v[s][ii*3 + kk], pjk);
                        v = fmaf(pjk, m2v[t][jj*3 + kk], v);
                    }
                EMIT(v);
            }

    for (int r = 0; r < NRAD; r++)
        for (int s = r; s < NRAD; s++) {
            float O[9];
            for (int ii = 0; ii < 3; ii++)
                for (int jj = 0; jj < 3; jj++)
                    O[ii*3 + jj] = m1v[r][ii] * m1v[s][jj];
            for (int t = 0; t < NRAD; t++) {
                float v = 0.0f;
                for (int e = 0; e < 9; e++) v = fmaf(O[e], m2v[t][e], v);
                EMIT(v);
            }
        }

    for (int r = 0; r < NRAD; r++)
        for (int s = r; s < NRAD; s++) {
            float T[9];
            for (int kk = 0; kk < 3; kk++)
                for (int ll = 0; ll < 3; ll++) {
                    float acc2 = 0.0f;
                    for (int ij = 0; ij < 9; ij++)
                        acc2 = fmaf(m3v[r][ij*3 + kk], m3v[s][ij*3 + ll], acc2);
                    T[kk*3 + ll] = acc2;
                }
            for (int t = 0; t < NRAD; t++) {
                float v = 0.0f;
                for (int e = 0; e < 9; e++) v = fmaf(T[e], m2v[t][e], v);
                EMIT(v);
            }
        }

    for (int r = 0; r < NRAD; r++)
        for (int s = 0; s < NRAD; s++) {
            float w[3];
            for (int kk = 0; kk < 3; kk++) {
                float acc2 = 0.0f;
                for (int ij = 0; ij < 9; ij++)
                    acc2 = fmaf(m3v[r][ij*3 + kk], m2v[s][ij], acc2);
                w[kk] = acc2;
            }
            for (int t = 0; t < NRAD; t++) {
                float v = w[0]*m1v[t][0] + w[1]*m1v[t][1] + w[2]*m1v[t][2];
                EMIT(v);
            }
        }
#undef EMIT
}

// ============================================================================
// bf16x3 tensor-core GEMMs on pre-converted hi/lo operands.
// CTA tile 128x128, 8 warps (4m x 2n), BK=16, reg-prefetch double buffer.
// acc += Ah*Bh + Ah*Bl + Al*Bh (fp32 accumulators).
// ============================================================================
#define AS_STR  24    // gemm2 A smem: [m][k] rows of 16 + pad
#define KM_STR  136   // gemm1 A smem: [k][m] rows of 128 + pad; also B smem [k][n]

__device__ __forceinline__ unsigned smem_u32(const void* p) {
    return (unsigned)__cvta_generic_to_shared(p);
}
__device__ __forceinline__ void ldsm4(unsigned* r, unsigned addr) {
    asm volatile("ldmatrix.sync.aligned.m8n8.x4.shared.b16 {%0,%1,%2,%3}, [%4];"
        : "=r"(r[0]), "=r"(r[1]), "=r"(r[2]), "=r"(r[3]) : "r"(addr));
}
__device__ __forceinline__ void ldsm4t(unsigned* r, unsigned addr) {
    asm volatile("ldmatrix.sync.aligned.m8n8.x4.trans.shared.b16 {%0,%1,%2,%3}, [%4];"
        : "=r"(r[0]), "=r"(r[1]), "=r"(r[2]), "=r"(r[3]) : "r"(addr));
}
__device__ __forceinline__ void mma_bf16(float* d, const unsigned* a, unsigned b0, unsigned b1) {
    asm volatile("mma.sync.aligned.m16n8k16.row.col.f32.bf16.bf16.f32 "
        "{%0,%1,%2,%3}, {%4,%5,%6,%7}, {%8,%9}, {%0,%1,%2,%3};"
        : "+f"(d[0]), "+f"(d[1]), "+f"(d[2]), "+f"(d[3])
        : "r"(a[0]), "r"(a[1]), "r"(a[2]), "r"(a[3]), "r"(b0), "r"(b1));
}

// LAYER: 1 = GM(KxM bf16, K-major) -> H1 bf16 hi/lo, swish
//        2 = H1(MxK bf16) -> H2 fp32, swish
template<int LAYER>
__global__ __launch_bounds__(256) void mma_gemm_kernel(
    const __nv_bfloat16* __restrict__ Ah, const __nv_bfloat16* __restrict__ Al,
    const __nv_bfloat16* __restrict__ Bh, const __nv_bfloat16* __restrict__ Bl,
    const float* __restrict__ bias,
    int M, int N, int K, int Astride)
{
    // A smem: LAYER==1 -> [k][m] (KM_STR), LAYER==2 -> [m][k] (AS_STR)
    __shared__ __align__(16) __nv_bfloat16 Ash[2][2][(16 * KM_STR > 128 * AS_STR) ? 16 * KM_STR : 128 * AS_STR];
    __shared__ __align__(16) __nv_bfloat16 Bsh[2][2][16 * KM_STR];

    int tid = threadIdx.x;
    int lane = tid & 31;
    int wid = tid >> 5;
    int wm = wid & 3;
    int wn = wid >> 2;
    int m0 = blockIdx.y * 128;
    int n0 = blockIdx.x * 128;

    // loader indices (one uint4 = 8 bf16 per thread per half)
    int lk = tid >> 4;             // 0..15 (k row)     [LAYER1 A, and B]
    int lm8 = (tid & 15) * 8;      // m/n offset
    int lmB = tid >> 1;            // LAYER2 A: m row 0..127
    int lkg = (tid & 1) * 8;       // LAYER2 A: k offset

    float acc[2][8][4];
#pragma unroll
    for (int f = 0; f < 2; f++)
#pragma unroll
        for (int n8 = 0; n8 < 8; n8++)
#pragma unroll
            for (int q = 0; q < 4; q++) acc[f][n8][q] = 0.0f;

    int nT = K / 16;

    uint4 pah, pal, pwh, pwl;
    auto fetch = [&](int kt) {
        if (LAYER == 1) {
            size_t off = (size_t)(kt + lk) * Astride + m0 + lm8;
            pah = *(const uint4*)&Ah[off];
            pal = *(const uint4*)&Al[off];
        } else {
            int gm = m0 + lmB;
            if (gm < M) {
                size_t off = (size_t)gm * K + kt + lkg;
                pah = *(const uint4*)&Ah[off];
                pal = *(const uint4*)&Al[off];
            } else {
                pah = make_uint4(0,0,0,0);
                pal = make_uint4(0,0,0,0);
            }
        }
        size_t woff = (size_t)(kt + lk) * N + n0 + lm8;
        pwh = *(const uint4*)&Bh[woff];
        pwl = *(const uint4*)&Bl[woff];
    };
    auto commit = [&](int buf) {
        if (LAYER == 1) {
            *(uint4*)&Ash[buf][0][lk * KM_STR + lm8] = pah;
            *(uint4*)&Ash[buf][1][lk * KM_STR + lm8] = pal;
        } else {
            *(uint4*)&Ash[buf][0][lmB * AS_STR + lkg] = pah;
            *(uint4*)&Ash[buf][1][lmB * AS_STR + lkg] = pal;
        }
        *(uint4*)&Bsh[buf][0][lk * KM_STR + lm8] = pwh;
        *(uint4*)&Bsh[buf][1][lk * KM_STR + lm8] = pwl;
    };

    // fragment smem byte offsets
    unsigned aoff;
    if (LAYER == 1) {
        // [k][m]: trans ldsm. lanes 0-7: k0-7,m+0; 8-15: k0-7,m+8; 16-23: k8-15,m+0; 24-31: k8-15,m+8
        int krow = (lane & 7) + ((lane >> 4) << 3);
        int mcol = wm * 32 + (((lane >> 3) & 1) << 3);
        aoff = (krow * KM_STR + mcol) * 2;
    } else {
        // [m][k]: non-trans ldsm (verified in R6)
        aoff = ((wm * 32 + (lane & 15)) * AS_STR + (lane >> 4) * 8) * 2;
    }
    unsigned boff = ((lane & 15) * KM_STR + wn * 64 + (lane >> 4) * 8) * 2;

    fetch(0);
    commit(0);
    __syncthreads();

    for (int t = 0; t < nT; t++) {
        int cur = t & 1;
        bool has = (t + 1 < nT);
        if (has) fetch((t + 1) * 16);

        unsigned aBaseH = smem_u32(&Ash[cur][0][0]) + aoff;
        unsigned aBaseL = smem_u32(&Ash[cur][1][0]) + aoff;
        unsigned bBaseH = smem_u32(&Bsh[cur][0][0]) + boff;
        unsigned bBaseL = smem_u32(&Bsh[cur][1][0]) + boff;

        unsigned ah[2][4], al[2][4], bh[4][4], bl[4][4];
#pragma unroll
        for (int f = 0; f < 2; f++) {
            if (LAYER == 1) {
                ldsm4t(ah[f], aBaseH + f * 16 * 2);          // +16 m cols
                ldsm4t(al[f], aBaseL + f * 16 * 2);
            } else {
                ldsm4(ah[f], aBaseH + f * 16 * AS_STR * 2);  // +16 m rows
                ldsm4(al[f], aBaseL + f * 16 * AS_STR * 2);
            }
        }
#pragma unroll
        for (int nb = 0; nb < 4; nb++) {
            ldsm4t(bh[nb], bBaseH + nb * 32);
            ldsm4t(bl[nb], bBaseL + nb * 32);
        }

#pragma unroll
        for (int f = 0; f < 2; f++)
#pragma unroll
            for (int nb = 0; nb < 4; nb++)
#pragma unroll
                for (int j = 0; j < 2; j++) {
                    float* d = acc[f][nb * 2 + j];
                    unsigned bh0 = bh[nb][2 * j], bh1 = bh[nb][2 * j + 1];
                    unsigned bl0 = bl[nb][2 * j], bl1 = bl[nb][2 * j + 1];
                    mma_bf16(d, ah[f], bh0, bh1);
                    mma_bf16(d, ah[f], bl0, bl1);
                    mma_bf16(d, al[f], bh0, bh1);
                }

        if (has) commit(cur ^ 1);
        __syncthreads();
    }

    // ---- epilogue: bias + swish; LAYER1 -> bf16 hi/lo, LAYER2 -> fp32 ----
#pragma unroll
    for (int f = 0; f < 2; f++) {
#pragma unroll
        for (int n8 = 0; n8 < 8; n8++) {
            int rm = m0 + wm * 32 + f * 16 + (lane >> 2);
            int cn = n0 + wn * 64 + n8 * 8 + (lane & 3) * 2;
            float b0 = bias[cn], b1 = bias[cn + 1];
#pragma unroll
            for (int half = 0; half < 2; half++) {
                int r = rm + half * 8;
                if (r >= M) continue;
                float v0 = acc[f][n8][half * 2 + 0] + b0;
                float v1 = acc[f][n8][half * 2 + 1] + b1;
                v0 = v0 / (1.0f + __expf(-v0));
                v1 = v1 / (1.0f + __expf(-v1));
                if (LAYER == 1) {
                    __nv_bfloat16 h0, l0, h1, l1;
                    bsplit(v0, h0, l0); bsplit(v1, h1, l1);
                    *(__nv_bfloat162*)&g_H1h[(size_t)r * NU1 + cn] = __nv_bfloat162(h0, h1);
                    *(__nv_bfloat162*)&g_H1l[(size_t)r * NU1 + cn] = __nv_bfloat162(l0, l1);
                } else {
                    *(float2*)&g_H2[(size_t)r * NU2 + cn] = make_float2(v0, v1);
                }
            }
        }
    }
}

// ---------------- final layer: per-row dot + scale/shift ----------------
__global__ __launch_bounds__(256) void out_kernel(
    const float* __restrict__ w3, const float* __restrict__ b3,
    const float* __restrict__ scale, const float* __restrict__ shift,
    const int* __restrict__ Z, float* __restrict__ out)
{
    int gw = (blockIdx.x * blockDim.x + threadIdx.x) >> 5;
    int lane = threadIdx.x & 31;
    if (gw >= NATOMS) return;
    const float* h = g_H2 + (size_t)gw * NU2;
    float s = 0.0f;
#pragma unroll
    for (int t = 0; t < NU2 / 32; t++) {
        int i = lane + t * 32;
        s = fmaf(h[i], w3[i], s);
    }
#pragma unroll
    for (int o = 16; o; o >>= 1) s += __shfl_xor_sync(0xffffffffu, s, o);
    if (lane == 0) {
        float v = s + b3[0];
        int z = Z[gw];
        out[gw] = scale[z] * v + shift[z];
    }
}

// ---------------- launch ----------------
extern "C" void kernel_launch(void* const* d_in, const int* in_sizes, int n_in,
                              void* d_out, int out_size)
{
    const float* R     = (const float*)d_in[0];
    const int*   Z     = (const int*)  d_in[1];
    const int*   idx   = (const int*)  d_in[2];
    const float* Wr    = (const float*)d_in[3];
    const float* w1    = (const float*)d_in[4];
    const float* b1    = (const float*)d_in[5];
    const float* w2    = (const float*)d_in[6];
    const float* b2    = (const float*)d_in[7];
    const float* w3    = (const float*)d_in[8];
    const float* b3    = (const float*)d_in[9];
    const float* scale = (const float*)d_in[10];
    const float* shift = (const float*)d_in[11];
    float* out = (float*)d_out;

    __nv_bfloat16 *pGMh, *pGMl, *pW1h, *pW1l, *pW2h, *pW2l, *pH1h, *pH1l;
    cudaGetSymbolAddress((void**)&pGMh, g_GMh);
    cudaGetSymbolAddress((void**)&pGMl, g_GMl);
    cudaGetSymbolAddress((void**)&pW1h, g_w1h);
    cudaGetSymbolAddress((void**)&pW1l, g_w1l);
    cudaGetSymbolAddress((void**)&pW2h, g_w2h);
    cudaGetSymbolAddress((void**)&pW2l, g_w2l);
    cudaGetSymbolAddress((void**)&pH1h, g_H1h);
    cudaGetSymbolAddress((void**)&pH1l, g_H1l);

    prep_kernel<<<(NATOMS + 255) / 256, 256>>>(R);
    convw_kernel<<<(NU1 * NU2 + 255) / 256, 256>>>(w1, w2);
    hist_kernel<<<(NPAIRS + 255) / 256, 256>>>(idx);
    scan_kernel<<<1, 1024>>>();
    scatter_kernel<<<(NPAIRS + 255) / 256, 256>>>(Z, idx, Wr);
    accum_kernel<<<(NATOMS * NRAD + 255) / 256, 256>>>();
    feat_kernel<<<(NATOMS + 127) / 128, 128>>>();

    dim3 g1(NU1 / 128, (NATOMS + 127) / 128);
    mma_gemm_kernel<1><<<g1, 256>>>(pGMh, pGMl, pW1h, pW1l, b1, NATOMS, NU1, NFEATP, AP);

    dim3 g2(NU2 / 128, (NATOMS + 127) / 128);
    mma_gemm_kernel<2><<<g2, 256>>>(pH1h, pH1l, pW2h, pW2l, b2, NATOMS, NU2, NU1, 0);

    out_kernel<<<(NATOMS * 32 + 255) / 256, 256>>>(w3, b3, scale, shift, Z, out);
}

// round 10
// speedup vs baseline: 3.0394x; 1.2809x over previous
#include <cuda_runtime.h>
#include <cuda_bf16.h>
#include <math.h>
#include <stdint.h>
#include <cstdint>

#define NATOMS 30000
#define NPAIRS 1200000
#define NBASIS 7
#define NRAD   5
#define NSPEC  119
#define NFEAT  360
#define NFEATP 368          // layer-1 K padded to multiple of 16
#define AP     30080        // atoms padded (unused rows zero)
#define NMOM   100
#define NU1    512
#define NU2    512
#define NSCB   30           // scan blocks

// ---------------- static scratch (no allocations; BSS zero-initialized) ----------------
__device__ int    g_cnt[NATOMS];
__device__ int    g_off[NATOMS];
__device__ int    g_cur[NATOMS];
__device__ int    g_bsum[32];
__device__ float4 g_R4[NATOMS];
__device__ float  g_pd[(size_t)NPAIRS * 8];
__device__ float  g_Mom[NMOM * NATOMS];
// feature-major GM [NFEATP][AP] bf16 hi/lo (pads stay zero)
__device__ __nv_bfloat16 g_GMh[(size_t)NFEATP * AP];
__device__ __nv_bfloat16 g_GMl[(size_t)NFEATP * AP];
__device__ __nv_bfloat16 g_w1h[NFEATP * NU1];
__device__ __nv_bfloat16 g_w1l[NFEATP * NU1];
__device__ __nv_bfloat16 g_w2h[NU1 * NU2];
__device__ __nv_bfloat16 g_w2l[NU1 * NU2];
__device__ __nv_bfloat16 g_H1h[(size_t)NATOMS * NU1];
__device__ __nv_bfloat16 g_H1l[(size_t)NATOMS * NU1];
__device__ float  g_H2 [(size_t)NATOMS * NU2];

__device__ __forceinline__ void bsplit(float v, __nv_bfloat16& h, __nv_bfloat16& l) {
    h = __float2bfloat16(v);
    l = __float2bfloat16(v - __bfloat162float(h));
}

// ---------------- prep ----------------
__global__ void prep_kernel(const float* __restrict__ R) {
    int i = blockIdx.x * blockDim.x + threadIdx.x;
    if (i < NATOMS) {
        g_cnt[i] = 0;
        g_R4[i] = make_float4(R[3*i+0], R[3*i+1], R[3*i+2], 0.0f);
    }
}

// ---------------- weights -> bf16 hi/lo (w1 K-padded) ----------------
__global__ void convw_kernel(const float* __restrict__ w1, const float* __restrict__ w2) {
    int i = blockIdx.x * blockDim.x + threadIdx.x;
    if (i < NFEATP * NU1) {
        int k = i / NU1, n = i % NU1;
        float v = (k < NFEAT) ? w1[(size_t)k * NU1 + n] : 0.0f;
        bsplit(v, g_w1h[i], g_w1l[i]);
    }
    if (i < NU1 * NU2) {
        bsplit(w2[i], g_w2h[i], g_w2l[i]);
    }
}

// ---------------- histogram ----------------
__global__ __launch_bounds__(256) void hist_kernel(const int* __restrict__ idx) {
    int p = blockIdx.x * blockDim.x + threadIdx.x;
    if (p < NPAIRS) atomicAdd(&g_cnt[idx[p]], 1);
}

// ---------------- 3-phase scan ----------------
__global__ __launch_bounds__(1024) void scan1_kernel() {
    __shared__ int wsum[32];
    int tid = threadIdx.x, lane = tid & 31, w = tid >> 5;
    int i = blockIdx.x * 1024 + tid;
    int v = (i < NATOMS) ? g_cnt[i] : 0;
    int x = v;
#pragma unroll
    for (int o = 1; o < 32; o <<= 1) {
        int y = __shfl_up_sync(0xffffffffu, x, o);
        if (lane >= o) x += y;
    }
    if (lane == 31) wsum[w] = x;
    __syncthreads();
    if (w == 0) {
        int t = wsum[lane];
        int xs = t;
#pragma unroll
        for (int o = 1; o < 32; o <<= 1) {
            int y = __shfl_up_sync(0xffffffffu, xs, o);
            if (lane >= o) xs += y;
        }
        wsum[lane] = xs - t;
    }
    __syncthreads();
    if (i < NATOMS) g_off[i] = wsum[w] + x - v;
    if (tid == 1023) g_bsum[blockIdx.x] = wsum[31] + x;
}
__global__ void scan2_kernel() {
    int lane = threadIdx.x;
    int v = (lane < NSCB) ? g_bsum[lane] : 0;
    int x = v;
#pragma unroll
    for (int o = 1; o < 32; o <<= 1) {
        int y = __shfl_up_sync(0xffffffffu, x, o);
        if (lane >= o) x += y;
    }
    if (lane < NSCB) g_bsum[lane] = x - v;
}
__global__ __launch_bounds__(1024) void scan3_kernel() {
    int i = blockIdx.x * 1024 + threadIdx.x;
    if (i < NATOMS) {
        int o = g_off[i] + g_bsum[blockIdx.x];
        g_off[i] = o;
        g_cur[i] = o;
    }
}

// ---------------- per-pair math + scatter ----------------
__global__ __launch_bounds__(256) void scatter_kernel(
    const int* __restrict__ Z,
    const int* __restrict__ idx, const float* __restrict__ Wr)
{
    int p = blockIdx.x * blockDim.x + threadIdx.x;
    if (p >= NPAIRS) return;
    int i = idx[p];
    int j = idx[NPAIRS + p];

    float4 Ri = g_R4[i];
    float4 Rj = g_R4[j];
    float dx = Rj.x - Ri.x;
    float dy = Rj.y - Ri.y;
    float dz = Rj.z - Ri.z;
    float dr = sqrtf(dx*dx + dy*dy + dz*dz + 1e-12f);

    const float PI = 3.14159265358979323846f;
    float cut = (dr < 6.0f)
              ? 0.5f * (__cosf((PI / 6.0f) * dr) + 1.0f) * 0.37796447300922720f
              : 0.0f;

    float inv = 1.0f / (dr + 1e-5f);
    float ux = dx * inv, uy = dy * inv, uz = dz * inv;

    const float betta = 49.0f / 36.0f;
    const float rn = 0.9601717136386805f;
    float basis[NBASIS];
#pragma unroll
    for (int b = 0; b < NBASIS; b++) {
        float d = dr - (0.5f + 0.7857142857142857f * (float)b);
        basis[b] = rn * __expf(-betta * d * d);
    }

    int zi = Z[i], zj = Z[j];
    const float* cf = Wr + ((size_t)(zi * NSPEC + zj) * NRAD) * NBASIS;
    float radial[NRAD];
#pragma unroll
    for (int k = 0; k < NRAD; k++) {
        float s = 0.0f;
#pragma unroll
        for (int b = 0; b < NBASIS; b++) s = fmaf(cf[k*NBASIS + b], basis[b], s);
        radial[k] = s * cut;
    }

    int pos = atomicAdd(&g_cur[i], 1);
    float4 lo = make_float4(radial[0], radial[1], radial[2], radial[3]);
    float4 hi = make_float4(radial[4], ux, uy, uz);
    *(float4*)&g_pd[(size_t)pos * 8 + 0] = lo;
    *(float4*)&g_pd[(size_t)pos * 8 + 4] = hi;
}

// ---------------- per-atom moment accumulation: all 5 radial channels in-register ----------------
__global__ __launch_bounds__(128) void accum_kernel()
{
    int a = blockIdx.x * blockDim.x + threadIdx.x;
    if (a >= NATOMS) return;

    int beg = g_off[a];
    int end = beg + g_cnt[a];

    float acc[NRAD][20];
#pragma unroll
    for (int k = 0; k < NRAD; k++)
#pragma unroll
        for (int m = 0; m < 20; m++) acc[k][m] = 0.0f;

    for (int p = beg; p < end; p++) {
        float4 lo = *(const float4*)&g_pd[(size_t)p * 8 + 0];
        float4 hi = *(const float4*)&g_pd[(size_t)p * 8 + 4];
        float rad[NRAD] = {lo.x, lo.y, lo.z, lo.w, hi.x};
        float ux = hi.y, uy = hi.z, uz = hi.w;
        float g[20];
        g[0] = 1.0f;
        g[1] = ux; g[2] = uy; g[3] = uz;
        float xx = ux*ux, yy = uy*uy, zz = uz*uz;
        float xy = ux*uy, xz = ux*uz, yz = uy*uz;
        g[4] = xx; g[5] = yy; g[6] = zz; g[7] = xy; g[8] = xz; g[9] = yz;
        g[10] = xx*ux; g[11] = xx*uy; g[12] = xx*uz;
        g[13] = yy*ux; g[14] = xy*uz; g[15] = zz*ux;
        g[16] = yy*uy; g[17] = yy*uz; g[18] = zz*uy; g[19] = zz*uz;
#pragma unroll
        for (int k = 0; k < NRAD; k++)
#pragma unroll
            for (int m = 0; m < 20; m++)
                acc[k][m] = fmaf(rad[k], g[m], acc[k][m]);
    }

#pragma unroll
    for (int k = 0; k < NRAD; k++)
#pragma unroll
        for (int m = 0; m < 20; m++)
            g_Mom[(size_t)(k * 20 + m) * NATOMS + a] = acc[k][m];
}

// ---------------- per-atom invariant contractions -> 360 bf16 hi/lo features ----------------
__global__ __launch_bounds__(128) void feat_kernel()
{
    int a = blockIdx.x * blockDim.x + threadIdx.x;
    if (a >= NATOMS) return;

    const int T2[9]  = {0,3,4, 3,1,5, 4,5,2};
    const int T3[27] = {0,1,2, 1,3,4, 2,4,5,
                        1,3,4, 3,6,7, 4,7,8,
                        2,4,5, 4,7,8, 5,8,9};

    float m0v[NRAD];
    float m1v[NRAD][3];
    float m2v[NRAD][9];
    float m3v[NRAD][27];

    for (int k = 0; k < NRAD; k++) {
        const float* base = g_Mom + (size_t)(k*20) * NATOMS;
        m0v[k] = base[a];
        for (int d = 0; d < 3; d++) m1v[k][d] = base[(1+d)*NATOMS + a];
        float s2[6];
        for (int u = 0; u < 6; u++) s2[u] = base[(4+u)*NATOMS + a];
        for (int e = 0; e < 9; e++) m2v[k][e] = s2[T2[e]];
        float s3[10];
        for (int u = 0; u < 10; u++) s3[u] = base[(10+u)*NATOMS + a];
        for (int e = 0; e < 27; e++) m3v[k][e] = s3[T3[e]];
    }

    int f = 0;
#define EMIT(v) do { __nv_bfloat16 _h, _l; bsplit((v), _h, _l); \
    g_GMh[(size_t)(f) * AP + a] = _h; g_GMl[(size_t)(f) * AP + a] = _l; f++; } while (0)

    for (int k = 0; k < NRAD; k++) EMIT(m0v[k]);

    for (int r = 0; r < NRAD; r++)
        for (int s = r; s < NRAD; s++) {
            float v = m1v[r][0]*m1v[s][0] + m1v[r][1]*m1v[s][1] + m1v[r][2]*m1v[s][2];
            EMIT(v);
        }

    for (int r = 0; r < NRAD; r++)
        for (int s = r; s < NRAD; s++) {
            float v = 0.0f;
            for (int e = 0; e < 9; e++) v = fmaf(m2v[r][e], m2v[s][e], v);
            EMIT(v);
        }

    for (int r = 0; r < NRAD; r++)
        for (int s = r; s < NRAD; s++) {
            float v = 0.0f;
            for (int e = 0; e < 27; e++) v = fmaf(m3v[r][e], m3v[s][e], v);
            EMIT(v);
        }

    for (int r = 0; r < NRAD; r++)
        for (int s = r; s < NRAD; s++)
            for (int t = s; t < NRAD; t++) {
                float v = 0.0f;
                for (int jj = 0; jj < 3; jj++)
                    for (int kk = 0; kk < 3; kk++) {
                        float pjk = 0.0f;
                        for (int ii = 0; ii < 3; ii++)
                            pjk = fmaf(m2v[r][ii*3 + jj], m2v[s][ii*3 + kk], pjk);
                        v = fmaf(pjk, m2v[t][jj*3 + kk], v);
                    }
                EMIT(v);
            }

    for (int r = 0; r < NRAD; r++)
        for (int s = r; s < NRAD; s++) {
            float O[9];
            for (int ii = 0; ii < 3; ii++)
                for (int jj = 0; jj < 3; jj++)
                    O[ii*3 + jj] = m1v[r][ii] * m1v[s][jj];
            for (int t = 0; t < NRAD; t++) {
                float v = 0.0f;
                for (int e = 0; e < 9; e++) v = fmaf(O[e], m2v[t][e], v);
                EMIT(v);
            }
        }

    for (int r = 0; r < NRAD; r++)
        for (int s = r; s < NRAD; s++) {
            float T[9];
            for (int kk = 0; kk < 3; kk++)
                for (int ll = 0; ll < 3; ll++) {
                    float acc2 = 0.0f;
                    for (int ij = 0; ij < 9; ij++)
                        acc2 = fmaf(m3v[r][ij*3 + kk], m3v[s][ij*3 + ll], acc2);
                    T[kk*3 + ll] = acc2;
                }
            for (int t = 0; t < NRAD; t++) {
                float v = 0.0f;
                for (int e = 0; e < 9; e++) v = fmaf(T[e], m2v[t][e], v);
                EMIT(v);
            }
        }

    for (int r = 0; r < NRAD; r++)
        for (int s = 0; s < NRAD; s++) {
            float w[3];
            for (int kk = 0; kk < 3; kk++) {
                float acc2 = 0.0f;
                for (int ij = 0; ij < 9; ij++)
                    acc2 = fmaf(m3v[r][ij*3 + kk], m2v[s][ij], acc2);
                w[kk] = acc2;
            }
            for (int t = 0; t < NRAD; t++) {
                float v = w[0]*m1v[t][0] + w[1]*m1v[t][1] + w[2]*m1v[t][2];
                EMIT(v);
            }
        }
#undef EMIT
}

// ============================================================================
// bf16x3 tensor-core GEMMs (mma.sync) on pre-converted hi/lo operands,
// cp.async-pipelined. CTA tile 128x128, 8 warps (4m x 2n), BK=16.
// acc += Ah*Bh + Ah*Bl + Al*Bh (fp32 accumulators).
// ============================================================================
#define AS_STR  24    // gemm2 A smem: [m][k] rows of 16 + pad
#define KM_STR  136   // gemm1 A smem: [k][m] rows of 128 + pad; also B smem [k][n]

__device__ __forceinline__ unsigned smem_u32(const void* p) {
    return (unsigned)__cvta_generic_to_shared(p);
}
__device__ __forceinline__ void cpa16(void* s, const void* g) {
    asm volatile("cp.async.cg.shared.global [%0], [%1], 16;"
                 :: "r"(smem_u32(s)), "l"(g) : "memory");
}
__device__ __forceinline__ void cp_commit() {
    asm volatile("cp.async.commit_group;" ::: "memory");
}
__device__ __forceinline__ void cp_wait0() {
    asm volatile("cp.async.wait_group 0;" ::: "memory");
}
__device__ __forceinline__ void ldsm4(unsigned* r, unsigned addr) {
    asm volatile("ldmatrix.sync.aligned.m8n8.x4.shared.b16 {%0,%1,%2,%3}, [%4];"
        : "=r"(r[0]), "=r"(r[1]), "=r"(r[2]), "=r"(r[3]) : "r"(addr));
}
__device__ __forceinline__ void ldsm4t(unsigned* r, unsigned addr) {
    asm volatile("ldmatrix.sync.aligned.m8n8.x4.trans.shared.b16 {%0,%1,%2,%3}, [%4];"
        : "=r"(r[0]), "=r"(r[1]), "=r"(r[2]), "=r"(r[3]) : "r"(addr));
}
__device__ __forceinline__ void mma_bf16(float* d, const unsigned* a, unsigned b0, unsigned b1) {
    asm volatile("mma.sync.aligned.m16n8k16.row.col.f32.bf16.bf16.f32 "
        "{%0,%1,%2,%3}, {%4,%5,%6,%7}, {%8,%9}, {%0,%1,%2,%3};"
        : "+f"(d[0]), "+f"(d[1]), "+f"(d[2]), "+f"(d[3])
        : "r"(a[0]), "r"(a[1]), "r"(a[2]), "r"(a[3]), "r"(b0), "r"(b1));
}

// LAYER: 1 = GM([K][M] bf16) -> H1 bf16 hi/lo, swish
//        2 = H1([M][K] bf16) -> H2 fp32, swish
template<int LAYER>
__global__ __launch_bounds__(256, 2) void mma_gemm_kernel(
    const __nv_bfloat16* __restrict__ Ah, const __nv_bfloat16* __restrict__ Al,
    const __nv_bfloat16* __restrict__ Bh, const __nv_bfloat16* __restrict__ Bl,
    const float* __restrict__ bias,
    int M, int N, int K, int Astride)
{
    __shared__ __align__(16) __nv_bfloat16 Ash[2][2][(16 * KM_STR > 128 * AS_STR) ? 16 * KM_STR : 128 * AS_STR];
    __shared__ __align__(16) __nv_bfloat16 Bsh[2][2][16 * KM_STR];

    int tid = threadIdx.x;
    int lane = tid & 31;
    int wid = tid >> 5;
    int wm = wid & 3;
    int wn = wid >> 2;
    int m0 = blockIdx.y * 128;
    int n0 = blockIdx.x * 128;

    int lk = tid >> 4;             // 0..15 (k row) [LAYER1 A, and B]
    int lm8 = (tid & 15) * 8;      // m/n offset
    int lmB = tid >> 1;            // LAYER2 A: m row 0..127
    int lkg = (tid & 1) * 8;       // LAYER2 A: k offset

    float acc[2][8][4];
#pragma unroll
    for (int f = 0; f < 2; f++)
#pragma unroll
        for (int n8 = 0; n8 < 8; n8++)
#pragma unroll
            for (int q = 0; q < 4; q++) acc[f][n8][q] = 0.0f;

    int nT = K / 16;

    // A reads: LAYER2 rows beyond M-1 are valid buffer rows only when m0+lmB < M;
    // guard by clamping the row (values unused because epilogue guards stores).
    auto issue_tile = [&](int kt, int buf) {
        if (LAYER == 1) {
            size_t off = (size_t)(kt + lk) * Astride + m0 + lm8;
            cpa16(&Ash[buf][0][lk * KM_STR + lm8], &Ah[off]);
            cpa16(&Ash[buf][1][lk * KM_STR + lm8], &Al[off]);
        } else {
            int gm = m0 + lmB;
            if (gm >= M) gm = M - 1;
            size_t off = (size_t)gm * K + kt + lkg;
            cpa16(&Ash[buf][0][lmB * AS_STR + lkg], &Ah[off]);
            cpa16(&Ash[buf][1][lmB * AS_STR + lkg], &Al[off]);
        }
        size_t woff = (size_t)(kt + lk) * N + n0 + lm8;
        cpa16(&Bsh[buf][0][lk * KM_STR + lm8], &Bh[woff]);
        cpa16(&Bsh[buf][1][lk * KM_STR + lm8], &Bl[woff]);
    };

    // fragment smem byte offsets
    unsigned aoff;
    if (LAYER == 1) {
        int krow = (lane & 7) + ((lane >> 4) << 3);
        int mcol = wm * 32 + (((lane >> 3) & 1) << 3);
        aoff = (krow * KM_STR + mcol) * 2;
    } else {
        aoff = ((wm * 32 + (lane & 15)) * AS_STR + (lane >> 4) * 8) * 2;
    }
    unsigned boff = ((lane & 15) * KM_STR + wn * 64 + (lane >> 4) * 8) * 2;

    issue_tile(0, 0);
    cp_commit();
    cp_wait0();
    __syncthreads();

    for (int t = 0; t < nT; t++) {
        int cur = t & 1;
        bool has = (t + 1 < nT);
        if (has) { issue_tile((t + 1) * 16, cur ^ 1); cp_commit(); }

        unsigned aBaseH = smem_u32(&Ash[cur][0][0]) + aoff;
        unsigned aBaseL = smem_u32(&Ash[cur][1][0]) + aoff;
        unsigned bBaseH = smem_u32(&Bsh[cur][0][0]) + boff;
        unsigned bBaseL = smem_u32(&Bsh[cur][1][0]) + boff;

        unsigned ah[2][4], al[2][4], bh[4][4], bl[4][4];
#pragma unroll
        for (int f = 0; f < 2; f++) {
            if (LAYER == 1) {
                ldsm4t(ah[f], aBaseH + f * 16 * 2);
                ldsm4t(al[f], aBaseL + f * 16 * 2);
            } else {
                ldsm4(ah[f], aBaseH + f * 16 * AS_STR * 2);
                ldsm4(al[f], aBaseL + f * 16 * AS_STR * 2);
            }
        }
#pragma unroll
        for (int nb = 0; nb < 4; nb++) {
            ldsm4t(bh[nb], bBaseH + nb * 32);
            ldsm4t(bl[nb], bBaseL + nb * 32);
        }

#pragma unroll
        for (int f = 0; f < 2; f++)
#pragma unroll
            for (int nb = 0; nb < 4; nb++)
#pragma unroll
                for (int j = 0; j < 2; j++) {
                    float* d = acc[f][nb * 2 + j];
                    unsigned bh0 = bh[nb][2 * j], bh1 = bh[nb][2 * j + 1];
                    unsigned bl0 = bl[nb][2 * j], bl1 = bl[nb][2 * j + 1];
                    mma_bf16(d, ah[f], bh0, bh1);
                    mma_bf16(d, ah[f], bl0, bl1);
                    mma_bf16(d, al[f], bh0, bh1);
                }

        if (has) cp_wait0();
        __syncthreads();
    }

    // ---- epilogue: bias + swish; LAYER1 -> H1 bf16 hi/lo, LAYER2 -> H2 fp32 ----
#pragma unroll
    for (int f = 0; f < 2; f++) {
#pragma unroll
        for (int n8 = 0; n8 < 8; n8++) {
            int rm = m0 + wm * 32 + f * 16 + (lane >> 2);
            int cn = n0 + wn * 64 + n8 * 8 + (lane & 3) * 2;
            float b0 = bias[cn], b1 = bias[cn + 1];
#pragma unroll
            for (int half = 0; half < 2; half++) {
                int r = rm + half * 8;
                if (r >= M) continue;
                float v0 = acc[f][n8][half * 2 + 0] + b0;
                float v1 = acc[f][n8][half * 2 + 1] + b1;
                v0 = v0 / (1.0f + __expf(-v0));
                v1 = v1 / (1.0f + __expf(-v1));
                if (LAYER == 1) {
                    __nv_bfloat16 h0, l0, h1, l1;
                    bsplit(v0, h0, l0); bsplit(v1, h1, l1);
                    *(__nv_bfloat162*)&g_H1h[(size_t)r * NU1 + cn] = __nv_bfloat162(h0, h1);
                    *(__nv_bfloat162*)&g_H1l[(size_t)r * NU1 + cn] = __nv_bfloat162(l0, l1);
                } else {
                    *(float2*)&g_H2[(size_t)r * NU2 + cn] = make_float2(v0, v1);
                }
            }
        }
    }
}

// ---------------- final layer: per-row dot + scale/shift ----------------
__global__ __launch_bounds__(256) void out_kernel(
    const float* __restrict__ w3, const float* __restrict__ b3,
    const float* __restrict__ scale, const float* __restrict__ shift,
    const int* __restrict__ Z, float* __restrict__ out)
{
    int gw = (blockIdx.x * blockDim.x + threadIdx.x) >> 5;
    int lane = threadIdx.x & 31;
    if (gw >= NATOMS) return;
    const float* h = g_H2 + (size_t)gw * NU2;
    float s = 0.0f;
#pragma unroll
    for (int t = 0; t < NU2 / 32; t++) {
        int i = lane + t * 32;
        s = fmaf(h[i], w3[i], s);
    }
#pragma unroll
    for (int o = 16; o; o >>= 1) s += __shfl_xor_sync(0xffffffffu, s, o);
    if (lane == 0) {
        float v = s + b3[0];
        int z = Z[gw];
        out[gw] = scale[z] * v + shift[z];
    }
}

// ---------------- launch ----------------
extern "C" void kernel_launch(void* const* d_in, const int* in_sizes, int n_in,
                              void* d_out, int out_size)
{
    const float* R     = (const float*)d_in[0];
    const int*   Z     = (const int*)  d_in[1];
    const int*   idx   = (const int*)  d_in[2];
    const float* Wr    = (const float*)d_in[3];
    const float* w1    = (const float*)d_in[4];
    const float* b1    = (const float*)d_in[5];
    const float* w2    = (const float*)d_in[6];
    const float* b2    = (const float*)d_in[7];
    const float* w3    = (const float*)d_in[8];
    const float* b3    = (const float*)d_in[9];
    const float* scale = (const float*)d_in[10];
    const float* shift = (const float*)d_in[11];
    float* out = (float*)d_out;

    __nv_bfloat16 *pGMh, *pGMl, *pW1h, *pW1l, *pW2h, *pW2l, *pH1h, *pH1l;
    cudaGetSymbolAddress((void**)&pGMh, g_GMh);
    cudaGetSymbolAddress((void**)&pGMl, g_GMl);
    cudaGetSymbolAddress((void**)&pW1h, g_w1h);
    cudaGetSymbolAddress((void**)&pW1l, g_w1l);
    cudaGetSymbolAddress((void**)&pW2h, g_w2h);
    cudaGetSymbolAddress((void**)&pW2l, g_w2l);
    cudaGetSymbolAddress((void**)&pH1h, g_H1h);
    cudaGetSymbolAddress((void**)&pH1l, g_H1l);

    prep_kernel<<<(NATOMS + 255) / 256, 256>>>(R);
    convw_kernel<<<(NU1 * NU2 + 255) / 256, 256>>>(w1, w2);
    hist_kernel<<<(NPAIRS + 255) / 256, 256>>>(idx);
    scan1_kernel<<<NSCB, 1024>>>();
    scan2_kernel<<<1, 32>>>();
    scan3_kernel<<<NSCB, 1024>>>();
    scatter_kernel<<<(NPAIRS + 255) / 256, 256>>>(Z, idx, Wr);
    accum_kernel<<<(NATOMS + 127) / 128, 128>>>();
    feat_kernel<<<(NATOMS + 127) / 128, 128>>>();

    dim3 g1(NU1 / 128, (NATOMS + 127) / 128);
    mma_gemm_kernel<1><<<g1, 256>>>(pGMh, pGMl, pW1h, pW1l, b1, NATOMS, NU1, NFEATP, AP);

    dim3 g2(NU2 / 128, (NATOMS + 127) / 128);
    mma_gemm_kernel<2><<<g2, 256>>>(pH1h, pH1l, pW2h, pW2l, b2, NATOMS, NU2, NU1, 0);

    out_kernel<<<(NATOMS * 32 + 255) / 256, 256>>>(w3, b3, scale, shift, Z, out);
}

// round 11
// speedup vs baseline: 3.1693x; 1.0427x over previous
#include <cuda_runtime.h>
#include <cuda_bf16.h>
#include <math.h>
#include <stdint.h>
#include <cstdint>

#define NATOMS 30000
#define NPAIRS 1200000
#define NBASIS 7
#define NRAD   5
#define NSPEC  119
#define NFEAT  360
#define NFEATP 368          // layer-1 K padded to multiple of 16
#define AP     30080        // atoms padded (unused rows zero)
#define NMOM   100
#define NU1    512
#define NU2    512
#define NSCB   30           // scan blocks

// ---------------- static scratch (no allocations; BSS zero-initialized) ----------------
__device__ int    g_cnt[NATOMS];
__device__ int    g_off[NATOMS];
__device__ int    g_cur[NATOMS];
__device__ int    g_bsum[32];
__device__ float4 g_R4[NATOMS];
__device__ float  g_Wp[(size_t)NSPEC * NSPEC * NRAD * 8];   // padded radial weights [pair][k][8]
__device__ float  g_pd[(size_t)NPAIRS * 8];
__device__ float  g_Mom[NMOM * NATOMS];
// feature-major GM [NFEATP][AP] bf16 hi/lo (pads stay zero)
__device__ __nv_bfloat16 g_GMh[(size_t)NFEATP * AP];
__device__ __nv_bfloat16 g_GMl[(size_t)NFEATP * AP];
__device__ __nv_bfloat16 g_w1h[NFEATP * NU1];
__device__ __nv_bfloat16 g_w1l[NFEATP * NU1];
__device__ __nv_bfloat16 g_w2h[NU1 * NU2];
__device__ __nv_bfloat16 g_w2l[NU1 * NU2];
__device__ __nv_bfloat16 g_H1h[(size_t)NATOMS * NU1];
__device__ __nv_bfloat16 g_H1l[(size_t)NATOMS * NU1];
__device__ float  g_H2 [(size_t)NATOMS * NU2];

__device__ __forceinline__ void bsplit(float v, __nv_bfloat16& h, __nv_bfloat16& l) {
    h = __float2bfloat16(v);
    l = __float2bfloat16(v - __bfloat162float(h));
}

// ---------------- prep ----------------
__global__ void prep_kernel(const float* __restrict__ R) {
    int i = blockIdx.x * blockDim.x + threadIdx.x;
    if (i < NATOMS) {
        g_cnt[i] = 0;
        g_R4[i] = make_float4(R[3*i+0], R[3*i+1], R[3*i+2], 0.0f);
    }
}

// ---------------- repack Wr [pair][5][7] -> float4-aligned [pair][5][8] ----------------
__global__ __launch_bounds__(256) void packw_kernel(const float* __restrict__ Wr) {
    int i = blockIdx.x * blockDim.x + threadIdx.x;
    int total = NSPEC * NSPEC * NRAD * NBASIS;
    if (i >= total) return;
    int b = i % NBASIS;
    int rest = i / NBASIS;
    int k = rest % NRAD;
    int pair = rest / NRAD;
    g_Wp[((size_t)pair * NRAD + k) * 8 + b] = Wr[i];
}

// ---------------- weights -> bf16 hi/lo (w1 K-padded) ----------------
__global__ void convw_kernel(const float* __restrict__ w1, const float* __restrict__ w2) {
    int i = blockIdx.x * blockDim.x + threadIdx.x;
    if (i < NFEATP * NU1) {
        int k = i / NU1, n = i % NU1;
        float v = (k < NFEAT) ? w1[(size_t)k * NU1 + n] : 0.0f;
        bsplit(v, g_w1h[i], g_w1l[i]);
    }
    if (i < NU1 * NU2) {
        bsplit(w2[i], g_w2h[i], g_w2l[i]);
    }
}

// ---------------- histogram ----------------
__global__ __launch_bounds__(256) void hist_kernel(const int* __restrict__ idx) {
    int p = blockIdx.x * blockDim.x + threadIdx.x;
    if (p < NPAIRS) atomicAdd(&g_cnt[idx[p]], 1);
}

// ---------------- 3-phase scan ----------------
__global__ __launch_bounds__(1024) void scan1_kernel() {
    __shared__ int wsum[32];
    int tid = threadIdx.x, lane = tid & 31, w = tid >> 5;
    int i = blockIdx.x * 1024 + tid;
    int v = (i < NATOMS) ? g_cnt[i] : 0;
    int x = v;
#pragma unroll
    for (int o = 1; o < 32; o <<= 1) {
        int y = __shfl_up_sync(0xffffffffu, x, o);
        if (lane >= o) x += y;
    }
    if (lane == 31) wsum[w] = x;
    __syncthreads();
    if (w == 0) {
        int t = wsum[lane];
        int xs = t;
#pragma unroll
        for (int o = 1; o < 32; o <<= 1) {
            int y = __shfl_up_sync(0xffffffffu, xs, o);
            if (lane >= o) xs += y;
        }
        wsum[lane] = xs - t;
    }
    __syncthreads();
    if (i < NATOMS) g_off[i] = wsum[w] + x - v;
    if (tid == 1023) g_bsum[blockIdx.x] = wsum[31] + x;
}
__global__ void scan2_kernel() {
    int lane = threadIdx.x;
    int v = (lane < NSCB) ? g_bsum[lane] : 0;
    int x = v;
#pragma unroll
    for (int o = 1; o < 32; o <<= 1) {
        int y = __shfl_up_sync(0xffffffffu, x, o);
        if (lane >= o) x += y;
    }
    if (lane < NSCB) g_bsum[lane] = x - v;
}
__global__ __launch_bounds__(1024) void scan3_kernel() {
    int i = blockIdx.x * 1024 + threadIdx.x;
    if (i < NATOMS) {
        int o = g_off[i] + g_bsum[blockIdx.x];
        g_off[i] = o;
        g_cur[i] = o;
    }
}

// ---------------- per-pair math + scatter (vectorized weight loads) ----------------
__global__ __launch_bounds__(256) void scatter_kernel(
    const int* __restrict__ Z, const int* __restrict__ idx)
{
    int p = blockIdx.x * blockDim.x + threadIdx.x;
    if (p >= NPAIRS) return;
    int i = idx[p];
    int j = idx[NPAIRS + p];

    float4 Ri = g_R4[i];
    float4 Rj = g_R4[j];
    float dx = Rj.x - Ri.x;
    float dy = Rj.y - Ri.y;
    float dz = Rj.z - Ri.z;
    float dr = sqrtf(dx*dx + dy*dy + dz*dz + 1e-12f);

    const float PI = 3.14159265358979323846f;
    float cut = (dr < 6.0f)
              ? 0.5f * (__cosf((PI / 6.0f) * dr) + 1.0f) * 0.37796447300922720f
              : 0.0f;

    float inv = 1.0f / (dr + 1e-5f);
    float ux = dx * inv, uy = dy * inv, uz = dz * inv;

    const float betta = 49.0f / 36.0f;
    const float rn = 0.9601717136386805f;
    float basis[NBASIS];
#pragma unroll
    for (int b = 0; b < NBASIS; b++) {
        float d = dr - (0.5f + 0.7857142857142857f * (float)b);
        basis[b] = rn * __expf(-betta * d * d);
    }

    int zi = Z[i], zj = Z[j];
    const float4* cf4 = (const float4*)(g_Wp + (size_t)(zi * NSPEC + zj) * NRAD * 8);
    float radial[NRAD];
#pragma unroll
    for (int k = 0; k < NRAD; k++) {
        float4 c0 = cf4[k * 2];
        float4 c1 = cf4[k * 2 + 1];
        float s = c0.x * basis[0];
        s = fmaf(c0.y, basis[1], s);
        s = fmaf(c0.z, basis[2], s);
        s = fmaf(c0.w, basis[3], s);
        s = fmaf(c1.x, basis[4], s);
        s = fmaf(c1.y, basis[5], s);
        s = fmaf(c1.z, basis[6], s);
        radial[k] = s * cut;
    }

    int pos = atomicAdd(&g_cur[i], 1);
    float4 lo = make_float4(radial[0], radial[1], radial[2], radial[3]);
    float4 hi = make_float4(radial[4], ux, uy, uz);
    *(float4*)&g_pd[(size_t)pos * 8 + 0] = lo;
    *(float4*)&g_pd[(size_t)pos * 8 + 4] = hi;
}

// ---------------- per-atom moment accumulation: all 5 radial channels in-register ----------------
__global__ __launch_bounds__(128) void accum_kernel()
{
    int a = blockIdx.x * blockDim.x + threadIdx.x;
    if (a >= NATOMS) return;

    int beg = g_off[a];
    int end = beg + g_cnt[a];

    float acc[NRAD][20];
#pragma unroll
    for (int k = 0; k < NRAD; k++)
#pragma unroll
        for (int m = 0; m < 20; m++) acc[k][m] = 0.0f;

    for (int p = beg; p < end; p++) {
        float4 lo = *(const float4*)&g_pd[(size_t)p * 8 + 0];
        float4 hi = *(const float4*)&g_pd[(size_t)p * 8 + 4];
        float rad[NRAD] = {lo.x, lo.y, lo.z, lo.w, hi.x};
        float ux = hi.y, uy = hi.z, uz = hi.w;
        float g[20];
        g[0] = 1.0f;
        g[1] = ux; g[2] = uy; g[3] = uz;
        float xx = ux*ux, yy = uy*uy, zz = uz*uz;
        float xy = ux*uy, xz = ux*uz, yz = uy*uz;
        g[4] = xx; g[5] = yy; g[6] = zz; g[7] = xy; g[8] = xz; g[9] = yz;
        g[10] = xx*ux; g[11] = xx*uy; g[12] = xx*uz;
        g[13] = yy*ux; g[14] = xy*uz; g[15] = zz*ux;
        g[16] = yy*uy; g[17] = yy*uz; g[18] = zz*uy; g[19] = zz*uz;
#pragma unroll
        for (int k = 0; k < NRAD; k++)
#pragma unroll
            for (int m = 0; m < 20; m++)
                acc[k][m] = fmaf(rad[k], g[m], acc[k][m]);
    }

#pragma unroll
    for (int k = 0; k < NRAD; k++)
#pragma unroll
        for (int m = 0; m < 20; m++)
            g_Mom[(size_t)(k * 20 + m) * NATOMS + a] = acc[k][m];
}

// ---------------- per-atom invariant contractions -> 360 bf16 hi/lo features ----------------
__global__ __launch_bounds__(128) void feat_kernel()
{
    int a = blockIdx.x * blockDim.x + threadIdx.x;
    if (a >= NATOMS) return;

    const int T2[9]  = {0,3,4, 3,1,5, 4,5,2};
    const int T3[27] = {0,1,2, 1,3,4, 2,4,5,
                        1,3,4, 3,6,7, 4,7,8,
                        2,4,5, 4,7,8, 5,8,9};

    float m0v[NRAD];
    float m1v[NRAD][3];
    float m2v[NRAD][9];
    float m3v[NRAD][27];

    for (int k = 0; k < NRAD; k++) {
        const float* base = g_Mom + (size_t)(k*20) * NATOMS;
        m0v[k] = base[a];
        for (int d = 0; d < 3; d++) m1v[k][d] = base[(1+d)*NATOMS + a];
        float s2[6];
        for (int u = 0; u < 6; u++) s2[u] = base[(4+u)*NATOMS + a];
        for (int e = 0; e < 9; e++) m2v[k][e] = s2[T2[e]];
        float s3[10];
        for (int u = 0; u < 10; u++) s3[u] = base[(10+u)*NATOMS + a];
        for (int e = 0; e < 27; e++) m3v[k][e] = s3[T3[e]];
    }

    int f = 0;
#define EMIT(v) do { __nv_bfloat16 _h, _l; bsplit((v), _h, _l); \
    g_GMh[(size_t)(f) * AP + a] = _h; g_GMl[(size_t)(f) * AP + a] = _l; f++; } while (0)

    for (int k = 0; k < NRAD; k++) EMIT(m0v[k]);

    for (int r = 0; r < NRAD; r++)
        for (int s = r; s < NRAD; s++) {
            float v = m1v[r][0]*m1v[s][0] + m1v[r][1]*m1v[s][1] + m1v[r][2]*m1v[s][2];
            EMIT(v);
        }

    for (int r = 0; r < NRAD; r++)
        for (int s = r; s < NRAD; s++) {
            float v = 0.0f;
            for (int e = 0; e < 9; e++) v = fmaf(m2v[r][e], m2v[s][e], v);
            EMIT(v);
        }

    for (int r = 0; r < NRAD; r++)
        for (int s = r; s < NRAD; s++) {
            float v = 0.0f;
            for (int e = 0; e < 27; e++) v = fmaf(m3v[r][e], m3v[s][e], v);
            EMIT(v);
        }

    for (int r = 0; r < NRAD; r++)
        for (int s = r; s < NRAD; s++)
            for (int t = s; t < NRAD; t++) {
                float v = 0.0f;
                for (int jj = 0; jj < 3; jj++)
                    for (int kk = 0; kk < 3; kk++) {
                        float pjk = 0.0f;
                        for (int ii = 0; ii < 3; ii++)
                            pjk = fmaf(m2v[r][ii*3 + jj], m2v[s][ii*3 + kk], pjk);
                        v = fmaf(pjk, m2v[t][jj*3 + kk], v);
                    }
                EMIT(v);
            }

    for (int r = 0; r < NRAD; r++)
        for (int s = r; s < NRAD; s++) {
            float O[9];
            for (int ii = 0; ii < 3; ii++)
                for (int jj = 0; jj < 3; jj++)
                    O[ii*3 + jj] = m1v[r][ii] * m1v[s][jj];
            for (int t = 0; t < NRAD; t++) {
                float v = 0.0f;
                for (int e = 0; e < 9; e++) v = fmaf(O[e], m2v[t][e], v);
                EMIT(v);
            }
        }

    for (int r = 0; r < NRAD; r++)
        for (int s = r; s < NRAD; s++) {
            float T[9];
            for (int kk = 0; kk < 3; kk++)
                for (int ll = 0; ll < 3; ll++) {
                    float acc2 = 0.0f;
                    for (int ij = 0; ij < 9; ij++)
                        acc2 = fmaf(m3v[r][ij*3 + kk], m3v[s][ij*3 + ll], acc2);
                    T[kk*3 + ll] = acc2;
                }
            for (int t = 0; t < NRAD; t++) {
                float v = 0.0f;
                for (int e = 0; e < 9; e++) v = fmaf(T[e], m2v[t][e], v);
                EMIT(v);
            }
        }

    for (int r = 0; r < NRAD; r++)
        for (int s = 0; s < NRAD; s++) {
            float w[3];
            for (int kk = 0; kk < 3; kk++) {
                float acc2 = 0.0f;
                for (int ij = 0; ij < 9; ij++)
                    acc2 = fmaf(m3v[r][ij*3 + kk], m2v[s][ij], acc2);
                w[kk] = acc2;
            }
            for (int t = 0; t < NRAD; t++) {
                float v = w[0]*m1v[t][0] + w[1]*m1v[t][1] + w[2]*m1v[t][2];
                EMIT(v);
            }
        }
#undef EMIT
}

// ============================================================================
// bf16x3 tensor-core GEMMs (mma.sync) on pre-converted hi/lo operands,
// cp.async-pipelined. CTA tile 128x128, 8 warps (4m x 2n), BK=16.
// acc += Ah*Bh + Ah*Bl + Al*Bh (fp32 accumulators).
// ============================================================================
#define AS_STR  24    // gemm2 A smem: [m][k] rows of 16 + pad
#define KM_STR  136   // gemm1 A smem: [k][m] rows of 128 + pad; also B smem [k][n]

__device__ __forceinline__ unsigned smem_u32(const void* p) {
    return (unsigned)__cvta_generic_to_shared(p);
}
__device__ __forceinline__ void cpa16(void* s, const void* g) {
    asm volatile("cp.async.cg.shared.global [%0], [%1], 16;"
                 :: "r"(smem_u32(s)), "l"(g) : "memory");
}
__device__ __forceinline__ void cp_commit() {
    asm volatile("cp.async.commit_group;" ::: "memory");
}
__device__ __forceinline__ void cp_wait0() {
    asm volatile("cp.async.wait_group 0;" ::: "memory");
}
__device__ __forceinline__ void ldsm4(unsigned* r, unsigned addr) {
    asm volatile("ldmatrix.sync.aligned.m8n8.x4.shared.b16 {%0,%1,%2,%3}, [%4];"
        : "=r"(r[0]), "=r"(r[1]), "=r"(r[2]), "=r"(r[3]) : "r"(addr));
}
__device__ __forceinline__ void ldsm4t(unsigned* r, unsigned addr) {
    asm volatile("ldmatrix.sync.aligned.m8n8.x4.trans.shared.b16 {%0,%1,%2,%3}, [%4];"
        : "=r"(r[0]), "=r"(r[1]), "=r"(r[2]), "=r"(r[3]) : "r"(addr));
}
__device__ __forceinline__ void mma_bf16(float* d, const unsigned* a, unsigned b0, unsigned b1) {
    asm volatile("mma.sync.aligned.m16n8k16.row.col.f32.bf16.bf16.f32 "
        "{%0,%1,%2,%3}, {%4,%5,%6,%7}, {%8,%9}, {%0,%1,%2,%3};"
        : "+f"(d[0]), "+f"(d[1]), "+f"(d[2]), "+f"(d[3])
        : "r"(a[0]), "r"(a[1]), "r"(a[2]), "r"(a[3]), "r"(b0), "r"(b1));
}

// LAYER: 1 = GM([K][M] bf16) -> H1 bf16 hi/lo, swish
//        2 = H1([M][K] bf16) -> H2 fp32, swish
template<int LAYER>
__global__ __launch_bounds__(256, 2) void mma_gemm_kernel(
    const __nv_bfloat16* __restrict__ Ah, const __nv_bfloat16* __restrict__ Al,
    const __nv_bfloat16* __restrict__ Bh, const __nv_bfloat16* __restrict__ Bl,
    const float* __restrict__ bias,
    int M, int N, int K, int Astride)
{
    __shared__ __align__(16) __nv_bfloat16 Ash[2][2][(16 * KM_STR > 128 * AS_STR) ? 16 * KM_STR : 128 * AS_STR];
    __shared__ __align__(16) __nv_bfloat16 Bsh[2][2][16 * KM_STR];

    int tid = threadIdx.x;
    int lane = tid & 31;
    int wid = tid >> 5;
    int wm = wid & 3;
    int wn = wid >> 2;
    int m0 = blockIdx.y * 128;
    int n0 = blockIdx.x * 128;

    int lk = tid >> 4;             // 0..15 (k row) [LAYER1 A, and B]
    int lm8 = (tid & 15) * 8;      // m/n offset
    int lmB = tid >> 1;            // LAYER2 A: m row 0..127
    int lkg = (tid & 1) * 8;       // LAYER2 A: k offset

    float acc[2][8][4];
#pragma unroll
    for (int f = 0; f < 2; f++)
#pragma unroll
        for (int n8 = 0; n8 < 8; n8++)
#pragma unroll
            for (int q = 0; q < 4; q++) acc[f][n8][q] = 0.0f;

    int nT = K / 16;

    auto issue_tile = [&](int kt, int buf) {
        if (LAYER == 1) {
            size_t off = (size_t)(kt + lk) * Astride + m0 + lm8;
            cpa16(&Ash[buf][0][lk * KM_STR + lm8], &Ah[off]);
            cpa16(&Ash[buf][1][lk * KM_STR + lm8], &Al[off]);
        } else {
            int gm = m0 + lmB;
            if (gm >= M) gm = M - 1;
            size_t off = (size_t)gm * K + kt + lkg;
            cpa16(&Ash[buf][0][lmB * AS_STR + lkg], &Ah[off]);
            cpa16(&Ash[buf][1][lmB * AS_STR + lkg], &Al[off]);
        }
        size_t woff = (size_t)(kt + lk) * N + n0 + lm8;
        cpa16(&Bsh[buf][0][lk * KM_STR + lm8], &Bh[woff]);
        cpa16(&Bsh[buf][1][lk * KM_STR + lm8], &Bl[woff]);
    };

    unsigned aoff;
    if (LAYER == 1) {
        int krow = (lane & 7) + ((lane >> 4) << 3);
        int mcol = wm * 32 + (((lane >> 3) & 1) << 3);
        aoff = (krow * KM_STR + mcol) * 2;
    } else {
        aoff = ((wm * 32 + (lane & 15)) * AS_STR + (lane >> 4) * 8) * 2;
    }
    unsigned boff = ((lane & 15) * KM_STR + wn * 64 + (lane >> 4) * 8) * 2;

    issue_tile(0, 0);
    cp_commit();
    cp_wait0();
    __syncthreads();

    for (int t = 0; t < nT; t++) {
        int cur = t & 1;
        bool has = (t + 1 < nT);
        if (has) { issue_tile((t + 1) * 16, cur ^ 1); cp_commit(); }

        unsigned aBaseH = smem_u32(&Ash[cur][0][0]) + aoff;
        unsigned aBaseL = smem_u32(&Ash[cur][1][0]) + aoff;
        unsigned bBaseH = smem_u32(&Bsh[cur][0][0]) + boff;
        unsigned bBaseL = smem_u32(&Bsh[cur][1][0]) + boff;

        unsigned ah[2][4], al[2][4], bh[4][4], bl[4][4];
#pragma unroll
        for (int f = 0; f < 2; f++) {
            if (LAYER == 1) {
                ldsm4t(ah[f], aBaseH + f * 16 * 2);
                ldsm4t(al[f], aBaseL + f * 16 * 2);
            } else {
                ldsm4(ah[f], aBaseH + f * 16 * AS_STR * 2);
                ldsm4(al[f], aBaseL + f * 16 * AS_STR * 2);
            }
        }
#pragma unroll
        for (int nb = 0; nb < 4; nb++) {
            ldsm4t(bh[nb], bBaseH + nb * 32);
            ldsm4t(bl[nb], bBaseL + nb * 32);
        }

#pragma unroll
        for (int f = 0; f < 2; f++)
#pragma unroll
            for (int nb = 0; nb < 4; nb++)
#pragma unroll
                for (int j = 0; j < 2; j++) {
                    float* d = acc[f][nb * 2 + j];
                    unsigned bh0 = bh[nb][2 * j], bh1 = bh[nb][2 * j + 1];
                    unsigned bl0 = bl[nb][2 * j], bl1 = bl[nb][2 * j + 1];
                    mma_bf16(d, ah[f], bh0, bh1);
                    mma_bf16(d, ah[f], bl0, bl1);
                    mma_bf16(d, al[f], bh0, bh1);
                }

        if (has) cp_wait0();
        __syncthreads();
    }

    // ---- epilogue: bias + swish; LAYER1 -> H1 bf16 hi/lo, LAYER2 -> H2 fp32 ----
#pragma unroll
    for (int f = 0; f < 2; f++) {
#pragma unroll
        for (int n8 = 0; n8 < 8; n8++) {
            int rm = m0 + wm * 32 + f * 16 + (lane >> 2);
            int cn = n0 + wn * 64 + n8 * 8 + (lane & 3) * 2;
            float b0 = bias[cn], b1 = bias[cn + 1];
#pragma unroll
            for (int half = 0; half < 2; half++) {
                int r = rm + half * 8;
                if (r >= M) continue;
                float v0 = acc[f][n8][half * 2 + 0] + b0;
                float v1 = acc[f][n8][half * 2 + 1] + b1;
                v0 = v0 / (1.0f + __expf(-v0));
                v1 = v1 / (1.0f + __expf(-v1));
                if (LAYER == 1) {
                    __nv_bfloat16 h0, l0, h1, l1;
                    bsplit(v0, h0, l0); bsplit(v1, h1, l1);
                    *(__nv_bfloat162*)&g_H1h[(size_t)r * NU1 + cn] = __nv_bfloat162(h0, h1);
                    *(__nv_bfloat162*)&g_H1l[(size_t)r * NU1 + cn] = __nv_bfloat162(l0, l1);
                } else {
                    *(float2*)&g_H2[(size_t)r * NU2 + cn] = make_float2(v0, v1);
                }
            }
        }
    }
}

// ---------------- final layer: per-row dot + scale/shift ----------------
__global__ __launch_bounds__(256) void out_kernel(
    const float* __restrict__ w3, const float* __restrict__ b3,
    const float* __restrict__ scale, const float* __restrict__ shift,
    const int* __restrict__ Z, float* __restrict__ out)
{
    int gw = (blockIdx.x * blockDim.x + threadIdx.x) >> 5;
    int lane = threadIdx.x & 31;
    if (gw >= NATOMS) return;
    const float* h = g_H2 + (size_t)gw * NU2;
    float s = 0.0f;
#pragma unroll
    for (int t = 0; t < NU2 / 32; t++) {
        int i = lane + t * 32;
        s = fmaf(h[i], w3[i], s);
    }
#pragma unroll
    for (int o = 16; o; o >>= 1) s += __shfl_xor_sync(0xffffffffu, s, o);
    if (lane == 0) {
        float v = s + b3[0];
        int z = Z[gw];
        out[gw] = scale[z] * v + shift[z];
    }
}

// ---------------- launch ----------------
extern "C" void kernel_launch(void* const* d_in, const int* in_sizes, int n_in,
                              void* d_out, int out_size)
{
    const float* R     = (const float*)d_in[0];
    const int*   Z     = (const int*)  d_in[1];
    const int*   idx   = (const int*)  d_in[2];
    const float* Wr    = (const float*)d_in[3];
    const float* w1    = (const float*)d_in[4];
    const float* b1    = (const float*)d_in[5];
    const float* w2    = (const float*)d_in[6];
    const float* b2    = (const float*)d_in[7];
    const float* w3    = (const float*)d_in[8];
    const float* b3    = (const float*)d_in[9];
    const float* scale = (const float*)d_in[10];
    const float* shift = (const float*)d_in[11];
    float* out = (float*)d_out;

    __nv_bfloat16 *pGMh, *pGMl, *pW1h, *pW1l, *pW2h, *pW2l, *pH1h, *pH1l;
    cudaGetSymbolAddress((void**)&pGMh, g_GMh);
    cudaGetSymbolAddress((void**)&pGMl, g_GMl);
    cudaGetSymbolAddress((void**)&pW1h, g_w1h);
    cudaGetSymbolAddress((void**)&pW1l, g_w1l);
    cudaGetSymbolAddress((void**)&pW2h, g_w2h);
    cudaGetSymbolAddress((void**)&pW2l, g_w2l);
    cudaGetSymbolAddress((void**)&pH1h, g_H1h);
    cudaGetSymbolAddress((void**)&pH1l, g_H1l);

    prep_kernel<<<(NATOMS + 255) / 256, 256>>>(R);
    packw_kernel<<<(NSPEC * NSPEC * NRAD * NBASIS + 255) / 256, 256>>>(Wr);
    convw_kernel<<<(NU1 * NU2 + 255) / 256, 256>>>(w1, w2);
    hist_kernel<<<(NPAIRS + 255) / 256, 256>>>(idx);
    scan1_kernel<<<NSCB, 1024>>>();
    scan2_kernel<<<1, 32>>>();
    scan3_kernel<<<NSCB, 1024>>>();
    scatter_kernel<<<(NPAIRS + 255) / 256, 256>>>(Z, idx);
    accum_kernel<<<(NATOMS + 127) / 128, 128>>>();
    feat_kernel<<<(NATOMS + 127) / 128, 128>>>();

    dim3 g1(NU1 / 128, (NATOMS + 127) / 128);
    mma_gemm_kernel<1><<<g1, 256>>>(pGMh, pGMl, pW1h, pW1l, b1, NATOMS, NU1, NFEATP, AP);

    dim3 g2(NU2 / 128, (NATOMS + 127) / 128);
    mma_gemm_kernel<2><<<g2, 256>>>(pH1h, pH1l, pW2h, pW2l, b2, NATOMS, NU2, NU1, 0);

    out_kernel<<<(NATOMS * 32 + 255) / 256, 256>>>(w3, b3, scale, shift, Z, out);
}

// round 12
// speedup vs baseline: 3.3329x; 1.0516x over previous
#include <cuda_runtime.h>
#include <cuda_bf16.h>
#include <math.h>
#include <stdint.h>
#include <cstdint>

#define NATOMS 30000
#define NPAIRS 1200000
#define NBASIS 7
#define NRAD   5
#define NSPEC  119
#define NFEAT  360
#define NFEATP 368          // layer-1 K padded to multiple of 16
#define AP     30080        // atoms padded (unused rows zero)
#define NU1    512
#define NU2    512
#define NSCB   30           // scan blocks

// ---------------- static scratch (no allocations; BSS zero-initialized) ----------------
__device__ int    g_cnt[NATOMS];
__device__ int    g_off[NATOMS];
__device__ int    g_cur[NATOMS];
__device__ int    g_bsum[32];
__device__ float4 g_R4[NATOMS];
__device__ float  g_Wp[(size_t)NSPEC * NSPEC * NRAD * 8];   // padded radial weights [pair][k][8]
__device__ float  g_pd[(size_t)NPAIRS * 8];
// feature-major GM [NFEATP][AP] bf16 hi/lo (pads stay zero)
__device__ __nv_bfloat16 g_GMh[(size_t)NFEATP * AP];
__device__ __nv_bfloat16 g_GMl[(size_t)NFEATP * AP];
__device__ __nv_bfloat16 g_w1h[NFEATP * NU1];
__device__ __nv_bfloat16 g_w1l[NFEATP * NU1];
__device__ __nv_bfloat16 g_w2h[NU1 * NU2];
__device__ __nv_bfloat16 g_w2l[NU1 * NU2];
__device__ __nv_bfloat16 g_H1h[(size_t)NATOMS * NU1];
__device__ __nv_bfloat16 g_H1l[(size_t)NATOMS * NU1];

__device__ __forceinline__ void bsplit(float v, __nv_bfloat16& h, __nv_bfloat16& l) {
    h = __float2bfloat16(v);
    l = __float2bfloat16(v - __bfloat162float(h));
}

// ---------------- prep: counters, padded R, init out = scale*b3 + shift ----------------
__global__ void prep_kernel(const float* __restrict__ R, const int* __restrict__ Z,
                            const float* __restrict__ scale, const float* __restrict__ shift,
                            const float* __restrict__ b3, float* __restrict__ out) {
    int i = blockIdx.x * blockDim.x + threadIdx.x;
    if (i < NATOMS) {
        g_cnt[i] = 0;
        g_R4[i] = make_float4(R[3*i+0], R[3*i+1], R[3*i+2], 0.0f);
        int z = Z[i];
        out[i] = scale[z] * b3[0] + shift[z];
    }
}

// ---------------- repack Wr [pair][5][7] -> float4-aligned [pair][5][8] ----------------
__global__ __launch_bounds__(256) void packw_kernel(const float* __restrict__ Wr) {
    int i = blockIdx.x * blockDim.x + threadIdx.x;
    int total = NSPEC * NSPEC * NRAD * NBASIS;
    if (i >= total) return;
    int b = i % NBASIS;
    int rest = i / NBASIS;
    int k = rest % NRAD;
    int pair = rest / NRAD;
    g_Wp[((size_t)pair * NRAD + k) * 8 + b] = Wr[i];
}

// ---------------- weights -> bf16 hi/lo (w1 K-padded) ----------------
__global__ void convw_kernel(const float* __restrict__ w1, const float* __restrict__ w2) {
    int i = blockIdx.x * blockDim.x + threadIdx.x;
    if (i < NFEATP * NU1) {
        int k = i / NU1, n = i % NU1;
        float v = (k < NFEAT) ? w1[(size_t)k * NU1 + n] : 0.0f;
        bsplit(v, g_w1h[i], g_w1l[i]);
    }
    if (i < NU1 * NU2) {
        bsplit(w2[i], g_w2h[i], g_w2l[i]);
    }
}

// ---------------- histogram (4 pairs per thread) ----------------
__global__ __launch_bounds__(256) void hist_kernel(const int* __restrict__ idx) {
    int t = blockIdx.x * blockDim.x + threadIdx.x;
    if (t < NPAIRS / 4) {
        int4 v = ((const int4*)idx)[t];
        atomicAdd(&g_cnt[v.x], 1);
        atomicAdd(&g_cnt[v.y], 1);
        atomicAdd(&g_cnt[v.z], 1);
        atomicAdd(&g_cnt[v.w], 1);
    }
}

// ---------------- 3-phase scan ----------------
__global__ __launch_bounds__(1024) void scan1_kernel() {
    __shared__ int wsum[32];
    int tid = threadIdx.x, lane = tid & 31, w = tid >> 5;
    int i = blockIdx.x * 1024 + tid;
    int v = (i < NATOMS) ? g_cnt[i] : 0;
    int x = v;
#pragma unroll
    for (int o = 1; o < 32; o <<= 1) {
        int y = __shfl_up_sync(0xffffffffu, x, o);
        if (lane >= o) x += y;
    }
    if (lane == 31) wsum[w] = x;
    __syncthreads();
    if (w == 0) {
        int t = wsum[lane];
        int xs = t;
#pragma unroll
        for (int o = 1; o < 32; o <<= 1) {
            int y = __shfl_up_sync(0xffffffffu, xs, o);
            if (lane >= o) xs += y;
        }
        wsum[lane] = xs - t;
    }
    __syncthreads();
    if (i < NATOMS) g_off[i] = wsum[w] + x - v;
    if (tid == 1023) g_bsum[blockIdx.x] = wsum[31] + x;
}
__global__ void scan2_kernel() {
    int lane = threadIdx.x;
    int v = (lane < NSCB) ? g_bsum[lane] : 0;
    int x = v;
#pragma unroll
    for (int o = 1; o < 32; o <<= 1) {
        int y = __shfl_up_sync(0xffffffffu, x, o);
        if (lane >= o) x += y;
    }
    if (lane < NSCB) g_bsum[lane] = x - v;
}
__global__ __launch_bounds__(1024) void scan3_kernel() {
    int i = blockIdx.x * 1024 + threadIdx.x;
    if (i < NATOMS) {
        int o = g_off[i] + g_bsum[blockIdx.x];
        g_off[i] = o;
        g_cur[i] = o;
    }
}

// ---------------- per-pair math + scatter ----------------
__global__ __launch_bounds__(256) void scatter_kernel(
    const int* __restrict__ Z, const int* __restrict__ idx)
{
    int p = blockIdx.x * blockDim.x + threadIdx.x;
    if (p >= NPAIRS) return;
    int i = idx[p];
    int j = idx[NPAIRS + p];

    float4 Ri = g_R4[i];
    float4 Rj = g_R4[j];
    float dx = Rj.x - Ri.x;
    float dy = Rj.y - Ri.y;
    float dz = Rj.z - Ri.z;
    float dr = sqrtf(dx*dx + dy*dy + dz*dz + 1e-12f);

    const float PI = 3.14159265358979323846f;
    float cut = (dr < 6.0f)
              ? 0.5f * (__cosf((PI / 6.0f) * dr) + 1.0f) * 0.37796447300922720f
              : 0.0f;

    float inv = 1.0f / (dr + 1e-5f);
    float ux = dx * inv, uy = dy * inv, uz = dz * inv;

    const float betta = 49.0f / 36.0f;
    const float rn = 0.9601717136386805f;
    float basis[NBASIS];
#pragma unroll
    for (int b = 0; b < NBASIS; b++) {
        float d = dr - (0.5f + 0.7857142857142857f * (float)b);
        basis[b] = rn * __expf(-betta * d * d);
    }

    int zi = Z[i], zj = Z[j];
    const float4* cf4 = (const float4*)(g_Wp + (size_t)(zi * NSPEC + zj) * NRAD * 8);
    float radial[NRAD];
#pragma unroll
    for (int k = 0; k < NRAD; k++) {
        float4 c0 = cf4[k * 2];
        float4 c1 = cf4[k * 2 + 1];
        float s = c0.x * basis[0];
        s = fmaf(c0.y, basis[1], s);
        s = fmaf(c0.z, basis[2], s);
        s = fmaf(c0.w, basis[3], s);
        s = fmaf(c1.x, basis[4], s);
        s = fmaf(c1.y, basis[5], s);
        s = fmaf(c1.z, basis[6], s);
        radial[k] = s * cut;
    }

    int pos = atomicAdd(&g_cur[i], 1);
    float4 lo = make_float4(radial[0], radial[1], radial[2], radial[3]);
    float4 hi = make_float4(radial[4], ux, uy, uz);
    *(float4*)&g_pd[(size_t)pos * 8 + 0] = lo;
    *(float4*)&g_pd[(size_t)pos * 8 + 4] = hi;
}

// ---------------- fused: moment accumulation + invariant contractions -> bf16 features ----------------
__global__ __launch_bounds__(128) void moments_kernel()
{
    int a = blockIdx.x * blockDim.x + threadIdx.x;
    if (a >= NATOMS) return;

    int beg = g_off[a];
    int end = beg + g_cnt[a];

    float acc[NRAD][20];
#pragma unroll
    for (int k = 0; k < NRAD; k++)
#pragma unroll
        for (int m = 0; m < 20; m++) acc[k][m] = 0.0f;

    for (int p = beg; p < end; p++) {
        float4 lo = *(const float4*)&g_pd[(size_t)p * 8 + 0];
        float4 hi = *(const float4*)&g_pd[(size_t)p * 8 + 4];
        float rad[NRAD] = {lo.x, lo.y, lo.z, lo.w, hi.x};
        float ux = hi.y, uy = hi.z, uz = hi.w;
        float g[20];
        g[0] = 1.0f;
        g[1] = ux; g[2] = uy; g[3] = uz;
        float xx = ux*ux, yy = uy*uy, zz = uz*uz;
        float xy = ux*uy, xz = ux*uz, yz = uy*uz;
        g[4] = xx; g[5] = yy; g[6] = zz; g[7] = xy; g[8] = xz; g[9] = yz;
        g[10] = xx*ux; g[11] = xx*uy; g[12] = xx*uz;
        g[13] = yy*ux; g[14] = xy*uz; g[15] = zz*ux;
        g[16] = yy*uy; g[17] = yy*uz; g[18] = zz*uy; g[19] = zz*uz;
#pragma unroll
        for (int k = 0; k < NRAD; k++)
#pragma unroll
            for (int m = 0; m < 20; m++)
                acc[k][m] = fmaf(rad[k], g[m], acc[k][m]);
    }

    // ---- expand symmetric moments and emit 360 features ----
    const int T2[9]  = {0,3,4, 3,1,5, 4,5,2};
    const int T3[27] = {0,1,2, 1,3,4, 2,4,5,
                        1,3,4, 3,6,7, 4,7,8,
                        2,4,5, 4,7,8, 5,8,9};

    float m0v[NRAD];
    float m1v[NRAD][3];
    float m2v[NRAD][9];
    float m3v[NRAD][27];
    for (int k = 0; k < NRAD; k++) {
        m0v[k] = acc[k][0];
        for (int d = 0; d < 3; d++) m1v[k][d] = acc[k][1 + d];
        for (int e = 0; e < 9; e++)  m2v[k][e] = acc[k][4 + T2[e]];
        for (int e = 0; e < 27; e++) m3v[k][e] = acc[k][10 + T3[e]];
    }

    int f = 0;
#define EMIT(v) do { __nv_bfloat16 _h, _l; bsplit((v), _h, _l); \
    g_GMh[(size_t)(f) * AP + a] = _h; g_GMl[(size_t)(f) * AP + a] = _l; f++; } while (0)

    for (int k = 0; k < NRAD; k++) EMIT(m0v[k]);

    for (int r = 0; r < NRAD; r++)
        for (int s = r; s < NRAD; s++) {
            float v = m1v[r][0]*m1v[s][0] + m1v[r][1]*m1v[s][1] + m1v[r][2]*m1v[s][2];
            EMIT(v);
        }

    for (int r = 0; r < NRAD; r++)
        for (int s = r; s < NRAD; s++) {
            float v = 0.0f;
            for (int e = 0; e < 9; e++) v = fmaf(m2v[r][e], m2v[s][e], v);
            EMIT(v);
        }

    for (int r = 0; r < NRAD; r++)
        for (int s = r; s < NRAD; s++) {
            float v = 0.0f;
            for (int e = 0; e < 27; e++) v = fmaf(m3v[r][e], m3v[s][e], v);
            EMIT(v);
        }

    for (int r = 0; r < NRAD; r++)
        for (int s = r; s < NRAD; s++)
            for (int t = s; t < NRAD; t++) {
                float v = 0.0f;
                for (int jj = 0; jj < 3; jj++)
                    for (int kk = 0; kk < 3; kk++) {
                        float pjk = 0.0f;
                        for (int ii = 0; ii < 3; ii++)
                            pjk = fmaf(m2v[r][ii*3 + jj], m2v[s][ii*3 + kk], pjk);
                        v = fmaf(pjk, m2v[t][jj*3 + kk], v);
                    }
                EMIT(v);
            }

    for (int r = 0; r < NRAD; r++)
        for (int s = r; s < NRAD; s++) {
            float O[9];
            for (int ii = 0; ii < 3; ii++)
                for (int jj = 0; jj < 3; jj++)
                    O[ii*3 + jj] = m1v[r][ii] * m1v[s][jj];
            for (int t = 0; t < NRAD; t++) {
                float v = 0.0f;
                for (int e = 0; e < 9; e++) v = fmaf(O[e], m2v[t][e], v);
                EMIT(v);
            }
        }

    for (int r = 0; r < NRAD; r++)
        for (int s = r; s < NRAD; s++) {
            float T[9];
            for (int kk = 0; kk < 3; kk++)
                for (int ll = 0; ll < 3; ll++) {
                    float acc2 = 0.0f;
                    for (int ij = 0; ij < 9; ij++)
                        acc2 = fmaf(m3v[r][ij*3 + kk], m3v[s][ij*3 + ll], acc2);
                    T[kk*3 + ll] = acc2;
                }
            for (int t = 0; t < NRAD; t++) {
                float v = 0.0f;
                for (int e = 0; e < 9; e++) v = fmaf(T[e], m2v[t][e], v);
                EMIT(v);
            }
        }

    for (int r = 0; r < NRAD; r++)
        for (int s = 0; s < NRAD; s++) {
            float w[3];
            for (int kk = 0; kk < 3; kk++) {
                float acc2 = 0.0f;
                for (int ij = 0; ij < 9; ij++)
                    acc2 = fmaf(m3v[r][ij*3 + kk], m2v[s][ij], acc2);
                w[kk] = acc2;
            }
            for (int t = 0; t < NRAD; t++) {
                float v = w[0]*m1v[t][0] + w[1]*m1v[t][1] + w[2]*m1v[t][2];
                EMIT(v);
            }
        }
#undef EMIT
}

// ============================================================================
// bf16x3 tensor-core GEMMs (mma.sync), cp.async-pipelined. 128x128 tile, BK=16.
// LAYER1: GM -> H1 (bf16 hi/lo, swish). LAYER2: H1 -> fused layer-3 dot -> out.
// ============================================================================
#define AS_STR  24
#define KM_STR  136

__device__ __forceinline__ unsigned smem_u32(const void* p) {
    return (unsigned)__cvta_generic_to_shared(p);
}
__device__ __forceinline__ void cpa16(void* s, const void* g) {
    asm volatile("cp.async.cg.shared.global [%0], [%1], 16;"
                 :: "r"(smem_u32(s)), "l"(g) : "memory");
}
__device__ __forceinline__ void cp_commit() {
    asm volatile("cp.async.commit_group;" ::: "memory");
}
__device__ __forceinline__ void cp_wait0() {
    asm volatile("cp.async.wait_group 0;" ::: "memory");
}
__device__ __forceinline__ void ldsm4(unsigned* r, unsigned addr) {
    asm volatile("ldmatrix.sync.aligned.m8n8.x4.shared.b16 {%0,%1,%2,%3}, [%4];"
        : "=r"(r[0]), "=r"(r[1]), "=r"(r[2]), "=r"(r[3]) : "r"(addr));
}
__device__ __forceinline__ void ldsm4t(unsigned* r, unsigned addr) {
    asm volatile("ldmatrix.sync.aligned.m8n8.x4.trans.shared.b16 {%0,%1,%2,%3}, [%4];"
        : "=r"(r[0]), "=r"(r[1]), "=r"(r[2]), "=r"(r[3]) : "r"(addr));
}
__device__ __forceinline__ void mma_bf16(float* d, const unsigned* a, unsigned b0, unsigned b1) {
    asm volatile("mma.sync.aligned.m16n8k16.row.col.f32.bf16.bf16.f32 "
        "{%0,%1,%2,%3}, {%4,%5,%6,%7}, {%8,%9}, {%0,%1,%2,%3};"
        : "+f"(d[0]), "+f"(d[1]), "+f"(d[2]), "+f"(d[3])
        : "r"(a[0]), "r"(a[1]), "r"(a[2]), "r"(a[3]), "r"(b0), "r"(b1));
}

template<int LAYER>
__global__ __launch_bounds__(256, 2) void mma_gemm_kernel(
    const __nv_bfloat16* __restrict__ Ah, const __nv_bfloat16* __restrict__ Al,
    const __nv_bfloat16* __restrict__ Bh, const __nv_bfloat16* __restrict__ Bl,
    const float* __restrict__ bias,
    int M, int N, int K, int Astride,
    const float* __restrict__ w3, const float* __restrict__ scale,
    const int* __restrict__ Z, float* __restrict__ out)
{
    __shared__ __align__(16) __nv_bfloat16 Ash[2][2][(16 * KM_STR > 128 * AS_STR) ? 16 * KM_STR : 128 * AS_STR];
    __shared__ __align__(16) __nv_bfloat16 Bsh[2][2][16 * KM_STR];

    int tid = threadIdx.x;
    int lane = tid & 31;
    int wid = tid >> 5;
    int wm = wid & 3;
    int wn = wid >> 2;
    int m0 = blockIdx.y * 128;
    int n0 = blockIdx.x * 128;

    int lk = tid >> 4;
    int lm8 = (tid & 15) * 8;
    int lmB = tid >> 1;
    int lkg = (tid & 1) * 8;

    float acc[2][8][4];
#pragma unroll
    for (int f = 0; f < 2; f++)
#pragma unroll
        for (int n8 = 0; n8 < 8; n8++)
#pragma unroll
            for (int q = 0; q < 4; q++) acc[f][n8][q] = 0.0f;

    int nT = K / 16;

    auto issue_tile = [&](int kt, int buf) {
        if (LAYER == 1) {
            size_t off = (size_t)(kt + lk) * Astride + m0 + lm8;
            cpa16(&Ash[buf][0][lk * KM_STR + lm8], &Ah[off]);
            cpa16(&Ash[buf][1][lk * KM_STR + lm8], &Al[off]);
        } else {
            int gm = m0 + lmB;
            if (gm >= M) gm = M - 1;
            size_t off = (size_t)gm * K + kt + lkg;
            cpa16(&Ash[buf][0][lmB * AS_STR + lkg], &Ah[off]);
            cpa16(&Ash[buf][1][lmB * AS_STR + lkg], &Al[off]);
        }
        size_t woff = (size_t)(kt + lk) * N + n0 + lm8;
        cpa16(&Bsh[buf][0][lk * KM_STR + lm8], &Bh[woff]);
        cpa16(&Bsh[buf][1][lk * KM_STR + lm8], &Bl[woff]);
    };

    unsigned aoff;
    if (LAYER == 1) {
        int krow = (lane & 7) + ((lane >> 4) << 3);
        int mcol = wm * 32 + (((lane >> 3) & 1) << 3);
        aoff = (krow * KM_STR + mcol) * 2;
    } else {
        aoff = ((wm * 32 + (lane & 15)) * AS_STR + (lane >> 4) * 8) * 2;
    }
    unsigned boff = ((lane & 15) * KM_STR + wn * 64 + (lane >> 4) * 8) * 2;

    issue_tile(0, 0);
    cp_commit();
    cp_wait0();
    __syncthreads();

    for (int t = 0; t < nT; t++) {
        int cur = t & 1;
        bool has = (t + 1 < nT);
        if (has) { issue_tile((t + 1) * 16, cur ^ 1); cp_commit(); }

        unsigned aBaseH = smem_u32(&Ash[cur][0][0]) + aoff;
        unsigned aBaseL = smem_u32(&Ash[cur][1][0]) + aoff;
        unsigned bBaseH = smem_u32(&Bsh[cur][0][0]) + boff;
        unsigned bBaseL = smem_u32(&Bsh[cur][1][0]) + boff;

        unsigned ah[2][4], al[2][4], bh[4][4], bl[4][4];
#pragma unroll
        for (int f = 0; f < 2; f++) {
            if (LAYER == 1) {
                ldsm4t(ah[f], aBaseH + f * 16 * 2);
                ldsm4t(al[f], aBaseL + f * 16 * 2);
            } else {
                ldsm4(ah[f], aBaseH + f * 16 * AS_STR * 2);
                ldsm4(al[f], aBaseL + f * 16 * AS_STR * 2);
            }
        }
#pragma unroll
        for (int nb = 0; nb < 4; nb++) {
            ldsm4t(bh[nb], bBaseH + nb * 32);
            ldsm4t(bl[nb], bBaseL + nb * 32);
        }

#pragma unroll
        for (int f = 0; f < 2; f++)
#pragma unroll
            for (int nb = 0; nb < 4; nb++)
#pragma unroll
                for (int j = 0; j < 2; j++) {
                    float* d = acc[f][nb * 2 + j];
                    unsigned bh0 = bh[nb][2 * j], bh1 = bh[nb][2 * j + 1];
                    unsigned bl0 = bl[nb][2 * j], bl1 = bl[nb][2 * j + 1];
                    mma_bf16(d, ah[f], bh0, bh1);
                    mma_bf16(d, ah[f], bl0, bl1);
                    mma_bf16(d, al[f], bh0, bh1);
                }

        if (has) cp_wait0();
        __syncthreads();
    }

    // ---- epilogue ----
    if (LAYER == 1) {
#pragma unroll
        for (int f = 0; f < 2; f++)
#pragma unroll
            for (int n8 = 0; n8 < 8; n8++) {
                int rm = m0 + wm * 32 + f * 16 + (lane >> 2);
                int cn = n0 + wn * 64 + n8 * 8 + (lane & 3) * 2;
                float b0 = bias[cn], b1 = bias[cn + 1];
#pragma unroll
                for (int half = 0; half < 2; half++) {
                    int r = rm + half * 8;
                    if (r >= M) continue;
                    float v0 = acc[f][n8][half * 2 + 0] + b0;
                    float v1 = acc[f][n8][half * 2 + 1] + b1;
                    v0 = v0 / (1.0f + __expf(-v0));
                    v1 = v1 / (1.0f + __expf(-v1));
                    __nv_bfloat16 h0, l0, h1, l1;
                    bsplit(v0, h0, l0); bsplit(v1, h1, l1);
                    *(__nv_bfloat162*)&g_H1h[(size_t)r * NU1 + cn] = __nv_bfloat162(h0, h1);
                    *(__nv_bfloat162*)&g_H1l[(size_t)r * NU1 + cn] = __nv_bfloat162(l0, l1);
                }
            }
    } else {
        // fused layer 3: swish then dot with w3, reduce over the 4 lanes (lane&3),
        // atomicAdd scale[z]*partial into out[r].
        float rs[2][2] = {{0.0f, 0.0f}, {0.0f, 0.0f}};
#pragma unroll
        for (int f = 0; f < 2; f++)
#pragma unroll
            for (int n8 = 0; n8 < 8; n8++) {
                int cn = n0 + wn * 64 + n8 * 8 + (lane & 3) * 2;
                float b0 = bias[cn], b1 = bias[cn + 1];
                float w0 = w3[cn], w1 = w3[cn + 1];
#pragma unroll
                for (int half = 0; half < 2; half++) {
                    float v0 = acc[f][n8][half * 2 + 0] + b0;
                    float v1 = acc[f][n8][half * 2 + 1] + b1;
                    v0 = v0 / (1.0f + __expf(-v0));
                    v1 = v1 / (1.0f + __expf(-v1));
                    rs[f][half] = fmaf(v0, w0, fmaf(v1, w1, rs[f][half]));
                }
            }
#pragma unroll
        for (int f = 0; f < 2; f++)
#pragma unroll
            for (int half = 0; half < 2; half++) {
                float s = rs[f][half];
                s += __shfl_xor_sync(0xffffffffu, s, 1);
                s += __shfl_xor_sync(0xffffffffu, s, 2);
                if ((lane & 3) == 0) {
                    int r = m0 + wm * 32 + f * 16 + (lane >> 2) + half * 8;
                    if (r < M) {
                        atomicAdd(&out[r], scale[Z[r]] * s);
                    }
                }
            }
    }
}

// ---------------- launch ----------------
extern "C" void kernel_launch(void* const* d_in, const int* in_sizes, int n_in,
                              void* d_out, int out_size)
{
    const float* R     = (const float*)d_in[0];
    const int*   Z     = (const int*)  d_in[1];
    const int*   idx   = (const int*)  d_in[2];
    const float* Wr    = (const float*)d_in[3];
    const float* w1    = (const float*)d_in[4];
    const float* b1    = (const float*)d_in[5];
    const float* w2    = (const float*)d_in[6];
    const float* b2    = (const float*)d_in[7];
    const float* w3    = (const float*)d_in[8];
    const float* b3    = (const float*)d_in[9];
    const float* scale = (const float*)d_in[10];
    const float* shift = (const float*)d_in[11];
    float* out = (float*)d_out;

    __nv_bfloat16 *pGMh, *pGMl, *pW1h, *pW1l, *pW2h, *pW2l, *pH1h, *pH1l;
    cudaGetSymbolAddress((void**)&pGMh, g_GMh);
    cudaGetSymbolAddress((void**)&pGMl, g_GMl);
    cudaGetSymbolAddress((void**)&pW1h, g_w1h);
    cudaGetSymbolAddress((void**)&pW1l, g_w1l);
    cudaGetSymbolAddress((void**)&pW2h, g_w2h);
    cudaGetSymbolAddress((void**)&pW2l, g_w2l);
    cudaGetSymbolAddress((void**)&pH1h, g_H1h);
    cudaGetSymbolAddress((void**)&pH1l, g_H1l);

    prep_kernel<<<(NATOMS + 255) / 256, 256>>>(R, Z, scale, shift, b3, out);
    packw_kernel<<<(NSPEC * NSPEC * NRAD * NBASIS + 255) / 256, 256>>>(Wr);
    convw_kernel<<<(NU1 * NU2 + 255) / 256, 256>>>(w1, w2);
    hist_kernel<<<(NPAIRS / 4 + 255) / 256, 256>>>(idx);
    scan1_kernel<<<NSCB, 1024>>>();
    scan2_kernel<<<1, 32>>>();
    scan3_kernel<<<NSCB, 1024>>>();
    scatter_kernel<<<(NPAIRS + 255) / 256, 256>>>(Z, idx);
    moments_kernel<<<(NATOMS + 127) / 128, 128>>>();

    dim3 g1(NU1 / 128, (NATOMS + 127) / 128);
    mma_gemm_kernel<1><<<g1, 256>>>(pGMh, pGMl, pW1h, pW1l, b1, NATOMS, NU1, NFEATP, AP,
                                    nullptr, nullptr, nullptr, nullptr);

    dim3 g2(NU2 / 128, (NATOMS + 127) / 128);
    mma_gemm_kernel<2><<<g2, 256>>>(pH1h, pH1l, pW2h, pW2l, b2, NATOMS, NU2, NU1, 0,
                                    w3, scale, Z, out);
}

// round 13
// speedup vs baseline: 3.4123x; 1.0238x over previous
#include <cuda_runtime.h>
#include <cuda_bf16.h>
#include <math.h>
#include <stdint.h>
#include <cstdint>

#define NATOMS 30000
#define NPAIRS 1200000
#define NBASIS 7
#define NRAD   5
#define NSPEC  119
#define NFEAT  360
#define NFEATP 368          // layer-1 K padded to multiple of 16
#define AP     30080        // atoms padded (unused rows zero)
#define NU1    512
#define NU2    512
#define NSCB   30           // scan blocks

// ---------------- static scratch (no allocations; BSS zero-initialized) ----------------
__device__ int    g_cnt[NATOMS];
__device__ int    g_off[NATOMS];
__device__ int    g_cur[NATOMS];
__device__ int    g_bsum[32];
__device__ float4 g_R4[NATOMS];
__device__ float  g_Wp[(size_t)NSPEC * NSPEC * NRAD * 8];   // padded radial weights [pair][k][8]
__device__ float  g_pd[(size_t)NPAIRS * 8];
// feature-major GM [NFEATP][AP] bf16 hi/lo (pads stay zero)
__device__ __nv_bfloat16 g_GMh[(size_t)NFEATP * AP];
__device__ __nv_bfloat16 g_GMl[(size_t)NFEATP * AP];
__device__ __nv_bfloat16 g_w1h[NFEATP * NU1];
__device__ __nv_bfloat16 g_w1l[NFEATP * NU1];
__device__ __nv_bfloat16 g_w2h[NU1 * NU2];
__device__ __nv_bfloat16 g_w2l[NU1 * NU2];
__device__ __nv_bfloat16 g_H1h[(size_t)NATOMS * NU1];
__device__ __nv_bfloat16 g_H1l[(size_t)NATOMS * NU1];

__device__ __forceinline__ void bsplit(float v, __nv_bfloat16& h, __nv_bfloat16& l) {
    h = __float2bfloat16(v);
    l = __float2bfloat16(v - __bfloat162float(h));
}

// ---------------- prep: counters, padded R, init out = scale*b3 + shift ----------------
__global__ void prep_kernel(const float* __restrict__ R, const int* __restrict__ Z,
                            const float* __restrict__ scale, const float* __restrict__ shift,
                            const float* __restrict__ b3, float* __restrict__ out) {
    int i = blockIdx.x * blockDim.x + threadIdx.x;
    if (i < NATOMS) {
        g_cnt[i] = 0;
        g_R4[i] = make_float4(R[3*i+0], R[3*i+1], R[3*i+2], 0.0f);
        int z = Z[i];
        out[i] = scale[z] * b3[0] + shift[z];
    }
}

// ---------------- repack Wr [pair][5][7] -> float4-aligned [pair][5][8] ----------------
__global__ __launch_bounds__(256) void packw_kernel(const float* __restrict__ Wr) {
    int i = blockIdx.x * blockDim.x + threadIdx.x;
    int total = NSPEC * NSPEC * NRAD * NBASIS;
    if (i >= total) return;
    int b = i % NBASIS;
    int rest = i / NBASIS;
    int k = rest % NRAD;
    int pair = rest / NRAD;
    g_Wp[((size_t)pair * NRAD + k) * 8 + b] = Wr[i];
}

// ---------------- weights -> bf16 hi/lo (w1 K-padded) ----------------
__global__ void convw_kernel(const float* __restrict__ w1, const float* __restrict__ w2) {
    int i = blockIdx.x * blockDim.x + threadIdx.x;
    if (i < NFEATP * NU1) {
        int k = i / NU1, n = i % NU1;
        float v = (k < NFEAT) ? w1[(size_t)k * NU1 + n] : 0.0f;
        bsplit(v, g_w1h[i], g_w1l[i]);
    }
    if (i < NU1 * NU2) {
        bsplit(w2[i], g_w2h[i], g_w2l[i]);
    }
}

// ---------------- histogram (4 pairs per thread) ----------------
__global__ __launch_bounds__(256) void hist_kernel(const int* __restrict__ idx) {
    int t = blockIdx.x * blockDim.x + threadIdx.x;
    if (t < NPAIRS / 4) {
        int4 v = ((const int4*)idx)[t];
        atomicAdd(&g_cnt[v.x], 1);
        atomicAdd(&g_cnt[v.y], 1);
        atomicAdd(&g_cnt[v.z], 1);
        atomicAdd(&g_cnt[v.w], 1);
    }
}

// ---------------- 3-phase scan ----------------
__global__ __launch_bounds__(1024) void scan1_kernel() {
    __shared__ int wsum[32];
    int tid = threadIdx.x, lane = tid & 31, w = tid >> 5;
    int i = blockIdx.x * 1024 + tid;
    int v = (i < NATOMS) ? g_cnt[i] : 0;
    int x = v;
#pragma unroll
    for (int o = 1; o < 32; o <<= 1) {
        int y = __shfl_up_sync(0xffffffffu, x, o);
        if (lane >= o) x += y;
    }
    if (lane == 31) wsum[w] = x;
    __syncthreads();
    if (w == 0) {
        int t = wsum[lane];
        int xs = t;
#pragma unroll
        for (int o = 1; o < 32; o <<= 1) {
            int y = __shfl_up_sync(0xffffffffu, xs, o);
            if (lane >= o) xs += y;
        }
        wsum[lane] = xs - t;
    }
    __syncthreads();
    if (i < NATOMS) g_off[i] = wsum[w] + x - v;
    if (tid == 1023) g_bsum[blockIdx.x] = wsum[31] + x;
}
__global__ void scan2_kernel() {
    int lane = threadIdx.x;
    int v = (lane < NSCB) ? g_bsum[lane] : 0;
    int x = v;
#pragma unroll
    for (int o = 1; o < 32; o <<= 1) {
        int y = __shfl_up_sync(0xffffffffu, x, o);
        if (lane >= o) x += y;
    }
    if (lane < NSCB) g_bsum[lane] = x - v;
}
__global__ __launch_bounds__(1024) void scan3_kernel() {
    int i = blockIdx.x * 1024 + threadIdx.x;
    if (i < NATOMS) {
        int o = g_off[i] + g_bsum[blockIdx.x];
        g_off[i] = o;
        g_cur[i] = o;
    }
}

// ---------------- per-pair math + scatter (2 pairs/thread for MLP) ----------------
__global__ __launch_bounds__(256) void scatter_kernel(
    const int* __restrict__ Z, const int* __restrict__ idx)
{
    int t = blockIdx.x * blockDim.x + threadIdx.x;
    int p0 = t * 2;
    if (p0 >= NPAIRS) return;

    // batch the gathers for both pairs up front
    int i0 = idx[p0],            j0 = idx[NPAIRS + p0];
    int i1 = idx[p0 + 1],        j1 = idx[NPAIRS + p0 + 1];
    float4 Ri0 = g_R4[i0], Rj0 = g_R4[j0];
    float4 Ri1 = g_R4[i1], Rj1 = g_R4[j1];
    int zi0 = Z[i0], zj0 = Z[j0];
    int zi1 = Z[i1], zj1 = Z[j1];

    const float4* cf0 = (const float4*)(g_Wp + (size_t)(zi0 * NSPEC + zj0) * NRAD * 8);
    const float4* cf1 = (const float4*)(g_Wp + (size_t)(zi1 * NSPEC + zj1) * NRAD * 8);

    const float PI = 3.14159265358979323846f;
    const float betta = 49.0f / 36.0f;
    const float rn = 0.9601717136386805f;

#pragma unroll
    for (int q = 0; q < 2; q++) {
        float4 Ri = q ? Ri1 : Ri0;
        float4 Rj = q ? Rj1 : Rj0;
        const float4* cf4 = q ? cf1 : cf0;
        int i = q ? i1 : i0;

        float dx = Rj.x - Ri.x;
        float dy = Rj.y - Ri.y;
        float dz = Rj.z - Ri.z;
        float dr = sqrtf(dx*dx + dy*dy + dz*dz + 1e-12f);

        float cut = (dr < 6.0f)
                  ? 0.5f * (__cosf((PI / 6.0f) * dr) + 1.0f) * 0.37796447300922720f
                  : 0.0f;

        float inv = 1.0f / (dr + 1e-5f);
        float ux = dx * inv, uy = dy * inv, uz = dz * inv;

        float basis[NBASIS];
#pragma unroll
        for (int b = 0; b < NBASIS; b++) {
            float d = dr - (0.5f + 0.7857142857142857f * (float)b);
            basis[b] = rn * __expf(-betta * d * d);
        }

        float radial[NRAD];
#pragma unroll
        for (int k = 0; k < NRAD; k++) {
            float4 c0 = cf4[k * 2];
            float4 c1 = cf4[k * 2 + 1];
            float s = c0.x * basis[0];
            s = fmaf(c0.y, basis[1], s);
            s = fmaf(c0.z, basis[2], s);
            s = fmaf(c0.w, basis[3], s);
            s = fmaf(c1.x, basis[4], s);
            s = fmaf(c1.y, basis[5], s);
            s = fmaf(c1.z, basis[6], s);
            radial[k] = s * cut;
        }

        int pos = atomicAdd(&g_cur[i], 1);
        float4 lo = make_float4(radial[0], radial[1], radial[2], radial[3]);
        float4 hi = make_float4(radial[4], ux, uy, uz);
        *(float4*)&g_pd[(size_t)pos * 8 + 0] = lo;
        *(float4*)&g_pd[(size_t)pos * 8 + 4] = hi;
    }
}

// ---------------- fused: moment accumulation (unroll-2) + invariants -> bf16 features ----------------
__global__ __launch_bounds__(128) void moments_kernel()
{
    int a = blockIdx.x * blockDim.x + threadIdx.x;
    if (a >= NATOMS) return;

    int beg = g_off[a];
    int end = beg + g_cnt[a];

    float acc[NRAD][20];
#pragma unroll
    for (int k = 0; k < NRAD; k++)
#pragma unroll
        for (int m = 0; m < 20; m++) acc[k][m] = 0.0f;

    auto body = [&](float4 lo, float4 hi) {
        float rad[NRAD] = {lo.x, lo.y, lo.z, lo.w, hi.x};
        float ux = hi.y, uy = hi.z, uz = hi.w;
        float g[20];
        g[0] = 1.0f;
        g[1] = ux; g[2] = uy; g[3] = uz;
        float xx = ux*ux, yy = uy*uy, zz = uz*uz;
        float xy = ux*uy, xz = ux*uz, yz = uy*uz;
        g[4] = xx; g[5] = yy; g[6] = zz; g[7] = xy; g[8] = xz; g[9] = yz;
        g[10] = xx*ux; g[11] = xx*uy; g[12] = xx*uz;
        g[13] = yy*ux; g[14] = xy*uz; g[15] = zz*ux;
        g[16] = yy*uy; g[17] = yy*uz; g[18] = zz*uy; g[19] = zz*uz;
#pragma unroll
        for (int k = 0; k < NRAD; k++)
#pragma unroll
            for (int m = 0; m < 20; m++)
                acc[k][m] = fmaf(rad[k], g[m], acc[k][m]);
    };

    int p = beg;
    for (; p + 1 < end; p += 2) {
        float4 lo0 = *(const float4*)&g_pd[(size_t)p * 8 + 0];
        float4 hi0 = *(const float4*)&g_pd[(size_t)p * 8 + 4];
        float4 lo1 = *(const float4*)&g_pd[(size_t)(p + 1) * 8 + 0];
        float4 hi1 = *(const float4*)&g_pd[(size_t)(p + 1) * 8 + 4];
        body(lo0, hi0);
        body(lo1, hi1);
    }
    if (p < end) {
        float4 lo = *(const float4*)&g_pd[(size_t)p * 8 + 0];
        float4 hi = *(const float4*)&g_pd[(size_t)p * 8 + 4];
        body(lo, hi);
    }

    // ---- expand symmetric moments and emit 360 features ----
    const int T2[9]  = {0,3,4, 3,1,5, 4,5,2};
    const int T3[27] = {0,1,2, 1,3,4, 2,4,5,
                        1,3,4, 3,6,7, 4,7,8,
                        2,4,5, 4,7,8, 5,8,9};

    float m0v[NRAD];
    float m1v[NRAD][3];
    float m2v[NRAD][9];
    float m3v[NRAD][27];
    for (int k = 0; k < NRAD; k++) {
        m0v[k] = acc[k][0];
        for (int d = 0; d < 3; d++) m1v[k][d] = acc[k][1 + d];
        for (int e = 0; e < 9; e++)  m2v[k][e] = acc[k][4 + T2[e]];
        for (int e = 0; e < 27; e++) m3v[k][e] = acc[k][10 + T3[e]];
    }

    int f = 0;
#define EMIT(v) do { __nv_bfloat16 _h, _l; bsplit((v), _h, _l); \
    g_GMh[(size_t)(f) * AP + a] = _h; g_GMl[(size_t)(f) * AP + a] = _l; f++; } while (0)

    for (int k = 0; k < NRAD; k++) EMIT(m0v[k]);

    for (int r = 0; r < NRAD; r++)
        for (int s = r; s < NRAD; s++) {
            float v = m1v[r][0]*m1v[s][0] + m1v[r][1]*m1v[s][1] + m1v[r][2]*m1v[s][2];
            EMIT(v);
        }

    for (int r = 0; r < NRAD; r++)
        for (int s = r; s < NRAD; s++) {
            float v = 0.0f;
            for (int e = 0; e < 9; e++) v = fmaf(m2v[r][e], m2v[s][e], v);
            EMIT(v);
        }

    for (int r = 0; r < NRAD; r++)
        for (int s = r; s < NRAD; s++) {
            float v = 0.0f;
            for (int e = 0; e < 27; e++) v = fmaf(m3v[r][e], m3v[s][e], v);
            EMIT(v);
        }

    for (int r = 0; r < NRAD; r++)
        for (int s = r; s < NRAD; s++)
            for (int t = s; t < NRAD; t++) {
                float v = 0.0f;
                for (int jj = 0; jj < 3; jj++)
                    for (int kk = 0; kk < 3; kk++) {
                        float pjk = 0.0f;
                        for (int ii = 0; ii < 3; ii++)
                            pjk = fmaf(m2v[r][ii*3 + jj], m2v[s][ii*3 + kk], pjk);
                        v = fmaf(pjk, m2v[t][jj*3 + kk], v);
                    }
                EMIT(v);
            }

    for (int r = 0; r < NRAD; r++)
        for (int s = r; s < NRAD; s++) {
            float O[9];
            for (int ii = 0; ii < 3; ii++)
                for (int jj = 0; jj < 3; jj++)
                    O[ii*3 + jj] = m1v[r][ii] * m1v[s][jj];
            for (int t = 0; t < NRAD; t++) {
                float v = 0.0f;
                for (int e = 0; e < 9; e++) v = fmaf(O[e], m2v[t][e], v);
                EMIT(v);
            }
        }

    for (int r = 0; r < NRAD; r++)
        for (int s = r; s < NRAD; s++) {
            float T[9];
            for (int kk = 0; kk < 3; kk++)
                for (int ll = 0; ll < 3; ll++) {
                    float acc2 = 0.0f;
                    for (int ij = 0; ij < 9; ij++)
                        acc2 = fmaf(m3v[r][ij*3 + kk], m3v[s][ij*3 + ll], acc2);
                    T[kk*3 + ll] = acc2;
                }
            for (int t = 0; t < NRAD; t++) {
                float v = 0.0f;
                for (int e = 0; e < 9; e++) v = fmaf(T[e], m2v[t][e], v);
                EMIT(v);
            }
        }

    for (int r = 0; r < NRAD; r++)
        for (int s = 0; s < NRAD; s++) {
            float w[3];
            for (int kk = 0; kk < 3; kk++) {
                float acc2 = 0.0f;
                for (int ij = 0; ij < 9; ij++)
                    acc2 = fmaf(m3v[r][ij*3 + kk], m2v[s][ij], acc2);
                w[kk] = acc2;
            }
            for (int t = 0; t < NRAD; t++) {
                float v = w[0]*m1v[t][0] + w[1]*m1v[t][1] + w[2]*m1v[t][2];
                EMIT(v);
            }
        }
#undef EMIT
}

// ============================================================================
// bf16x3 tensor-core GEMMs (mma.sync), cp.async-pipelined. 128x128 tile, BK=16.
// LAYER1: GM -> H1 (bf16 hi/lo, swish). LAYER2: H1 -> fused layer-3 dot -> out.
// ============================================================================
#define AS_STR  24
#define KM_STR  136

__device__ __forceinline__ unsigned smem_u32(const void* p) {
    return (unsigned)__cvta_generic_to_shared(p);
}
__device__ __forceinline__ void cpa16(void* s, const void* g) {
    asm volatile("cp.async.cg.shared.global [%0], [%1], 16;"
                 :: "r"(smem_u32(s)), "l"(g) : "memory");
}
__device__ __forceinline__ void cp_commit() {
    asm volatile("cp.async.commit_group;" ::: "memory");
}
__device__ __forceinline__ void cp_wait0() {
    asm volatile("cp.async.wait_group 0;" ::: "memory");
}
__device__ __forceinline__ void ldsm4(unsigned* r, unsigned addr) {
    asm volatile("ldmatrix.sync.aligned.m8n8.x4.shared.b16 {%0,%1,%2,%3}, [%4];"
        : "=r"(r[0]), "=r"(r[1]), "=r"(r[2]), "=r"(r[3]) : "r"(addr));
}
__device__ __forceinline__ void ldsm4t(unsigned* r, unsigned addr) {
    asm volatile("ldmatrix.sync.aligned.m8n8.x4.trans.shared.b16 {%0,%1,%2,%3}, [%4];"
        : "=r"(r[0]), "=r"(r[1]), "=r"(r[2]), "=r"(r[3]) : "r"(addr));
}
__device__ __forceinline__ void mma_bf16(float* d, const unsigned* a, unsigned b0, unsigned b1) {
    asm volatile("mma.sync.aligned.m16n8k16.row.col.f32.bf16.bf16.f32 "
        "{%0,%1,%2,%3}, {%4,%5,%6,%7}, {%8,%9}, {%0,%1,%2,%3};"
        : "+f"(d[0]), "+f"(d[1]), "+f"(d[2]), "+f"(d[3])
        : "r"(a[0]), "r"(a[1]), "r"(a[2]), "r"(a[3]), "r"(b0), "r"(b1));
}

template<int LAYER>
__global__ __launch_bounds__(256, 2) void mma_gemm_kernel(
    const __nv_bfloat16* __restrict__ Ah, const __nv_bfloat16* __restrict__ Al,
    const __nv_bfloat16* __restrict__ Bh, const __nv_bfloat16* __restrict__ Bl,
    const float* __restrict__ bias,
    int M, int N, int K, int Astride,
    const float* __restrict__ w3, const float* __restrict__ scale,
    const int* __restrict__ Z, float* __restrict__ out)
{
    __shared__ __align__(16) __nv_bfloat16 Ash[2][2][(16 * KM_STR > 128 * AS_STR) ? 16 * KM_STR : 128 * AS_STR];
    __shared__ __align__(16) __nv_bfloat16 Bsh[2][2][16 * KM_STR];

    int tid = threadIdx.x;
    int lane = tid & 31;
    int wid = tid >> 5;
    int wm = wid & 3;
    int wn = wid >> 2;
    int m0 = blockIdx.y * 128;
    int n0 = blockIdx.x * 128;

    int lk = tid >> 4;
    int lm8 = (tid & 15) * 8;
    int lmB = tid >> 1;
    int lkg = (tid & 1) * 8;

    float acc[2][8][4];
#pragma unroll
    for (int f = 0; f < 2; f++)
#pragma unroll
        for (int n8 = 0; n8 < 8; n8++)
#pragma unroll
            for (int q = 0; q < 4; q++) acc[f][n8][q] = 0.0f;

    int nT = K / 16;

    auto issue_tile = [&](int kt, int buf) {
        if (LAYER == 1) {
            size_t off = (size_t)(kt + lk) * Astride + m0 + lm8;
            cpa16(&Ash[buf][0][lk * KM_STR + lm8], &Ah[off]);
            cpa16(&Ash[buf][1][lk * KM_STR + lm8], &Al[off]);
        } else {
            int gm = m0 + lmB;
            if (gm >= M) gm = M - 1;
            size_t off = (size_t)gm * K + kt + lkg;
            cpa16(&Ash[buf][0][lmB * AS_STR + lkg], &Ah[off]);
            cpa16(&Ash[buf][1][lmB * AS_STR + lkg], &Al[off]);
        }
        size_t woff = (size_t)(kt + lk) * N + n0 + lm8;
        cpa16(&Bsh[buf][0][lk * KM_STR + lm8], &Bh[woff]);
        cpa16(&Bsh[buf][1][lk * KM_STR + lm8], &Bl[woff]);
    };

    unsigned aoff;
    if (LAYER == 1) {
        int krow = (lane & 7) + ((lane >> 4) << 3);
        int mcol = wm * 32 + (((lane >> 3) & 1) << 3);
        aoff = (krow * KM_STR + mcol) * 2;
    } else {
        aoff = ((wm * 32 + (lane & 15)) * AS_STR + (lane >> 4) * 8) * 2;
    }
    unsigned boff = ((lane & 15) * KM_STR + wn * 64 + (lane >> 4) * 8) * 2;

    issue_tile(0, 0);
    cp_commit();
    cp_wait0();
    __syncthreads();

    for (int t = 0; t < nT; t++) {
        int cur = t & 1;
        bool has = (t + 1 < nT);
        if (has) { issue_tile((t + 1) * 16, cur ^ 1); cp_commit(); }

        unsigned aBaseH = smem_u32(&Ash[cur][0][0]) + aoff;
        unsigned aBaseL = smem_u32(&Ash[cur][1][0]) + aoff;
        unsigned bBaseH = smem_u32(&Bsh[cur][0][0]) + boff;
        unsigned bBaseL = smem_u32(&Bsh[cur][1][0]) + boff;

        unsigned ah[2][4], al[2][4], bh[4][4], bl[4][4];
#pragma unroll
        for (int f = 0; f < 2; f++) {
            if (LAYER == 1) {
                ldsm4t(ah[f], aBaseH + f * 16 * 2);
                ldsm4t(al[f], aBaseL + f * 16 * 2);
            } else {
                ldsm4(ah[f], aBaseH + f * 16 * AS_STR * 2);
                ldsm4(al[f], aBaseL + f * 16 * AS_STR * 2);
            }
        }
#pragma unroll
        for (int nb = 0; nb < 4; nb++) {
            ldsm4t(bh[nb], bBaseH + nb * 32);
            ldsm4t(bl[nb], bBaseL + nb * 32);
        }

#pragma unroll
        for (int f = 0; f < 2; f++)
#pragma unroll
            for (int nb = 0; nb < 4; nb++)
#pragma unroll
                for (int j = 0; j < 2; j++) {
                    float* d = acc[f][nb * 2 + j];
                    unsigned bh0 = bh[nb][2 * j], bh1 = bh[nb][2 * j + 1];
                    unsigned bl0 = bl[nb][2 * j], bl1 = bl[nb][2 * j + 1];
                    mma_bf16(d, ah[f], bh0, bh1);
                    mma_bf16(d, ah[f], bl0, bl1);
                    mma_bf16(d, al[f], bh0, bh1);
                }

        if (has) cp_wait0();
        __syncthreads();
    }

    // ---- epilogue ----
    if (LAYER == 1) {
#pragma unroll
        for (int f = 0; f < 2; f++)
#pragma unroll
            for (int n8 = 0; n8 < 8; n8++) {
                int rm = m0 + wm * 32 + f * 16 + (lane >> 2);
                int cn = n0 + wn * 64 + n8 * 8 + (lane & 3) * 2;
                float b0 = bias[cn], b1 = bias[cn + 1];
#pragma unroll
                for (int half = 0; half < 2; half++) {
                    int r = rm + half * 8;
                    if (r >= M) continue;
                    float v0 = acc[f][n8][half * 2 + 0] + b0;
                    float v1 = acc[f][n8][half * 2 + 1] + b1;
                    v0 = v0 / (1.0f + __expf(-v0));
                    v1 = v1 / (1.0f + __expf(-v1));
                    __nv_bfloat16 h0, l0, h1, l1;
                    bsplit(v0, h0, l0); bsplit(v1, h1, l1);
                    *(__nv_bfloat162*)&g_H1h[(size_t)r * NU1 + cn] = __nv_bfloat162(h0, h1);
                    *(__nv_bfloat162*)&g_H1l[(size_t)r * NU1 + cn] = __nv_bfloat162(l0, l1);
                }
            }
    } else {
        float rs[2][2] = {{0.0f, 0.0f}, {0.0f, 0.0f}};
#pragma unroll
        for (int f = 0; f < 2; f++)
#pragma unroll
            for (int n8 = 0; n8 < 8; n8++) {
                int cn = n0 + wn * 64 + n8 * 8 + (lane & 3) * 2;
                float b0 = bias[cn], b1 = bias[cn + 1];
                float w0 = w3[cn], w1 = w3[cn + 1];
#pragma unroll
                for (int half = 0; half < 2; half++) {
                    float v0 = acc[f][n8][half * 2 + 0] + b0;
                    float v1 = acc[f][n8][half * 2 + 1] + b1;
                    v0 = v0 / (1.0f + __expf(-v0));
                    v1 = v1 / (1.0f + __expf(-v1));
                    rs[f][half] = fmaf(v0, w0, fmaf(v1, w1, rs[f][half]));
                }
            }
#pragma unroll
        for (int f = 0; f < 2; f++)
#pragma unroll
            for (int half = 0; half < 2; half++) {
                float s = rs[f][half];
                s += __shfl_xor_sync(0xffffffffu, s, 1);
                s += __shfl_xor_sync(0xffffffffu, s, 2);
                if ((lane & 3) == 0) {
                    int r = m0 + wm * 32 + f * 16 + (lane >> 2) + half * 8;
                    if (r < M) {
                        atomicAdd(&out[r], scale[Z[r]] * s);
                    }
                }
            }
    }
}

// ---------------- launch ----------------
extern "C" void kernel_launch(void* const* d_in, const int* in_sizes, int n_in,
                              void* d_out, int out_size)
{
    const float* R     = (const float*)d_in[0];
    const int*   Z     = (const int*)  d_in[1];
    const int*   idx   = (const int*)  d_in[2];
    const float* Wr    = (const float*)d_in[3];
    const float* w1    = (const float*)d_in[4];
    const float* b1    = (const float*)d_in[5];
    const float* w2    = (const float*)d_in[6];
    const float* b2    = (const float*)d_in[7];
    const float* w3    = (const float*)d_in[8];
    const float* b3    = (const float*)d_in[9];
    const float* scale = (const float*)d_in[10];
    const float* shift = (const float*)d_in[11];
    float* out = (float*)d_out;

    __nv_bfloat16 *pGMh, *pGMl, *pW1h, *pW1l, *pW2h, *pW2l, *pH1h, *pH1l;
    cudaGetSymbolAddress((void**)&pGMh, g_GMh);
    cudaGetSymbolAddress((void**)&pGMl, g_GMl);
    cudaGetSymbolAddress((void**)&pW1h, g_w1h);
    cudaGetSymbolAddress((void**)&pW1l, g_w1l);
    cudaGetSymbolAddress((void**)&pW2h, g_w2h);
    cudaGetSymbolAddress((void**)&pW2l, g_w2l);
    cudaGetSymbolAddress((void**)&pH1h, g_H1h);
    cudaGetSymbolAddress((void**)&pH1l, g_H1l);

    prep_kernel<<<(NATOMS + 255) / 256, 256>>>(R, Z, scale, shift, b3, out);
    packw_kernel<<<(NSPEC * NSPEC * NRAD * NBASIS + 255) / 256, 256>>>(Wr);
    convw_kernel<<<(NU1 * NU2 + 255) / 256, 256>>>(w1, w2);
    hist_kernel<<<(NPAIRS / 4 + 255) / 256, 256>>>(idx);
    scan1_kernel<<<NSCB, 1024>>>();
    scan2_kernel<<<1, 32>>>();
    scan3_kernel<<<NSCB, 1024>>>();
    scatter_kernel<<<(NPAIRS / 2 + 255) / 256, 256>>>(Z, idx);
    moments_kernel<<<(NATOMS + 127) / 128, 128>>>();

    dim3 g1(NU1 / 128, (NATOMS + 127) / 128);
    mma_gemm_kernel<1><<<g1, 256>>>(pGMh, pGMl, pW1h, pW1l, b1, NATOMS, NU1, NFEATP, AP,
                                    nullptr, nullptr, nullptr, nullptr);

    dim3 g2(NU2 / 128, (NATOMS + 127) / 128);
    mma_gemm_kernel<2><<<g2, 256>>>(pH1h, pH1l, pW2h, pW2l, b2, NATOMS, NU2, NU1, 0,
                                    w3, scale, Z, out);
}